// round 7
// baseline (speedup 1.0000x reference)
#include <cuda_runtime.h>
#include <cuda_bf16.h>
#include <cstdint>
#include <math.h>

#define BB 2
#define LL 2048
#define DD 1024
#define HH 16
#define HD 64
#define FF 4096
#define MROWS (BB*LL)   // 4096

// ---------------- scratch (device globals) ---------------------------------
__device__ __nv_bfloat16 g_xn_hi [MROWS * DD];
__device__ __nv_bfloat16 g_xn_lo [MROWS * DD];
__device__ __nv_bfloat16 g_qk_hi [MROWS * 4 * DD];
__device__ __nv_bfloat16 g_qk_lo [MROWS * 4 * DD];
__device__ __nv_bfloat16 g_a_hi  [MROWS * DD];
__device__ __nv_bfloat16 g_a_lo  [MROWS * DD];
__device__ float         g_x1    [MROWS * DD];
__device__ __nv_bfloat16 g_xn2_hi[MROWS * DD];
__device__ __nv_bfloat16 g_xn2_lo[MROWS * DD];
__device__ __nv_bfloat16 g_h_hi  [MROWS * FF];
__device__ __nv_bfloat16 g_h_lo  [MROWS * FF];
__device__ __nv_bfloat16 g_wqkuv_hi[4 * DD * DD];
__device__ __nv_bfloat16 g_wqkuv_lo[4 * DD * DD];
__device__ __nv_bfloat16 g_wout_hi [DD * DD];
__device__ __nv_bfloat16 g_wout_lo [DD * DD];
__device__ __nv_bfloat16 g_w1_hi   [DD * FF];
__device__ __nv_bfloat16 g_w1_lo   [DD * FF];
__device__ __nv_bfloat16 g_w3_hi   [DD * FF];
__device__ __nv_bfloat16 g_w3_lo   [DD * FF];
__device__ __nv_bfloat16 g_w2_hi   [FF * DD];
__device__ __nv_bfloat16 g_w2_lo   [FF * DD];

__device__ __forceinline__ float silu(float x) {
    return __fdividef(x, 1.0f + __expf(-x));
}
__device__ __forceinline__ uint32_t smem_u32(const void* p) {
    uint32_t a;
    asm("{ .reg .u64 t; cvta.to.shared.u64 t, %1; cvt.u32.u64 %0, t; }" : "=r"(a) : "l"(p));
    return a;
}
__device__ __forceinline__ void cp16(uint32_t s, const void* g) {
    asm volatile("cp.async.cg.shared.global [%0], [%1], 16;" :: "r"(s), "l"(g) : "memory");
}
#define CPCOMMIT() asm volatile("cp.async.commit_group;" ::: "memory")
#define CPWAIT(n)  asm volatile("cp.async.wait_group %0;" :: "n"(n) : "memory")
__device__ __forceinline__ void bf_split(float v, __nv_bfloat16& h, __nv_bfloat16& l) {
    h = __float2bfloat16(v);
    l = __float2bfloat16(v - __bfloat162float(h));
}
__device__ __forceinline__ uint32_t pack2(__nv_bfloat16 a, __nv_bfloat16 b) {
    return (uint32_t)__bfloat16_as_ushort(a) | ((uint32_t)__bfloat16_as_ushort(b) << 16);
}
__device__ __forceinline__ void ldsm4(uint32_t* r, uint32_t a) {
    asm volatile("ldmatrix.sync.aligned.m8n8.x4.shared.b16 {%0,%1,%2,%3}, [%4];"
        : "=r"(r[0]), "=r"(r[1]), "=r"(r[2]), "=r"(r[3]) : "r"(a));
}
__device__ __forceinline__ void ldsm4t(uint32_t* r, uint32_t a) {
    asm volatile("ldmatrix.sync.aligned.m8n8.x4.trans.shared.b16 {%0,%1,%2,%3}, [%4];"
        : "=r"(r[0]), "=r"(r[1]), "=r"(r[2]), "=r"(r[3]) : "r"(a));
}
__device__ __forceinline__ void mma16816(float* c, const uint32_t* a, uint32_t b0, uint32_t b1) {
    asm volatile(
        "mma.sync.aligned.m16n8k16.row.col.f32.bf16.bf16.f32 "
        "{%0,%1,%2,%3}, {%4,%5,%6,%7}, {%8,%9}, {%0,%1,%2,%3};"
        : "+f"(c[0]), "+f"(c[1]), "+f"(c[2]), "+f"(c[3])
        : "r"(a[0]), "r"(a[1]), "r"(a[2]), "r"(a[3]), "r"(b0), "r"(b1));
}

// ---------------- weight transpose + split ----------------------------------
__global__ __launch_bounds__(256) void wsplit_kernel(
    const float* __restrict__ w, __nv_bfloat16* __restrict__ whi,
    __nv_bfloat16* __restrict__ wlo, int K, int N)
{
    __shared__ float t[32][33];
    int n0 = blockIdx.x * 32, k0 = blockIdx.y * 32;
    int tx = threadIdx.x & 31, ty = threadIdx.x >> 5;
    #pragma unroll
    for (int j = 0; j < 4; j++)
        t[ty + j * 8][tx] = w[(size_t)(k0 + ty + j * 8) * N + n0 + tx];
    __syncthreads();
    #pragma unroll
    for (int j = 0; j < 4; j++) {
        int nn = ty + j * 8;
        float v = t[tx][nn];
        __nv_bfloat16 h, l; bf_split(v, h, l);
        size_t o = (size_t)(n0 + nn) * K + k0 + tx;
        whi[o] = h; wlo[o] = l;
    }
}

// ---------------- LayerNorm -> split bf16 -----------------------------------
__global__ __launch_bounds__(256) void ln_split_kernel(
    const float* __restrict__ x, const float* __restrict__ g,
    const float* __restrict__ b, __nv_bfloat16* __restrict__ oh,
    __nv_bfloat16* __restrict__ ol)
{
    int row = blockIdx.x;
    const float* xr = x + (size_t)row * DD;
    float s = 0.f, s2 = 0.f;
    for (int i = threadIdx.x; i < DD; i += 256) {
        float v = xr[i]; s += v; s2 += v * v;
    }
    __shared__ float red[8], red2[8], stats[2];
    for (int off = 16; off > 0; off >>= 1) {
        s  += __shfl_down_sync(0xffffffffu, s,  off);
        s2 += __shfl_down_sync(0xffffffffu, s2, off);
    }
    int wid = threadIdx.x >> 5, lid = threadIdx.x & 31;
    if (lid == 0) { red[wid] = s; red2[wid] = s2; }
    __syncthreads();
    if (threadIdx.x == 0) {
        float ts = 0.f, ts2 = 0.f;
        for (int i = 0; i < 8; i++) { ts += red[i]; ts2 += red2[i]; }
        float mu = ts * (1.0f / DD);
        float var = ts2 * (1.0f / DD) - mu * mu;
        stats[0] = mu; stats[1] = rsqrtf(var + 1e-5f);
    }
    __syncthreads();
    float mu = stats[0], rstd = stats[1];
    for (int i = threadIdx.x; i < DD; i += 256) {
        float v = (xr[i] - mu) * rstd * g[i] + b[i];
        __nv_bfloat16 h, l; bf_split(v, h, l);
        oh[(size_t)row * DD + i] = h;
        ol[(size_t)row * DD + i] = l;
    }
}

// ---------------- mma.sync split-bf16 GEMM: CTA 256x128, warp 64x64 ----------
// MODE 1: Cf = acc + aux (fp32 out).  MODE 3: silu(acc) -> Chi/Clo split.
#define SROW 144                    // padded row bytes (72 bf16)
#define ATEN (256 * SROW)           // 36864
#define BTEN (128 * SROW)           // 18432
#define STAGE2 (2 * ATEN + 2 * BTEN)// 110592
#define GEMM_SMEM (2 * STAGE2)      // 221184

template <int MODE>
__global__ __launch_bounds__(256, 1) void gemm_mma(
    const __nv_bfloat16* __restrict__ Ahi, const __nv_bfloat16* __restrict__ Alo,
    const __nv_bfloat16* __restrict__ Bhi, const __nv_bfloat16* __restrict__ Blo,
    float* __restrict__ Cf, const float* __restrict__ aux,
    __nv_bfloat16* __restrict__ Chi, __nv_bfloat16* __restrict__ Clo,
    int M, int N, int K)
{
    extern __shared__ char smem[];
    const uint32_t sbase = smem_u32(smem);
    const int tid = threadIdx.x, lane = tid & 31, wid = tid >> 5;
    const int wm = wid & 3, wn = wid >> 2;   // 4 x 2 warp grid, warp tile 64x64
    const int bx = blockIdx.x, by = blockIdx.y;

    const size_t rowbytes = (size_t)K * 2;
    const char* Ah = (const char*)(Ahi + (size_t)by * 256 * K);
    const char* Al = (const char*)(Alo + (size_t)by * 256 * K);
    const char* Bh = (const char*)(Bhi + (size_t)bx * 128 * K);
    const char* Bl = (const char*)(Blo + (size_t)bx * 128 * K);

    const uint32_t aRowOff = (uint32_t)((wm * 64 + (lane & 15)) * SROW + (lane >> 4) * 16);
    const int bg = lane >> 3;
    const uint32_t bRowOff = (uint32_t)((wn * 64 + (bg >> 1) * 8 + (lane & 7)) * SROW + (bg & 1) * 16);

    auto load_slab = [&](int ks, int st) {
        uint32_t stg = sbase + (uint32_t)st * STAGE2;
        size_t koff = (size_t)ks * 128;   // 64 bf16 = 128 B
        #pragma unroll
        for (int i = 0; i < 16; i++) {    // A hi+lo: 4096 chunks
            int c = tid + i * 256;
            int tn = c >> 11;             // 0=hi,1=lo
            int rr = (c >> 3) & 255;
            int ck = (c & 7) * 16;
            cp16(stg + (uint32_t)(tn * ATEN + rr * SROW + ck),
                 (tn ? Al : Ah) + (size_t)rr * rowbytes + koff + ck);
        }
        #pragma unroll
        for (int i = 0; i < 8; i++) {     // B hi+lo: 2048 chunks
            int c = tid + i * 256;
            int tn = c >> 10;
            int rr = (c >> 3) & 127;
            int ck = (c & 7) * 16;
            cp16(stg + (uint32_t)(2 * ATEN + tn * BTEN + rr * SROW + ck),
                 (tn ? Bl : Bh) + (size_t)rr * rowbytes + koff + ck);
        }
        CPCOMMIT();
    };

    float acc[4][8][4];
    #pragma unroll
    for (int mt = 0; mt < 4; mt++)
        #pragma unroll
        for (int nt = 0; nt < 8; nt++)
            #pragma unroll
            for (int j = 0; j < 4; j++) acc[mt][nt][j] = 0.f;

    const int ns = K >> 6;
    load_slab(0, 0);

    for (int i = 0; i < ns; i++) {
        CPWAIT(0);
        __syncthreads();
        if (i + 1 < ns) load_slab(i + 1, (i + 1) & 1);

        uint32_t stg = sbase + (uint32_t)(i & 1) * STAGE2;
        uint32_t aHiB = stg + aRowOff;
        uint32_t aLoB = stg + ATEN + aRowOff;
        uint32_t bHiB = stg + 2 * ATEN + bRowOff;
        uint32_t bLoB = stg + 2 * ATEN + BTEN + bRowOff;

        #pragma unroll
        for (int ks = 0; ks < 4; ks++) {
            uint32_t ah[4][4], al[4][4], bh[4][4], bl[4][4];
            #pragma unroll
            for (int mt = 0; mt < 4; mt++) {
                uint32_t o = (uint32_t)(mt * 16 * SROW + ks * 32);
                ldsm4(ah[mt], aHiB + o);
                ldsm4(al[mt], aLoB + o);
            }
            #pragma unroll
            for (int p = 0; p < 4; p++) {
                uint32_t o = (uint32_t)(p * 16 * SROW + ks * 32);
                ldsm4(bh[p], bHiB + o);
                ldsm4(bl[p], bLoB + o);
            }
            #pragma unroll
            for (int mt = 0; mt < 4; mt++) {
                #pragma unroll
                for (int nt = 0; nt < 8; nt++) {
                    int p = nt >> 1, o = (nt & 1) * 2;
                    mma16816(acc[mt][nt], ah[mt], bh[p][o], bh[p][o + 1]);
                    mma16816(acc[mt][nt], ah[mt], bl[p][o], bl[p][o + 1]);
                    mma16816(acc[mt][nt], al[mt], bh[p][o], bh[p][o + 1]);
                }
            }
        }
        __syncthreads();
    }

    const int groupID = lane >> 2, tid4 = lane & 3;
    #pragma unroll
    for (int mt = 0; mt < 4; mt++) {
        int r0 = by * 256 + wm * 64 + mt * 16 + groupID;
        #pragma unroll
        for (int nt = 0; nt < 8; nt++) {
            int cg = bx * 128 + wn * 64 + nt * 8 + tid4 * 2;
            float* a = acc[mt][nt];
            #pragma unroll
            for (int half = 0; half < 2; half++) {
                size_t off = (size_t)(r0 + half * 8) * N + cg;
                float v0 = a[half * 2 + 0], v1 = a[half * 2 + 1];
                if (MODE == 1) {
                    float2 ax = *(const float2*)(aux + off);
                    float2 o; o.x = v0 + ax.x; o.y = v1 + ax.y;
                    *(float2*)(Cf + off) = o;
                } else {
                    float t0 = silu(v0), t1 = silu(v1);
                    __nv_bfloat16 h0, l0, h1, l1;
                    bf_split(t0, h0, l0);
                    bf_split(t1, h1, l1);
                    *(uint32_t*)(Chi + off) = pack2(h0, h1);
                    *(uint32_t*)(Clo + off) = pack2(l0, l1);
                }
            }
        }
    }
}

// ---------------- dual GEMM: h = silu(A@W1) * (A@W3) -> split ----------------
#define DTEN (128 * SROW)                 // 18432
#define DSTAGE_BYTES (6 * DTEN)           // 110592
#define DUAL_SMEM (2 * DSTAGE_BYTES)      // 221184

__global__ __launch_bounds__(256, 1) void gemm_dual(
    const __nv_bfloat16* __restrict__ Ahi, const __nv_bfloat16* __restrict__ Alo,
    const __nv_bfloat16* __restrict__ B1hi, const __nv_bfloat16* __restrict__ B1lo,
    const __nv_bfloat16* __restrict__ B3hi, const __nv_bfloat16* __restrict__ B3lo,
    __nv_bfloat16* __restrict__ Chi, __nv_bfloat16* __restrict__ Clo,
    int M, int N, int K)
{
    extern __shared__ char smem[];
    const uint32_t sbase = smem_u32(smem);
    const int tid = threadIdx.x, lane = tid & 31, wid = tid >> 5;
    const int wm = wid & 1, wn = wid >> 1;
    const int bx = blockIdx.x, by = blockIdx.y;

    const size_t rowbytes = (size_t)K * 2;
    const char* base[6] = {
        (const char*)(Ahi  + (size_t)by * 128 * K),
        (const char*)(Alo  + (size_t)by * 128 * K),
        (const char*)(B1hi + (size_t)bx * 128 * K),
        (const char*)(B1lo + (size_t)bx * 128 * K),
        (const char*)(B3hi + (size_t)bx * 128 * K),
        (const char*)(B3lo + (size_t)bx * 128 * K)
    };

    const uint32_t aRowOff = (uint32_t)((wm * 64 + (lane & 15)) * SROW + (lane >> 4) * 16);
    const int bg = lane >> 3;
    const uint32_t bRowOff = (uint32_t)((wn * 32 + (bg >> 1) * 8 + (lane & 7)) * SROW + (bg & 1) * 16);

    auto load_slab = [&](int ks, int st) {
        uint32_t stg = sbase + (uint32_t)st * DSTAGE_BYTES;
        size_t koff = (size_t)ks * 128;
        #pragma unroll
        for (int i = 0; i < 24; i++) {
            int c = tid + i * 256;
            int tn = c >> 10;
            int rr = (c >> 3) & 127;
            int ck = (c & 7) * 16;
            cp16(stg + (uint32_t)(tn * DTEN + rr * SROW + ck),
                 base[tn] + (size_t)rr * rowbytes + koff + ck);
        }
        CPCOMMIT();
    };

    float acc1[4][4][4], acc3[4][4][4];
    #pragma unroll
    for (int mt = 0; mt < 4; mt++)
        #pragma unroll
        for (int nt = 0; nt < 4; nt++)
            #pragma unroll
            for (int j = 0; j < 4; j++) { acc1[mt][nt][j] = 0.f; acc3[mt][nt][j] = 0.f; }

    const int ns = K >> 6;
    load_slab(0, 0);

    for (int i = 0; i < ns; i++) {
        CPWAIT(0);
        __syncthreads();
        if (i + 1 < ns) load_slab(i + 1, (i + 1) & 1);

        uint32_t stg = sbase + (uint32_t)(i & 1) * DSTAGE_BYTES;
        uint32_t aHiB  = stg + aRowOff;
        uint32_t aLoB  = stg + DTEN + aRowOff;
        uint32_t b1HiB = stg + 2 * DTEN + bRowOff;
        uint32_t b1LoB = stg + 3 * DTEN + bRowOff;
        uint32_t b3HiB = stg + 4 * DTEN + bRowOff;
        uint32_t b3LoB = stg + 5 * DTEN + bRowOff;

        #pragma unroll
        for (int ks = 0; ks < 4; ks++) {
            uint32_t ah[4][4], al[4][4], bh[2][4], bl[2][4];
            #pragma unroll
            for (int mt = 0; mt < 4; mt++) {
                uint32_t o = (uint32_t)(mt * 16 * SROW + ks * 32);
                ldsm4(ah[mt], aHiB + o);
                ldsm4(al[mt], aLoB + o);
            }
            #pragma unroll
            for (int p = 0; p < 2; p++) {
                uint32_t o = (uint32_t)(p * 16 * SROW + ks * 32);
                ldsm4(bh[p], b1HiB + o);
                ldsm4(bl[p], b1LoB + o);
            }
            #pragma unroll
            for (int mt = 0; mt < 4; mt++)
                #pragma unroll
                for (int nt = 0; nt < 4; nt++) {
                    int p = nt >> 1, o = (nt & 1) * 2;
                    mma16816(acc1[mt][nt], ah[mt], bh[p][o], bh[p][o + 1]);
                    mma16816(acc1[mt][nt], ah[mt], bl[p][o], bl[p][o + 1]);
                    mma16816(acc1[mt][nt], al[mt], bh[p][o], bh[p][o + 1]);
                }
            #pragma unroll
            for (int p = 0; p < 2; p++) {
                uint32_t o = (uint32_t)(p * 16 * SROW + ks * 32);
                ldsm4(bh[p], b3HiB + o);
                ldsm4(bl[p], b3LoB + o);
            }
            #pragma unroll
            for (int mt = 0; mt < 4; mt++)
                #pragma unroll
                for (int nt = 0; nt < 4; nt++) {
                    int p = nt >> 1, o = (nt & 1) * 2;
                    mma16816(acc3[mt][nt], ah[mt], bh[p][o], bh[p][o + 1]);
                    mma16816(acc3[mt][nt], ah[mt], bl[p][o], bl[p][o + 1]);
                    mma16816(acc3[mt][nt], al[mt], bh[p][o], bh[p][o + 1]);
                }
        }
        __syncthreads();
    }

    const int groupID = lane >> 2, tid4 = lane & 3;
    #pragma unroll
    for (int mt = 0; mt < 4; mt++) {
        int r0 = by * 128 + wm * 64 + mt * 16 + groupID;
        #pragma unroll
        for (int nt = 0; nt < 4; nt++) {
            int cg = bx * 128 + wn * 32 + nt * 8 + tid4 * 2;
            #pragma unroll
            for (int half = 0; half < 2; half++) {
                size_t off = (size_t)(r0 + half * 8) * N + cg;
                float t0 = silu(acc1[mt][nt][half * 2 + 0]) * acc3[mt][nt][half * 2 + 0];
                float t1 = silu(acc1[mt][nt][half * 2 + 1]) * acc3[mt][nt][half * 2 + 1];
                __nv_bfloat16 h0, l0, h1, l1;
                bf_split(t0, h0, l0);
                bf_split(t1, h1, l1);
                *(uint32_t*)(Chi + off) = pack2(h0, h1);
                *(uint32_t*)(Clo + off) = pack2(l0, l1);
            }
        }
    }
}

// ---------------- Fused attention (pipelined loads, mma.sync) ----------------
#define AROWB 144
#define SROWB 272
#define ATT_SMEM 217088
#define GROWB 8192

__global__ __launch_bounds__(256, 1) void attn_mma(
    const __nv_bfloat16* __restrict__ qkh, const __nv_bfloat16* __restrict__ qkl,
    const float* __restrict__ nag, const float* __restrict__ nab,
    __nv_bfloat16* __restrict__ ahi, __nv_bfloat16* __restrict__ alo)
{
    extern __shared__ char smc[];
    const uint32_t sb = smem_u32(smc);
    const uint32_t oQh = 0, oQl = 18432;
    const uint32_t oKh[2] = {36864, 73728};
    const uint32_t oKl[2] = {55296, 92160};
    const uint32_t oVh = 110592, oVl = 129024;
    const uint32_t oSh = 147456, oSl = 182272;
    __nv_bfloat16* shp = (__nv_bfloat16*)(smc + oSh);
    __nv_bfloat16* slp = (__nv_bfloat16*)(smc + oSl);
    float* aS = (float*)(smc + oSh);
    __shared__ float mu_s[128], rs_s[128];

    const int qb = (int)gridDim.x - 1 - (int)blockIdx.x;
    const int bh = blockIdx.y;
    const int b = bh >> 4, h = bh & 15;
    const int tid = threadIdx.x, lane = tid & 31, wid = tid >> 5;
    const int wm = wid & 1, wn = wid >> 1;
    const int groupID = lane >> 2, tid4 = lane & 3;

    const char* gh = (const char*)qkh + (size_t)(b * LL) * GROWB + h * 128;
    const char* gl = (const char*)qkl + (size_t)(b * LL) * GROWB + h * 128;

    auto ldt = [&](uint32_t so, const char* g) {
        #pragma unroll
        for (int i = 0; i < 4; i++) {
            int idx = tid + i * 256;
            int r = idx >> 3, ck = (idx & 7) * 16;
            cp16(sb + so + (uint32_t)(r * AROWB + ck), g + (size_t)r * GROWB + ck);
        }
    };

    ldt(oQh, gh + (size_t)(qb * 128) * GROWB);
    ldt(oQl, gl + (size_t)(qb * 128) * GROWB);
    ldt(oKh[0], gh + 2048);
    ldt(oKl[0], gl + 2048);
    CPCOMMIT();

    const uint32_t aOffQ = (uint32_t)((wm * 64 + (lane & 15)) * AROWB + (lane >> 4) * 16);
    const int bg = lane >> 3;
    const uint32_t bOffK = (uint32_t)((wn * 32 + (bg >> 1) * 8 + (lane & 7)) * AROWB + (bg & 1) * 16);
    const uint32_t aOffS = (uint32_t)((wm * 64 + (lane & 15)) * SROWB + (lane >> 4) * 16);
    const uint32_t bOffV = (uint32_t)(((bg & 1) * 8 + (lane & 7)) * AROWB + (wn * 16 + (bg >> 1) * 8) * 2);

    float oacc[4][2][4];
    #pragma unroll
    for (int mt = 0; mt < 4; mt++)
        #pragma unroll
        for (int nt = 0; nt < 2; nt++)
            #pragma unroll
            for (int j = 0; j < 4; j++) oacc[mt][nt][j] = 0.f;

    for (int kb = 0; kb <= qb; kb++) {
        const int st = kb & 1;
        const bool more = (kb < qb);
        __syncthreads();
        ldt(oVh, gh + 4096 + (size_t)(kb * 128) * GROWB);
        ldt(oVl, gl + 4096 + (size_t)(kb * 128) * GROWB);
        CPCOMMIT();
        if (more) {
            ldt(oKh[st ^ 1], gh + 2048 + (size_t)((kb + 1) * 128) * GROWB);
            ldt(oKl[st ^ 1], gl + 2048 + (size_t)((kb + 1) * 128) * GROWB);
            CPCOMMIT();
        }
        if (more) CPWAIT(2); else CPWAIT(1);
        __syncthreads();

        float sacc[4][4][4];
        #pragma unroll
        for (int mt = 0; mt < 4; mt++)
            #pragma unroll
            for (int nt = 0; nt < 4; nt++)
                #pragma unroll
                for (int j = 0; j < 4; j++) sacc[mt][nt][j] = 0.f;

        #pragma unroll
        for (int ks = 0; ks < 4; ks++) {
            uint32_t qh4[4][4], ql4[4][4], kh4[2][4], kl4[2][4];
            #pragma unroll
            for (int mt = 0; mt < 4; mt++) {
                uint32_t o = (uint32_t)(mt * 16 * AROWB + ks * 32);
                ldsm4(qh4[mt], sb + oQh + aOffQ + o);
                ldsm4(ql4[mt], sb + oQl + aOffQ + o);
            }
            #pragma unroll
            for (int p = 0; p < 2; p++) {
                uint32_t o = (uint32_t)(p * 16 * AROWB + ks * 32);
                ldsm4(kh4[p], sb + oKh[st] + bOffK + o);
                ldsm4(kl4[p], sb + oKl[st] + bOffK + o);
            }
            #pragma unroll
            for (int mt = 0; mt < 4; mt++)
                #pragma unroll
                for (int nt = 0; nt < 4; nt++) {
                    int p = nt >> 1, o = (nt & 1) * 2;
                    mma16816(sacc[mt][nt], qh4[mt], kh4[p][o], kh4[p][o + 1]);
                    mma16816(sacc[mt][nt], qh4[mt], kl4[p][o], kl4[p][o + 1]);
                    mma16816(sacc[mt][nt], ql4[mt], kh4[p][o], kh4[p][o + 1]);
                }
        }

        const bool diag = (kb == qb);
        #pragma unroll
        for (int mt = 0; mt < 4; mt++) {
            #pragma unroll
            for (int half = 0; half < 2; half++) {
                int r = wm * 64 + mt * 16 + groupID + half * 8;
                #pragma unroll
                for (int nt = 0; nt < 4; nt++) {
                    int c = wn * 32 + nt * 8 + tid4 * 2;
                    float s0 = silu(sacc[mt][nt][half * 2 + 0] * 0.125f);
                    float s1 = silu(sacc[mt][nt][half * 2 + 1] * 0.125f);
                    if (diag) {
                        if (c > r) s0 = 0.f;
                        if (c + 1 > r) s1 = 0.f;
                    }
                    __nv_bfloat16 h0, l0, h1, l1;
                    bf_split(s0, h0, l0); bf_split(s1, h1, l1);
                    *(uint32_t*)(shp + r * 136 + c) = pack2(h0, h1);
                    *(uint32_t*)(slp + r * 136 + c) = pack2(l0, l1);
                }
            }
        }
        if (more) CPWAIT(1); else CPWAIT(0);
        __syncthreads();

        #pragma unroll
        for (int ks = 0; ks < 8; ks++) {
            uint32_t sh4[4][4], sl4[4][4], vh4[4], vl4[4];
            #pragma unroll
            for (int mt = 0; mt < 4; mt++) {
                uint32_t o = (uint32_t)(mt * 16 * SROWB + ks * 32);
                ldsm4(sh4[mt], sb + oSh + aOffS + o);
                ldsm4(sl4[mt], sb + oSl + aOffS + o);
            }
            uint32_t vo = (uint32_t)(ks * 16 * AROWB);
            ldsm4t(vh4, sb + oVh + bOffV + vo);
            ldsm4t(vl4, sb + oVl + bOffV + vo);
            #pragma unroll
            for (int mt = 0; mt < 4; mt++)
                #pragma unroll
                for (int nt = 0; nt < 2; nt++) {
                    int o = nt * 2;
                    mma16816(oacc[mt][nt], sh4[mt], vh4[o], vh4[o + 1]);
                    mma16816(oacc[mt][nt], sh4[mt], vl4[o], vl4[o + 1]);
                    mma16816(oacc[mt][nt], sl4[mt], vh4[o], vh4[o + 1]);
                }
        }
    }

    __syncthreads();
    #pragma unroll
    for (int mt = 0; mt < 4; mt++)
        #pragma unroll
        for (int half = 0; half < 2; half++) {
            int r = wm * 64 + mt * 16 + groupID + half * 8;
            #pragma unroll
            for (int nt = 0; nt < 2; nt++) {
                int c = wn * 16 + nt * 8 + tid4 * 2;
                float2 v;
                v.x = oacc[mt][nt][half * 2 + 0];
                v.y = oacc[mt][nt][half * 2 + 1];
                *(float2*)(aS + r * 68 + c) = v;
            }
        }
    __syncthreads();
    if (tid < 128) {
        float s = 0.f, s2 = 0.f;
        #pragma unroll
        for (int c = 0; c < 64; c++) {
            float v = aS[tid * 68 + c];
            s += v; s2 += v * v;
        }
        float mu = s * (1.0f / 64.0f);
        float var = s2 * (1.0f / 64.0f) - mu * mu;
        mu_s[tid] = mu;
        rs_s[tid] = rsqrtf(var + 1e-5f);
    }
    __syncthreads();
    {
        int r = tid >> 1;
        int c0 = (tid & 1) * 32;
        int l = qb * 128 + r;
        float mu = mu_s[r], rstd = rs_s[r];
        const __nv_bfloat16* uh = (const __nv_bfloat16*)(gh + 6144 + (size_t)l * GROWB);
        const __nv_bfloat16* ul = (const __nv_bfloat16*)(gl + 6144 + (size_t)l * GROWB);
        size_t obase = (size_t)(b * LL + l) * DD + h * HD;
        #pragma unroll
        for (int c = c0; c < c0 + 32; c += 2) {
            float u0 = __bfloat162float(uh[c + 0]) + __bfloat162float(ul[c + 0]);
            float u1 = __bfloat162float(uh[c + 1]) + __bfloat162float(ul[c + 1]);
            float t0 = ((aS[r * 68 + c + 0] - mu) * rstd * nag[c + 0] + nab[c + 0]) * u0;
            float t1 = ((aS[r * 68 + c + 1] - mu) * rstd * nag[c + 1] + nab[c + 1]) * u1;
            __nv_bfloat16 h0, l0, h1, l1;
            bf_split(t0, h0, l0); bf_split(t1, h1, l1);
            *(uint32_t*)(ahi + obase + c) = pack2(h0, h1);
            *(uint32_t*)(alo + obase + c) = pack2(l0, l1);
        }
    }
}

// ---------------- host -------------------------------------------------------
extern "C" void kernel_launch(void* const* d_in, const int* in_sizes, int n_in,
                              void* d_out, int out_size)
{
    const float* x      = (const float*)d_in[0];
    const float* w_qkuv = (const float*)d_in[2];
    const float* w_out  = (const float*)d_in[3];
    const float* w1     = (const float*)d_in[4];
    const float* w2     = (const float*)d_in[5];
    const float* w3     = (const float*)d_in[6];
    const float* ln1_g  = (const float*)d_in[7];
    const float* ln1_b  = (const float*)d_in[8];
    const float* ln2_g  = (const float*)d_in[9];
    const float* ln2_b  = (const float*)d_in[10];
    const float* na_g   = (const float*)d_in[11];
    const float* na_b   = (const float*)d_in[12];
    float* out = (float*)d_out;

    __nv_bfloat16 *xnh, *xnl, *qkh, *qkl, *ah, *al, *xn2h, *xn2l, *hh, *hl;
    __nv_bfloat16 *wqh, *wql, *woh, *wol, *w1h, *w1l, *w3h, *w3l, *w2h, *w2l;
    float *x1;
    cudaGetSymbolAddress((void**)&xnh,  g_xn_hi);  cudaGetSymbolAddress((void**)&xnl,  g_xn_lo);
    cudaGetSymbolAddress((void**)&qkh,  g_qk_hi);  cudaGetSymbolAddress((void**)&qkl,  g_qk_lo);
    cudaGetSymbolAddress((void**)&ah,   g_a_hi);   cudaGetSymbolAddress((void**)&al,   g_a_lo);
    cudaGetSymbolAddress((void**)&x1,   g_x1);
    cudaGetSymbolAddress((void**)&xn2h, g_xn2_hi); cudaGetSymbolAddress((void**)&xn2l, g_xn2_lo);
    cudaGetSymbolAddress((void**)&hh,   g_h_hi);   cudaGetSymbolAddress((void**)&hl,   g_h_lo);
    cudaGetSymbolAddress((void**)&wqh,  g_wqkuv_hi); cudaGetSymbolAddress((void**)&wql, g_wqkuv_lo);
    cudaGetSymbolAddress((void**)&woh,  g_wout_hi);  cudaGetSymbolAddress((void**)&wol, g_wout_lo);
    cudaGetSymbolAddress((void**)&w1h,  g_w1_hi);    cudaGetSymbolAddress((void**)&w1l, g_w1_lo);
    cudaGetSymbolAddress((void**)&w3h,  g_w3_hi);    cudaGetSymbolAddress((void**)&w3l, g_w3_lo);
    cudaGetSymbolAddress((void**)&w2h,  g_w2_hi);    cudaGetSymbolAddress((void**)&w2l, g_w2_lo);

    cudaFuncSetAttribute(gemm_mma<1>, cudaFuncAttributeMaxDynamicSharedMemorySize, GEMM_SMEM);
    cudaFuncSetAttribute(gemm_mma<3>, cudaFuncAttributeMaxDynamicSharedMemorySize, GEMM_SMEM);
    cudaFuncSetAttribute(gemm_dual,   cudaFuncAttributeMaxDynamicSharedMemorySize, DUAL_SMEM);
    cudaFuncSetAttribute(attn_mma,    cudaFuncAttributeMaxDynamicSharedMemorySize, ATT_SMEM);

    dim3 blk(256);

    // 0. weight transpose + split
    wsplit_kernel<<<dim3(4 * DD / 32, DD / 32), blk>>>(w_qkuv, wqh, wql, DD, 4 * DD);
    wsplit_kernel<<<dim3(DD / 32, DD / 32),     blk>>>(w_out,  woh, wol, DD, DD);
    wsplit_kernel<<<dim3(FF / 32, DD / 32),     blk>>>(w1,     w1h, w1l, DD, FF);
    wsplit_kernel<<<dim3(FF / 32, DD / 32),     blk>>>(w3,     w3h, w3l, DD, FF);
    wsplit_kernel<<<dim3(DD / 32, FF / 32),     blk>>>(w2,     w2h, w2l, FF, DD);

    // 1. LN1 -> split
    ln_split_kernel<<<MROWS, blk>>>(x, ln1_g, ln1_b, xnh, xnl);
    // 2. qkuv = silu(xn @ w_qkuv) -> split bf16
    gemm_mma<3><<<dim3(4 * DD / 128, MROWS / 256), blk, GEMM_SMEM>>>(
        xnh, xnl, wqh, wql, nullptr, nullptr, qkh, qkl, MROWS, 4 * DD, DD);
    // 3. attention -> a hi/lo
    attn_mma<<<dim3(LL / 128, BB * HH), blk, ATT_SMEM>>>(qkh, qkl, na_g, na_b, ah, al);
    // 4. x1 = x + a @ w_out
    gemm_mma<1><<<dim3(DD / 128, MROWS / 256), blk, GEMM_SMEM>>>(
        ah, al, woh, wol, x1, x, nullptr, nullptr, MROWS, DD, DD);
    // 5. LN2 -> split
    ln_split_kernel<<<MROWS, blk>>>(x1, ln2_g, ln2_b, xn2h, xn2l);
    // 6+7. h = silu(xn2@w1) * (xn2@w3) -> split
    gemm_dual<<<dim3(FF / 128, MROWS / 128), blk, DUAL_SMEM>>>(
        xn2h, xn2l, w1h, w1l, w3h, w3l, hh, hl, MROWS, FF, DD);
    // 8. out = x1 + h @ w2
    gemm_mma<1><<<dim3(DD / 128, MROWS / 256), blk, GEMM_SMEM>>>(
        hh, hl, w2h, w2l, out, x1, nullptr, nullptr, MROWS, DD, FF);
}

// round 8
// speedup vs baseline: 1.3731x; 1.3731x over previous
#include <cuda_runtime.h>
#include <cuda_fp16.h>
#include <cstdint>
#include <math.h>

#define BB 2
#define LL 2048
#define DD 1024
#define HH 16
#define HD 64
#define FF 4096
#define MROWS (BB*LL)   // 4096

// ---------------- scratch (device globals) ---------------------------------
__device__ __half g_xn_hi [MROWS * DD];
__device__ __half g_xn_lo [MROWS * DD];
__device__ __half g_qk_hi [MROWS * 4 * DD];   // silu(xn@w_qkuv) split fp16
__device__ __half g_qk_lo [MROWS * 4 * DD];
__device__ __half g_a_hi  [MROWS * DD];
__device__ __half g_a_lo  [MROWS * DD];
__device__ float  g_x1    [MROWS * DD];
__device__ __half g_xn2_hi[MROWS * DD];
__device__ __half g_xn2_lo[MROWS * DD];
__device__ __half g_h_hi  [MROWS * FF];
__device__ __half g_h_lo  [MROWS * FF];
// transposed weights: [N, K] K-major, single fp16
__device__ __half g_wqkuv [4 * DD * DD];
__device__ __half g_wout  [DD * DD];
__device__ __half g_w1    [DD * FF];
__device__ __half g_w3    [DD * FF];
__device__ __half g_w2    [FF * DD];

__device__ __forceinline__ float silu(float x) {
    return __fdividef(x, 1.0f + __expf(-x));
}
__device__ __forceinline__ uint32_t smem_u32(const void* p) {
    uint32_t a;
    asm("{ .reg .u64 t; cvta.to.shared.u64 t, %1; cvt.u32.u64 %0, t; }" : "=r"(a) : "l"(p));
    return a;
}
__device__ __forceinline__ void cp16(uint32_t s, const void* g) {
    asm volatile("cp.async.cg.shared.global [%0], [%1], 16;" :: "r"(s), "l"(g) : "memory");
}
#define CPCOMMIT() asm volatile("cp.async.commit_group;" ::: "memory")
#define CPWAIT(n)  asm volatile("cp.async.wait_group %0;" :: "n"(n) : "memory")
__device__ __forceinline__ void hf_split(float v, __half& h, __half& l) {
    h = __float2half(v);
    l = __float2half(v - __half2float(h));
}
__device__ __forceinline__ uint32_t pack2h(__half a, __half b) {
    return (uint32_t)__half_as_ushort(a) | ((uint32_t)__half_as_ushort(b) << 16);
}
__device__ __forceinline__ void ldsm4(uint32_t* r, uint32_t a) {
    asm volatile("ldmatrix.sync.aligned.m8n8.x4.shared.b16 {%0,%1,%2,%3}, [%4];"
        : "=r"(r[0]), "=r"(r[1]), "=r"(r[2]), "=r"(r[3]) : "r"(a));
}
__device__ __forceinline__ void ldsm4t(uint32_t* r, uint32_t a) {
    asm volatile("ldmatrix.sync.aligned.m8n8.x4.trans.shared.b16 {%0,%1,%2,%3}, [%4];"
        : "=r"(r[0]), "=r"(r[1]), "=r"(r[2]), "=r"(r[3]) : "r"(a));
}
__device__ __forceinline__ void mma16816(float* c, const uint32_t* a, uint32_t b0, uint32_t b1) {
    asm volatile(
        "mma.sync.aligned.m16n8k16.row.col.f32.f16.f16.f32 "
        "{%0,%1,%2,%3}, {%4,%5,%6,%7}, {%8,%9}, {%0,%1,%2,%3};"
        : "+f"(c[0]), "+f"(c[1]), "+f"(c[2]), "+f"(c[3])
        : "r"(a[0]), "r"(a[1]), "r"(a[2]), "r"(a[3]), "r"(b0), "r"(b1));
}

// ---------------- weight transpose -> single fp16: w[K,N] -> wt[N,K] --------
__global__ __launch_bounds__(256) void wconv_kernel(
    const float* __restrict__ w, __half* __restrict__ wt, int K, int N)
{
    __shared__ float t[32][33];
    int n0 = blockIdx.x * 32, k0 = blockIdx.y * 32;
    int tx = threadIdx.x & 31, ty = threadIdx.x >> 5;
    #pragma unroll
    for (int j = 0; j < 4; j++)
        t[ty + j * 8][tx] = w[(size_t)(k0 + ty + j * 8) * N + n0 + tx];
    __syncthreads();
    #pragma unroll
    for (int j = 0; j < 4; j++) {
        int nn = ty + j * 8;
        wt[(size_t)(n0 + nn) * K + k0 + tx] = __float2half(t[tx][nn]);
    }
}

// ---------------- LayerNorm -> split fp16 -----------------------------------
__global__ __launch_bounds__(256) void ln_split_kernel(
    const float* __restrict__ x, const float* __restrict__ g,
    const float* __restrict__ b, __half* __restrict__ oh,
    __half* __restrict__ ol)
{
    int row = blockIdx.x;
    const float* xr = x + (size_t)row * DD;
    float s = 0.f, s2 = 0.f;
    for (int i = threadIdx.x; i < DD; i += 256) {
        float v = xr[i]; s += v; s2 += v * v;
    }
    __shared__ float red[8], red2[8], stats[2];
    for (int off = 16; off > 0; off >>= 1) {
        s  += __shfl_down_sync(0xffffffffu, s,  off);
        s2 += __shfl_down_sync(0xffffffffu, s2, off);
    }
    int wid = threadIdx.x >> 5, lid = threadIdx.x & 31;
    if (lid == 0) { red[wid] = s; red2[wid] = s2; }
    __syncthreads();
    if (threadIdx.x == 0) {
        float ts = 0.f, ts2 = 0.f;
        for (int i = 0; i < 8; i++) { ts += red[i]; ts2 += red2[i]; }
        float mu = ts * (1.0f / DD);
        float var = ts2 * (1.0f / DD) - mu * mu;
        stats[0] = mu; stats[1] = rsqrtf(var + 1e-5f);
    }
    __syncthreads();
    float mu = stats[0], rstd = stats[1];
    for (int i = threadIdx.x; i < DD; i += 256) {
        float v = (xr[i] - mu) * rstd * g[i] + b[i];
        __half h, l; hf_split(v, h, l);
        oh[(size_t)row * DD + i] = h;
        ol[(size_t)row * DD + i] = l;
    }
}

// ---------------- 2-term fp16 GEMM: D = (Ahi+Alo) @ W^T ----------------------
// MODE 1: Cf = acc + aux (fp32 out).  MODE 3: silu(acc) -> Chi/Clo fp16 split.
// CTA 128x128, BK=64, warp 64x32 (2x4 grid), 3-stage pipeline.
#define SROW 144                    // padded row bytes (72 fp16)
#define T128 (128 * SROW)           // 18432
#define STAGE3 (3 * T128)           // 55296 : Ahi, Alo, W
#define GEMM_SMEM (3 * STAGE3)      // 165888

template <int MODE>
__global__ __launch_bounds__(256, 1) void gemm_mma(
    const __half* __restrict__ Ahi, const __half* __restrict__ Alo,
    const __half* __restrict__ Bw,
    float* __restrict__ Cf, const float* __restrict__ aux,
    __half* __restrict__ Chi, __half* __restrict__ Clo,
    int M, int N, int K)
{
    extern __shared__ char smem[];
    const uint32_t sbase = smem_u32(smem);
    const int tid = threadIdx.x, lane = tid & 31, wid = tid >> 5;
    const int wm = wid & 1, wn = wid >> 1;
    const int bx = blockIdx.x, by = blockIdx.y;

    const size_t rowbytes = (size_t)K * 2;
    const char* base[3] = {
        (const char*)(Ahi + (size_t)by * 128 * K),
        (const char*)(Alo + (size_t)by * 128 * K),
        (const char*)(Bw  + (size_t)bx * 128 * K)
    };

    const uint32_t aRowOff = (uint32_t)((wm * 64 + (lane & 15)) * SROW + (lane >> 4) * 16);
    const int bg = lane >> 3;
    const uint32_t bRowOff = (uint32_t)((wn * 32 + (bg >> 1) * 8 + (lane & 7)) * SROW + (bg & 1) * 16);

    auto load_slab = [&](int ks, int st) {
        uint32_t stg = sbase + (uint32_t)st * STAGE3;
        size_t koff = (size_t)ks * 128;        // 64 fp16 = 128 B
        #pragma unroll
        for (int i = 0; i < 12; i++) {         // 3 tensors x 1024 chunks
            int c = tid + i * 256;
            int tn = c >> 10;
            int rr = (c >> 3) & 127;
            int ck = (c & 7) * 16;
            cp16(stg + (uint32_t)(tn * T128 + rr * SROW + ck),
                 base[tn] + (size_t)rr * rowbytes + koff + ck);
        }
        CPCOMMIT();
    };

    float acc[4][4][4];
    #pragma unroll
    for (int mt = 0; mt < 4; mt++)
        #pragma unroll
        for (int nt = 0; nt < 4; nt++)
            #pragma unroll
            for (int j = 0; j < 4; j++) acc[mt][nt][j] = 0.f;

    const int ns = K >> 6;
    load_slab(0, 0);
    if (ns > 1) load_slab(1, 1);

    for (int i = 0; i < ns; i++) {
        if (i + 1 < ns) CPWAIT(1);
        else            CPWAIT(0);
        __syncthreads();
        if (i + 2 < ns) load_slab(i + 2, (i + 2) % 3);

        uint32_t stg = sbase + (uint32_t)(i % 3) * STAGE3;
        uint32_t aHiB = stg + aRowOff;
        uint32_t aLoB = stg + T128 + aRowOff;
        uint32_t bB   = stg + 2 * T128 + bRowOff;

        #pragma unroll
        for (int ks = 0; ks < 4; ks++) {
            uint32_t ah[4][4], al[4][4], bh[2][4];
            #pragma unroll
            for (int mt = 0; mt < 4; mt++) {
                uint32_t o = (uint32_t)(mt * 16 * SROW + ks * 32);
                ldsm4(ah[mt], aHiB + o);
                ldsm4(al[mt], aLoB + o);
            }
            #pragma unroll
            for (int p = 0; p < 2; p++) {
                uint32_t o = (uint32_t)(p * 16 * SROW + ks * 32);
                ldsm4(bh[p], bB + o);
            }
            #pragma unroll
            for (int mt = 0; mt < 4; mt++) {
                #pragma unroll
                for (int nt = 0; nt < 4; nt++) {
                    int p = nt >> 1, o = (nt & 1) * 2;
                    mma16816(acc[mt][nt], ah[mt], bh[p][o], bh[p][o + 1]);
                    mma16816(acc[mt][nt], al[mt], bh[p][o], bh[p][o + 1]);
                }
            }
        }
    }

    const int groupID = lane >> 2, tid4 = lane & 3;
    #pragma unroll
    for (int mt = 0; mt < 4; mt++) {
        int r0 = by * 128 + wm * 64 + mt * 16 + groupID;
        #pragma unroll
        for (int nt = 0; nt < 4; nt++) {
            int cg = bx * 128 + wn * 32 + nt * 8 + tid4 * 2;
            float* a = acc[mt][nt];
            #pragma unroll
            for (int half = 0; half < 2; half++) {
                size_t off = (size_t)(r0 + half * 8) * N + cg;
                float v0 = a[half * 2 + 0], v1 = a[half * 2 + 1];
                if (MODE == 1) {
                    float2 ax = *(const float2*)(aux + off);
                    float2 o; o.x = v0 + ax.x; o.y = v1 + ax.y;
                    *(float2*)(Cf + off) = o;
                } else {
                    float t0 = silu(v0), t1 = silu(v1);
                    __half h0, l0, h1, l1;
                    hf_split(t0, h0, l0);
                    hf_split(t1, h1, l1);
                    *(uint32_t*)(Chi + off) = pack2h(h0, h1);
                    *(uint32_t*)(Clo + off) = pack2h(l0, l1);
                }
            }
        }
    }
}

// ---------------- dual GEMM: h = silu(A@W1) * (A@W3) -> fp16 split -----------
#define DSTAGE (4 * T128)                 // 73728 : Ahi, Alo, W1, W3
#define DUAL_SMEM (2 * DSTAGE)            // 147456

__global__ __launch_bounds__(256, 1) void gemm_dual(
    const __half* __restrict__ Ahi, const __half* __restrict__ Alo,
    const __half* __restrict__ B1, const __half* __restrict__ B3,
    __half* __restrict__ Chi, __half* __restrict__ Clo,
    int M, int N, int K)
{
    extern __shared__ char smem[];
    const uint32_t sbase = smem_u32(smem);
    const int tid = threadIdx.x, lane = tid & 31, wid = tid >> 5;
    const int wm = wid & 1, wn = wid >> 1;
    const int bx = blockIdx.x, by = blockIdx.y;

    const size_t rowbytes = (size_t)K * 2;
    const char* base[4] = {
        (const char*)(Ahi + (size_t)by * 128 * K),
        (const char*)(Alo + (size_t)by * 128 * K),
        (const char*)(B1  + (size_t)bx * 128 * K),
        (const char*)(B3  + (size_t)bx * 128 * K)
    };

    const uint32_t aRowOff = (uint32_t)((wm * 64 + (lane & 15)) * SROW + (lane >> 4) * 16);
    const int bg = lane >> 3;
    const uint32_t bRowOff = (uint32_t)((wn * 32 + (bg >> 1) * 8 + (lane & 7)) * SROW + (bg & 1) * 16);

    auto load_slab = [&](int ks, int st) {
        uint32_t stg = sbase + (uint32_t)st * DSTAGE;
        size_t koff = (size_t)ks * 128;
        #pragma unroll
        for (int i = 0; i < 16; i++) {
            int c = tid + i * 256;
            int tn = c >> 10;
            int rr = (c >> 3) & 127;
            int ck = (c & 7) * 16;
            cp16(stg + (uint32_t)(tn * T128 + rr * SROW + ck),
                 base[tn] + (size_t)rr * rowbytes + koff + ck);
        }
        CPCOMMIT();
    };

    float acc1[4][4][4], acc3[4][4][4];
    #pragma unroll
    for (int mt = 0; mt < 4; mt++)
        #pragma unroll
        for (int nt = 0; nt < 4; nt++)
            #pragma unroll
            for (int j = 0; j < 4; j++) { acc1[mt][nt][j] = 0.f; acc3[mt][nt][j] = 0.f; }

    const int ns = K >> 6;
    load_slab(0, 0);

    for (int i = 0; i < ns; i++) {
        CPWAIT(0);
        __syncthreads();
        if (i + 1 < ns) load_slab(i + 1, (i + 1) & 1);

        uint32_t stg = sbase + (uint32_t)(i & 1) * DSTAGE;
        uint32_t aHiB = stg + aRowOff;
        uint32_t aLoB = stg + T128 + aRowOff;
        uint32_t b1B  = stg + 2 * T128 + bRowOff;
        uint32_t b3B  = stg + 3 * T128 + bRowOff;

        #pragma unroll
        for (int ks = 0; ks < 4; ks++) {
            uint32_t ah[4][4], al[4][4], b1h[2][4], b3h[2][4];
            #pragma unroll
            for (int mt = 0; mt < 4; mt++) {
                uint32_t o = (uint32_t)(mt * 16 * SROW + ks * 32);
                ldsm4(ah[mt], aHiB + o);
                ldsm4(al[mt], aLoB + o);
            }
            #pragma unroll
            for (int p = 0; p < 2; p++) {
                uint32_t o = (uint32_t)(p * 16 * SROW + ks * 32);
                ldsm4(b1h[p], b1B + o);
                ldsm4(b3h[p], b3B + o);
            }
            #pragma unroll
            for (int mt = 0; mt < 4; mt++)
                #pragma unroll
                for (int nt = 0; nt < 4; nt++) {
                    int p = nt >> 1, o = (nt & 1) * 2;
                    mma16816(acc1[mt][nt], ah[mt], b1h[p][o], b1h[p][o + 1]);
                    mma16816(acc1[mt][nt], al[mt], b1h[p][o], b1h[p][o + 1]);
                    mma16816(acc3[mt][nt], ah[mt], b3h[p][o], b3h[p][o + 1]);
                    mma16816(acc3[mt][nt], al[mt], b3h[p][o], b3h[p][o + 1]);
                }
        }
    }

    const int groupID = lane >> 2, tid4 = lane & 3;
    #pragma unroll
    for (int mt = 0; mt < 4; mt++) {
        int r0 = by * 128 + wm * 64 + mt * 16 + groupID;
        #pragma unroll
        for (int nt = 0; nt < 4; nt++) {
            int cg = bx * 128 + wn * 32 + nt * 8 + tid4 * 2;
            #pragma unroll
            for (int half = 0; half < 2; half++) {
                size_t off = (size_t)(r0 + half * 8) * N + cg;
                float t0 = silu(acc1[mt][nt][half * 2 + 0]) * acc3[mt][nt][half * 2 + 0];
                float t1 = silu(acc1[mt][nt][half * 2 + 1]) * acc3[mt][nt][half * 2 + 1];
                __half h0, l0, h1, l1;
                hf_split(t0, h0, l0);
                hf_split(t1, h1, l1);
                *(uint32_t*)(Chi + off) = pack2h(h0, h1);
                *(uint32_t*)(Clo + off) = pack2h(l0, l1);
            }
        }
    }
}

// ---------------- Fused attention (2-term fp16, pipelined loads) -------------
// smem: Qh 0, Ql 18432 | Kh stage0 36864, stage1 55296 | Vh 73728 |
//       Sh 92160 (128x136 fp16 = 34816), Sl 126976. total 161792. aS aliases Sh.
#define AROWB 144
#define SROWB 272
#define ATT_SMEM 161792
#define GROWB 8192     // global row stride of qkuv split arrays (4096 fp16)

__global__ __launch_bounds__(256, 1) void attn_mma(
    const __half* __restrict__ qkh, const __half* __restrict__ qkl,
    const float* __restrict__ nag, const float* __restrict__ nab,
    __half* __restrict__ ahi, __half* __restrict__ alo)
{
    extern __shared__ char smc[];
    const uint32_t sb = smem_u32(smc);
    const uint32_t oQh = 0, oQl = 18432;
    const uint32_t oKh[2] = {36864, 55296};
    const uint32_t oVh = 73728;
    const uint32_t oSh = 92160, oSl = 126976;
    __half* shp = (__half*)(smc + oSh);
    __half* slp = (__half*)(smc + oSl);
    float* aS = (float*)(smc + oSh);
    __shared__ float mu_s[128], rs_s[128];

    const int qb = (int)gridDim.x - 1 - (int)blockIdx.x;
    const int bh = blockIdx.y;
    const int b = bh >> 4, h = bh & 15;
    const int tid = threadIdx.x, lane = tid & 31, wid = tid >> 5;
    const int wm = wid & 1, wn = wid >> 1;
    const int groupID = lane >> 2, tid4 = lane & 3;

    const char* gh = (const char*)qkh + (size_t)(b * LL) * GROWB + h * 128;
    const char* gl = (const char*)qkl + (size_t)(b * LL) * GROWB + h * 128;

    auto ldt = [&](uint32_t so, const char* g) {
        #pragma unroll
        for (int i = 0; i < 4; i++) {
            int idx = tid + i * 256;
            int r = idx >> 3, ck = (idx & 7) * 16;
            cp16(sb + so + (uint32_t)(r * AROWB + ck), g + (size_t)r * GROWB + ck);
        }
    };

    // prologue: Q hi/lo + K(0) (hi only)
    ldt(oQh, gh + (size_t)(qb * 128) * GROWB);
    ldt(oQl, gl + (size_t)(qb * 128) * GROWB);
    ldt(oKh[0], gh + 2048);
    CPCOMMIT();

    const uint32_t aOffQ = (uint32_t)((wm * 64 + (lane & 15)) * AROWB + (lane >> 4) * 16);
    const int bg = lane >> 3;
    const uint32_t bOffK = (uint32_t)((wn * 32 + (bg >> 1) * 8 + (lane & 7)) * AROWB + (bg & 1) * 16);
    const uint32_t aOffS = (uint32_t)((wm * 64 + (lane & 15)) * SROWB + (lane >> 4) * 16);
    const uint32_t bOffV = (uint32_t)(((bg & 1) * 8 + (lane & 7)) * AROWB + (wn * 16 + (bg >> 1) * 8) * 2);

    float oacc[4][2][4];
    #pragma unroll
    for (int mt = 0; mt < 4; mt++)
        #pragma unroll
        for (int nt = 0; nt < 2; nt++)
            #pragma unroll
            for (int j = 0; j < 4; j++) oacc[mt][nt][j] = 0.f;

    for (int kb = 0; kb <= qb; kb++) {
        const int st = kb & 1;
        const bool more = (kb < qb);
        __syncthreads();
        // issue V(kb) (hi only)
        ldt(oVh, gh + 4096 + (size_t)(kb * 128) * GROWB);
        CPCOMMIT();
        // prefetch K(kb+1)
        if (more) {
            ldt(oKh[st ^ 1], gh + 2048 + (size_t)((kb + 1) * 128) * GROWB);
            CPCOMMIT();
        }
        if (more) CPWAIT(2); else CPWAIT(1);   // K(kb) ready
        __syncthreads();

        // ---- S = Q @ K^T (2-term) ----
        float sacc[4][4][4];
        #pragma unroll
        for (int mt = 0; mt < 4; mt++)
            #pragma unroll
            for (int nt = 0; nt < 4; nt++)
                #pragma unroll
                for (int j = 0; j < 4; j++) sacc[mt][nt][j] = 0.f;

        #pragma unroll
        for (int ks = 0; ks < 4; ks++) {
            uint32_t qh4[4][4], ql4[4][4], kh4[2][4];
            #pragma unroll
            for (int mt = 0; mt < 4; mt++) {
                uint32_t o = (uint32_t)(mt * 16 * AROWB + ks * 32);
                ldsm4(qh4[mt], sb + oQh + aOffQ + o);
                ldsm4(ql4[mt], sb + oQl + aOffQ + o);
            }
            #pragma unroll
            for (int p = 0; p < 2; p++) {
                uint32_t o = (uint32_t)(p * 16 * AROWB + ks * 32);
                ldsm4(kh4[p], sb + oKh[st] + bOffK + o);
            }
            #pragma unroll
            for (int mt = 0; mt < 4; mt++)
                #pragma unroll
                for (int nt = 0; nt < 4; nt++) {
                    int p = nt >> 1, o = (nt & 1) * 2;
                    mma16816(sacc[mt][nt], qh4[mt], kh4[p][o], kh4[p][o + 1]);
                    mma16816(sacc[mt][nt], ql4[mt], kh4[p][o], kh4[p][o + 1]);
                }
        }

        // ---- silu/scale/mask -> S split fp16 to smem ----
        const bool diag = (kb == qb);
        #pragma unroll
        for (int mt = 0; mt < 4; mt++) {
            #pragma unroll
            for (int half = 0; half < 2; half++) {
                int r = wm * 64 + mt * 16 + groupID + half * 8;
                #pragma unroll
                for (int nt = 0; nt < 4; nt++) {
                    int c = wn * 32 + nt * 8 + tid4 * 2;
                    float s0 = silu(sacc[mt][nt][half * 2 + 0] * 0.125f);
                    float s1 = silu(sacc[mt][nt][half * 2 + 1] * 0.125f);
                    if (diag) {
                        if (c > r) s0 = 0.f;
                        if (c + 1 > r) s1 = 0.f;
                    }
                    __half h0, l0, h1, l1;
                    hf_split(s0, h0, l0); hf_split(s1, h1, l1);
                    *(uint32_t*)(shp + r * 136 + c) = pack2h(h0, h1);
                    *(uint32_t*)(slp + r * 136 + c) = pack2h(l0, l1);
                }
            }
        }
        if (more) CPWAIT(1); else CPWAIT(0);   // V(kb) ready
        __syncthreads();

        // ---- A += S @ V (2-term, V single via ldsm.trans) ----
        #pragma unroll
        for (int ks = 0; ks < 8; ks++) {
            uint32_t sh4[4][4], sl4[4][4], vh4[4];
            #pragma unroll
            for (int mt = 0; mt < 4; mt++) {
                uint32_t o = (uint32_t)(mt * 16 * SROWB + ks * 32);
                ldsm4(sh4[mt], sb + oSh + aOffS + o);
                ldsm4(sl4[mt], sb + oSl + aOffS + o);
            }
            ldsm4t(vh4, sb + oVh + bOffV + (uint32_t)(ks * 16 * AROWB));
            #pragma unroll
            for (int mt = 0; mt < 4; mt++)
                #pragma unroll
                for (int nt = 0; nt < 2; nt++) {
                    int o = nt * 2;
                    mma16816(oacc[mt][nt], sh4[mt], vh4[o], vh4[o + 1]);
                    mma16816(oacc[mt][nt], sl4[mt], vh4[o], vh4[o + 1]);
                }
        }
    }

    // ---- headLN(d=64) * u, split out ----
    __syncthreads();
    #pragma unroll
    for (int mt = 0; mt < 4; mt++)
        #pragma unroll
        for (int half = 0; half < 2; half++) {
            int r = wm * 64 + mt * 16 + groupID + half * 8;
            #pragma unroll
            for (int nt = 0; nt < 2; nt++) {
                int c = wn * 16 + nt * 8 + tid4 * 2;
                float2 v;
                v.x = oacc[mt][nt][half * 2 + 0];
                v.y = oacc[mt][nt][half * 2 + 1];
                *(float2*)(aS + r * 68 + c) = v;
            }
        }
    __syncthreads();
    if (tid < 128) {
        float s = 0.f, s2 = 0.f;
        #pragma unroll
        for (int c = 0; c < 64; c++) {
            float v = aS[tid * 68 + c];
            s += v; s2 += v * v;
        }
        float mu = s * (1.0f / 64.0f);
        float var = s2 * (1.0f / 64.0f) - mu * mu;
        mu_s[tid] = mu;
        rs_s[tid] = rsqrtf(var + 1e-5f);
    }
    __syncthreads();
    {
        int r = tid >> 1;
        int c0 = (tid & 1) * 32;
        int l = qb * 128 + r;
        float mu = mu_s[r], rstd = rs_s[r];
        const __half* uh = (const __half*)(gh + 6144 + (size_t)l * GROWB);
        const __half* ul = (const __half*)(gl + 6144 + (size_t)l * GROWB);
        size_t obase = (size_t)(b * LL + l) * DD + h * HD;
        #pragma unroll
        for (int c = c0; c < c0 + 32; c += 2) {
            float u0 = __half2float(uh[c + 0]) + __half2float(ul[c + 0]);
            float u1 = __half2float(uh[c + 1]) + __half2float(ul[c + 1]);
            float t0 = ((aS[r * 68 + c + 0] - mu) * rstd * nag[c + 0] + nab[c + 0]) * u0;
            float t1 = ((aS[r * 68 + c + 1] - mu) * rstd * nag[c + 1] + nab[c + 1]) * u1;
            __half h0, l0, h1, l1;
            hf_split(t0, h0, l0); hf_split(t1, h1, l1);
            *(uint32_t*)(ahi + obase + c) = pack2h(h0, h1);
            *(uint32_t*)(alo + obase + c) = pack2h(l0, l1);
        }
    }
}

// ---------------- host -------------------------------------------------------
extern "C" void kernel_launch(void* const* d_in, const int* in_sizes, int n_in,
                              void* d_out, int out_size)
{
    const float* x      = (const float*)d_in[0];
    const float* w_qkuv = (const float*)d_in[2];
    const float* w_out  = (const float*)d_in[3];
    const float* w1     = (const float*)d_in[4];
    const float* w2     = (const float*)d_in[5];
    const float* w3     = (const float*)d_in[6];
    const float* ln1_g  = (const float*)d_in[7];
    const float* ln1_b  = (const float*)d_in[8];
    const float* ln2_g  = (const float*)d_in[9];
    const float* ln2_b  = (const float*)d_in[10];
    const float* na_g   = (const float*)d_in[11];
    const float* na_b   = (const float*)d_in[12];
    float* out = (float*)d_out;

    __half *xnh, *xnl, *qkh, *qkl, *ah, *al, *xn2h, *xn2l, *hh, *hl;
    __half *wq, *wo, *w1t, *w3t, *w2t;
    float *x1;
    cudaGetSymbolAddress((void**)&xnh,  g_xn_hi);  cudaGetSymbolAddress((void**)&xnl,  g_xn_lo);
    cudaGetSymbolAddress((void**)&qkh,  g_qk_hi);  cudaGetSymbolAddress((void**)&qkl,  g_qk_lo);
    cudaGetSymbolAddress((void**)&ah,   g_a_hi);   cudaGetSymbolAddress((void**)&al,   g_a_lo);
    cudaGetSymbolAddress((void**)&x1,   g_x1);
    cudaGetSymbolAddress((void**)&xn2h, g_xn2_hi); cudaGetSymbolAddress((void**)&xn2l, g_xn2_lo);
    cudaGetSymbolAddress((void**)&hh,   g_h_hi);   cudaGetSymbolAddress((void**)&hl,   g_h_lo);
    cudaGetSymbolAddress((void**)&wq,   g_wqkuv);
    cudaGetSymbolAddress((void**)&wo,   g_wout);
    cudaGetSymbolAddress((void**)&w1t,  g_w1);
    cudaGetSymbolAddress((void**)&w3t,  g_w3);
    cudaGetSymbolAddress((void**)&w2t,  g_w2);

    cudaFuncSetAttribute(gemm_mma<1>, cudaFuncAttributeMaxDynamicSharedMemorySize, GEMM_SMEM);
    cudaFuncSetAttribute(gemm_mma<3>, cudaFuncAttributeMaxDynamicSharedMemorySize, GEMM_SMEM);
    cudaFuncSetAttribute(gemm_dual,   cudaFuncAttributeMaxDynamicSharedMemorySize, DUAL_SMEM);
    cudaFuncSetAttribute(attn_mma,    cudaFuncAttributeMaxDynamicSharedMemorySize, ATT_SMEM);

    dim3 blk(256);

    // 0. weight transpose -> fp16
    wconv_kernel<<<dim3(4 * DD / 32, DD / 32), blk>>>(w_qkuv, wq,  DD, 4 * DD);
    wconv_kernel<<<dim3(DD / 32, DD / 32),     blk>>>(w_out,  wo,  DD, DD);
    wconv_kernel<<<dim3(FF / 32, DD / 32),     blk>>>(w1,     w1t, DD, FF);
    wconv_kernel<<<dim3(FF / 32, DD / 32),     blk>>>(w3,     w3t, DD, FF);
    wconv_kernel<<<dim3(DD / 32, FF / 32),     blk>>>(w2,     w2t, FF, DD);

    // 1. LN1 -> split fp16
    ln_split_kernel<<<MROWS, blk>>>(x, ln1_g, ln1_b, xnh, xnl);
    // 2. qkuv = silu(xn @ w_qkuv) -> split fp16
    gemm_mma<3><<<dim3(4 * DD / 128, MROWS / 128), blk, GEMM_SMEM>>>(
        xnh, xnl, wq, nullptr, nullptr, qkh, qkl, MROWS, 4 * DD, DD);
    // 3. attention -> a hi/lo
    attn_mma<<<dim3(LL / 128, BB * HH), blk, ATT_SMEM>>>(qkh, qkl, na_g, na_b, ah, al);
    // 4. x1 = x + a @ w_out
    gemm_mma<1><<<dim3(DD / 128, MROWS / 128), blk, GEMM_SMEM>>>(
        ah, al, wo, x1, x, nullptr, nullptr, MROWS, DD, DD);
    // 5. LN2 -> split fp16
    ln_split_kernel<<<MROWS, blk>>>(x1, ln2_g, ln2_b, xn2h, xn2l);
    // 6+7. h = silu(xn2@w1) * (xn2@w3) -> split fp16
    gemm_dual<<<dim3(FF / 128, MROWS / 128), blk, DUAL_SMEM>>>(
        xn2h, xn2l, w1t, w3t, hh, hl, MROWS, FF, DD);
    // 8. out = x1 + h @ w2
    gemm_mma<1><<<dim3(DD / 128, MROWS / 128), blk, GEMM_SMEM>>>(
        hh, hl, w2t, out, x1, nullptr, nullptr, MROWS, DD, FF);
}

// round 9
// speedup vs baseline: 2.1476x; 1.5641x over previous
#include <cuda_runtime.h>
#include <cuda_fp16.h>
#include <cstdint>
#include <math.h>

#define BB 2
#define LL 2048
#define DD 1024
#define HH 16
#define HD 64
#define FF 4096
#define MROWS (BB*LL)   // 4096

// ---------------- scratch (device globals) ---------------------------------
__device__ __half g_xn  [MROWS * DD];
__device__ __half g_qk  [MROWS * 4 * DD];   // silu(xn@w_qkuv) fp16
__device__ __half g_a   [MROWS * DD];
__device__ float  g_x1  [MROWS * DD];
__device__ __half g_xn2 [MROWS * DD];
__device__ __half g_h   [MROWS * FF];
// transposed weights: [N, K] K-major, fp16
__device__ __half g_wqkuv [4 * DD * DD];
__device__ __half g_wout  [DD * DD];
__device__ __half g_w1    [DD * FF];
__device__ __half g_w3    [DD * FF];
__device__ __half g_w2    [FF * DD];

__device__ __forceinline__ float silu(float x) {
    return __fdividef(x, 1.0f + __expf(-x));
}
__device__ __forceinline__ uint32_t smem_u32(const void* p) {
    uint32_t a;
    asm("{ .reg .u64 t; cvta.to.shared.u64 t, %1; cvt.u32.u64 %0, t; }" : "=r"(a) : "l"(p));
    return a;
}
__device__ __forceinline__ void cp16(uint32_t s, const void* g) {
    asm volatile("cp.async.cg.shared.global [%0], [%1], 16;" :: "r"(s), "l"(g) : "memory");
}
#define CPCOMMIT() asm volatile("cp.async.commit_group;" ::: "memory")
#define CPWAIT(n)  asm volatile("cp.async.wait_group %0;" :: "n"(n) : "memory")
__device__ __forceinline__ uint32_t pack2h(__half a, __half b) {
    return (uint32_t)__half_as_ushort(a) | ((uint32_t)__half_as_ushort(b) << 16);
}
__device__ __forceinline__ void ldsm4(uint32_t* r, uint32_t a) {
    asm volatile("ldmatrix.sync.aligned.m8n8.x4.shared.b16 {%0,%1,%2,%3}, [%4];"
        : "=r"(r[0]), "=r"(r[1]), "=r"(r[2]), "=r"(r[3]) : "r"(a));
}
__device__ __forceinline__ void ldsm4t(uint32_t* r, uint32_t a) {
    asm volatile("ldmatrix.sync.aligned.m8n8.x4.trans.shared.b16 {%0,%1,%2,%3}, [%4];"
        : "=r"(r[0]), "=r"(r[1]), "=r"(r[2]), "=r"(r[3]) : "r"(a));
}
__device__ __forceinline__ void mma16816(float* c, const uint32_t* a, uint32_t b0, uint32_t b1) {
    asm volatile(
        "mma.sync.aligned.m16n8k16.row.col.f32.f16.f16.f32 "
        "{%0,%1,%2,%3}, {%4,%5,%6,%7}, {%8,%9}, {%0,%1,%2,%3};"
        : "+f"(c[0]), "+f"(c[1]), "+f"(c[2]), "+f"(c[3])
        : "r"(a[0]), "r"(a[1]), "r"(a[2]), "r"(a[3]), "r"(b0), "r"(b1));
}

// ---------------- weight transpose -> fp16: w[K,N] -> wt[N,K] ---------------
__global__ __launch_bounds__(256) void wconv_kernel(
    const float* __restrict__ w, __half* __restrict__ wt, int K, int N)
{
    __shared__ float t[32][33];
    int n0 = blockIdx.x * 32, k0 = blockIdx.y * 32;
    int tx = threadIdx.x & 31, ty = threadIdx.x >> 5;
    #pragma unroll
    for (int j = 0; j < 4; j++)
        t[ty + j * 8][tx] = w[(size_t)(k0 + ty + j * 8) * N + n0 + tx];
    __syncthreads();
    #pragma unroll
    for (int j = 0; j < 4; j++) {
        int nn = ty + j * 8;
        wt[(size_t)(n0 + nn) * K + k0 + tx] = __float2half(t[tx][nn]);
    }
}

// ---------------- LayerNorm -> fp16 ------------------------------------------
__global__ __launch_bounds__(256) void ln_half_kernel(
    const float* __restrict__ x, const float* __restrict__ g,
    const float* __restrict__ b, __half* __restrict__ o)
{
    int row = blockIdx.x;
    const float* xr = x + (size_t)row * DD;
    float s = 0.f, s2 = 0.f;
    for (int i = threadIdx.x; i < DD; i += 256) {
        float v = xr[i]; s += v; s2 += v * v;
    }
    __shared__ float red[8], red2[8], stats[2];
    for (int off = 16; off > 0; off >>= 1) {
        s  += __shfl_down_sync(0xffffffffu, s,  off);
        s2 += __shfl_down_sync(0xffffffffu, s2, off);
    }
    int wid = threadIdx.x >> 5, lid = threadIdx.x & 31;
    if (lid == 0) { red[wid] = s; red2[wid] = s2; }
    __syncthreads();
    if (threadIdx.x == 0) {
        float ts = 0.f, ts2 = 0.f;
        for (int i = 0; i < 8; i++) { ts += red[i]; ts2 += red2[i]; }
        float mu = ts * (1.0f / DD);
        float var = ts2 * (1.0f / DD) - mu * mu;
        stats[0] = mu; stats[1] = rsqrtf(var + 1e-5f);
    }
    __syncthreads();
    float mu = stats[0], rstd = stats[1];
    for (int i = threadIdx.x; i < DD; i += 256) {
        o[(size_t)row * DD + i] = __float2half((xr[i] - mu) * rstd * g[i] + b[i]);
    }
}

// ---------------- fp16 GEMM: D = A @ W^T -------------------------------------
// MODE 1: Cf = acc + aux (fp32 out).  MODE 3: silu(acc) -> Ch fp16.
// CTA 128x128, BK=64, warp 64x32 (2x4 grid), 3-stage pipeline.
#define SROW 144                    // padded row bytes (72 fp16)
#define T128 (128 * SROW)           // 18432
#define STAGE3 (2 * T128)           // 36864 : A, W
#define GEMM_SMEM (3 * STAGE3)      // 110592

template <int MODE>
__global__ __launch_bounds__(256, 1) void gemm_mma(
    const __half* __restrict__ A, const __half* __restrict__ Bw,
    float* __restrict__ Cf, const float* __restrict__ aux,
    __half* __restrict__ Ch,
    int M, int N, int K)
{
    extern __shared__ char smem[];
    const uint32_t sbase = smem_u32(smem);
    const int tid = threadIdx.x, lane = tid & 31, wid = tid >> 5;
    const int wm = wid & 1, wn = wid >> 1;
    const int bx = blockIdx.x, by = blockIdx.y;

    const size_t rowbytes = (size_t)K * 2;
    const char* Ab = (const char*)(A  + (size_t)by * 128 * K);
    const char* Bb = (const char*)(Bw + (size_t)bx * 128 * K);

    const uint32_t aRowOff = (uint32_t)((wm * 64 + (lane & 15)) * SROW + (lane >> 4) * 16);
    const int bg = lane >> 3;
    const uint32_t bRowOff = (uint32_t)((wn * 32 + (bg >> 1) * 8 + (lane & 7)) * SROW + (bg & 1) * 16);

    auto load_slab = [&](int ks, int st) {
        uint32_t stg = sbase + (uint32_t)st * STAGE3;
        size_t koff = (size_t)ks * 128;        // 64 fp16 = 128 B
        #pragma unroll
        for (int i = 0; i < 8; i++) {          // 2 tensors x 1024 chunks
            int c = tid + i * 256;
            int tn = c >> 10;
            int rr = (c >> 3) & 127;
            int ck = (c & 7) * 16;
            cp16(stg + (uint32_t)(tn * T128 + rr * SROW + ck),
                 (tn ? Bb : Ab) + (size_t)rr * rowbytes + koff + ck);
        }
        CPCOMMIT();
    };

    float acc[4][4][4];
    #pragma unroll
    for (int mt = 0; mt < 4; mt++)
        #pragma unroll
        for (int nt = 0; nt < 4; nt++)
            #pragma unroll
            for (int j = 0; j < 4; j++) acc[mt][nt][j] = 0.f;

    const int ns = K >> 6;
    load_slab(0, 0);
    if (ns > 1) load_slab(1, 1);

    for (int i = 0; i < ns; i++) {
        if (i + 1 < ns) CPWAIT(1);
        else            CPWAIT(0);
        __syncthreads();
        if (i + 2 < ns) load_slab(i + 2, (i + 2) % 3);

        uint32_t stg = sbase + (uint32_t)(i % 3) * STAGE3;
        uint32_t aB = stg + aRowOff;
        uint32_t bB = stg + T128 + bRowOff;

        #pragma unroll
        for (int ks = 0; ks < 4; ks++) {
            uint32_t ah[4][4], bh[2][4];
            #pragma unroll
            for (int mt = 0; mt < 4; mt++)
                ldsm4(ah[mt], aB + (uint32_t)(mt * 16 * SROW + ks * 32));
            #pragma unroll
            for (int p = 0; p < 2; p++)
                ldsm4(bh[p], bB + (uint32_t)(p * 16 * SROW + ks * 32));
            #pragma unroll
            for (int mt = 0; mt < 4; mt++)
                #pragma unroll
                for (int nt = 0; nt < 4; nt++) {
                    int p = nt >> 1, o = (nt & 1) * 2;
                    mma16816(acc[mt][nt], ah[mt], bh[p][o], bh[p][o + 1]);
                }
        }
    }

    const int groupID = lane >> 2, tid4 = lane & 3;
    #pragma unroll
    for (int mt = 0; mt < 4; mt++) {
        int r0 = by * 128 + wm * 64 + mt * 16 + groupID;
        #pragma unroll
        for (int nt = 0; nt < 4; nt++) {
            int cg = bx * 128 + wn * 32 + nt * 8 + tid4 * 2;
            float* a = acc[mt][nt];
            #pragma unroll
            for (int half = 0; half < 2; half++) {
                size_t off = (size_t)(r0 + half * 8) * N + cg;
                float v0 = a[half * 2 + 0], v1 = a[half * 2 + 1];
                if (MODE == 1) {
                    float2 ax = *(const float2*)(aux + off);
                    float2 o; o.x = v0 + ax.x; o.y = v1 + ax.y;
                    *(float2*)(Cf + off) = o;
                } else {
                    *(uint32_t*)(Ch + off) = pack2h(__float2half(silu(v0)),
                                                    __float2half(silu(v1)));
                }
            }
        }
    }
}

// ---------------- dual GEMM: h = silu(A@W1) * (A@W3) -> fp16 -----------------
#define DSTAGE (3 * T128)                 // 55296 : A, W1, W3
#define DUAL_SMEM (2 * DSTAGE)            // 110592

__global__ __launch_bounds__(256, 1) void gemm_dual(
    const __half* __restrict__ A,
    const __half* __restrict__ B1, const __half* __restrict__ B3,
    __half* __restrict__ Ch,
    int M, int N, int K)
{
    extern __shared__ char smem[];
    const uint32_t sbase = smem_u32(smem);
    const int tid = threadIdx.x, lane = tid & 31, wid = tid >> 5;
    const int wm = wid & 1, wn = wid >> 1;
    const int bx = blockIdx.x, by = blockIdx.y;

    const size_t rowbytes = (size_t)K * 2;
    const char* base[3] = {
        (const char*)(A  + (size_t)by * 128 * K),
        (const char*)(B1 + (size_t)bx * 128 * K),
        (const char*)(B3 + (size_t)bx * 128 * K)
    };

    const uint32_t aRowOff = (uint32_t)((wm * 64 + (lane & 15)) * SROW + (lane >> 4) * 16);
    const int bg = lane >> 3;
    const uint32_t bRowOff = (uint32_t)((wn * 32 + (bg >> 1) * 8 + (lane & 7)) * SROW + (bg & 1) * 16);

    auto load_slab = [&](int ks, int st) {
        uint32_t stg = sbase + (uint32_t)st * DSTAGE;
        size_t koff = (size_t)ks * 128;
        #pragma unroll
        for (int i = 0; i < 12; i++) {
            int c = tid + i * 256;
            int tn = c >> 10;
            int rr = (c >> 3) & 127;
            int ck = (c & 7) * 16;
            cp16(stg + (uint32_t)(tn * T128 + rr * SROW + ck),
                 base[tn] + (size_t)rr * rowbytes + koff + ck);
        }
        CPCOMMIT();
    };

    float acc1[4][4][4], acc3[4][4][4];
    #pragma unroll
    for (int mt = 0; mt < 4; mt++)
        #pragma unroll
        for (int nt = 0; nt < 4; nt++)
            #pragma unroll
            for (int j = 0; j < 4; j++) { acc1[mt][nt][j] = 0.f; acc3[mt][nt][j] = 0.f; }

    const int ns = K >> 6;
    load_slab(0, 0);

    for (int i = 0; i < ns; i++) {
        CPWAIT(0);
        __syncthreads();
        if (i + 1 < ns) load_slab(i + 1, (i + 1) & 1);

        uint32_t stg = sbase + (uint32_t)(i & 1) * DSTAGE;
        uint32_t aB  = stg + aRowOff;
        uint32_t b1B = stg + T128 + bRowOff;
        uint32_t b3B = stg + 2 * T128 + bRowOff;

        #pragma unroll
        for (int ks = 0; ks < 4; ks++) {
            uint32_t ah[4][4], b1h[2][4], b3h[2][4];
            #pragma unroll
            for (int mt = 0; mt < 4; mt++)
                ldsm4(ah[mt], aB + (uint32_t)(mt * 16 * SROW + ks * 32));
            #pragma unroll
            for (int p = 0; p < 2; p++) {
                uint32_t o = (uint32_t)(p * 16 * SROW + ks * 32);
                ldsm4(b1h[p], b1B + o);
                ldsm4(b3h[p], b3B + o);
            }
            #pragma unroll
            for (int mt = 0; mt < 4; mt++)
                #pragma unroll
                for (int nt = 0; nt < 4; nt++) {
                    int p = nt >> 1, o = (nt & 1) * 2;
                    mma16816(acc1[mt][nt], ah[mt], b1h[p][o], b1h[p][o + 1]);
                    mma16816(acc3[mt][nt], ah[mt], b3h[p][o], b3h[p][o + 1]);
                }
        }
    }

    const int groupID = lane >> 2, tid4 = lane & 3;
    #pragma unroll
    for (int mt = 0; mt < 4; mt++) {
        int r0 = by * 128 + wm * 64 + mt * 16 + groupID;
        #pragma unroll
        for (int nt = 0; nt < 4; nt++) {
            int cg = bx * 128 + wn * 32 + nt * 8 + tid4 * 2;
            #pragma unroll
            for (int half = 0; half < 2; half++) {
                size_t off = (size_t)(r0 + half * 8) * N + cg;
                float t0 = silu(acc1[mt][nt][half * 2 + 0]) * acc3[mt][nt][half * 2 + 0];
                float t1 = silu(acc1[mt][nt][half * 2 + 1]) * acc3[mt][nt][half * 2 + 1];
                *(uint32_t*)(Ch + off) = pack2h(__float2half(t0), __float2half(t1));
            }
        }
    }
}

// ---------------- Fused attention (fp16, pipelined loads) --------------------
// smem: Q 0 (18432) | K stage0 18432, stage1 36864 | V 55296 |
//       S 73728 (128x136 fp16 = 34816). total 108544. aS (fp32 [128][68]) aliases S.
#define AROWB 144
#define SROWB 272
#define ATT_SMEM 108544
#define GROWB 8192     // global row stride of qkuv (4096 fp16)

__global__ __launch_bounds__(256, 1) void attn_mma(
    const __half* __restrict__ qk,
    const float* __restrict__ nag, const float* __restrict__ nab,
    __half* __restrict__ aout)
{
    extern __shared__ char smc[];
    const uint32_t sb = smem_u32(smc);
    const uint32_t oQ = 0;
    const uint32_t oK[2] = {18432, 36864};
    const uint32_t oV = 55296;
    const uint32_t oS = 73728;
    __half* sp = (__half*)(smc + oS);
    float* aS = (float*)(smc + oS);
    __shared__ float mu_s[128], rs_s[128];

    const int qb = (int)gridDim.x - 1 - (int)blockIdx.x;
    const int bh = blockIdx.y;
    const int b = bh >> 4, h = bh & 15;
    const int tid = threadIdx.x, lane = tid & 31, wid = tid >> 5;
    const int wm = wid & 1, wn = wid >> 1;
    const int groupID = lane >> 2, tid4 = lane & 3;

    const char* gq = (const char*)qk + (size_t)(b * LL) * GROWB + h * 128;

    auto ldt = [&](uint32_t so, const char* g) {
        #pragma unroll
        for (int i = 0; i < 4; i++) {
            int idx = tid + i * 256;
            int r = idx >> 3, ck = (idx & 7) * 16;
            cp16(sb + so + (uint32_t)(r * AROWB + ck), g + (size_t)r * GROWB + ck);
        }
    };

    // prologue: Q + K(0)
    ldt(oQ, gq + (size_t)(qb * 128) * GROWB);
    ldt(oK[0], gq + 2048);
    CPCOMMIT();

    const uint32_t aOffQ = (uint32_t)((wm * 64 + (lane & 15)) * AROWB + (lane >> 4) * 16);
    const int bg = lane >> 3;
    const uint32_t bOffK = (uint32_t)((wn * 32 + (bg >> 1) * 8 + (lane & 7)) * AROWB + (bg & 1) * 16);
    const uint32_t aOffS = (uint32_t)((wm * 64 + (lane & 15)) * SROWB + (lane >> 4) * 16);
    const uint32_t bOffV = (uint32_t)(((bg & 1) * 8 + (lane & 7)) * AROWB + (wn * 16 + (bg >> 1) * 8) * 2);

    float oacc[4][2][4];
    #pragma unroll
    for (int mt = 0; mt < 4; mt++)
        #pragma unroll
        for (int nt = 0; nt < 2; nt++)
            #pragma unroll
            for (int j = 0; j < 4; j++) oacc[mt][nt][j] = 0.f;

    for (int kb = 0; kb <= qb; kb++) {
        const int st = kb & 1;
        const bool more = (kb < qb);
        __syncthreads();
        ldt(oV, gq + 4096 + (size_t)(kb * 128) * GROWB);
        CPCOMMIT();
        if (more) {
            ldt(oK[st ^ 1], gq + 2048 + (size_t)((kb + 1) * 128) * GROWB);
            CPCOMMIT();
        }
        if (more) CPWAIT(2); else CPWAIT(1);   // K(kb) ready
        __syncthreads();

        // ---- S = Q @ K^T ----
        float sacc[4][4][4];
        #pragma unroll
        for (int mt = 0; mt < 4; mt++)
            #pragma unroll
            for (int nt = 0; nt < 4; nt++)
                #pragma unroll
                for (int j = 0; j < 4; j++) sacc[mt][nt][j] = 0.f;

        #pragma unroll
        for (int ks = 0; ks < 4; ks++) {
            uint32_t q4[4][4], k4[2][4];
            #pragma unroll
            for (int mt = 0; mt < 4; mt++)
                ldsm4(q4[mt], sb + oQ + aOffQ + (uint32_t)(mt * 16 * AROWB + ks * 32));
            #pragma unroll
            for (int p = 0; p < 2; p++)
                ldsm4(k4[p], sb + oK[st] + bOffK + (uint32_t)(p * 16 * AROWB + ks * 32));
            #pragma unroll
            for (int mt = 0; mt < 4; mt++)
                #pragma unroll
                for (int nt = 0; nt < 4; nt++) {
                    int p = nt >> 1, o = (nt & 1) * 2;
                    mma16816(sacc[mt][nt], q4[mt], k4[p][o], k4[p][o + 1]);
                }
        }

        // ---- silu/scale/mask -> S fp16 to smem ----
        const bool diag = (kb == qb);
        #pragma unroll
        for (int mt = 0; mt < 4; mt++) {
            #pragma unroll
            for (int half = 0; half < 2; half++) {
                int r = wm * 64 + mt * 16 + groupID + half * 8;
                #pragma unroll
                for (int nt = 0; nt < 4; nt++) {
                    int c = wn * 32 + nt * 8 + tid4 * 2;
                    float s0 = silu(sacc[mt][nt][half * 2 + 0] * 0.125f);
                    float s1 = silu(sacc[mt][nt][half * 2 + 1] * 0.125f);
                    if (diag) {
                        if (c > r) s0 = 0.f;
                        if (c + 1 > r) s1 = 0.f;
                    }
                    *(uint32_t*)(sp + r * 136 + c) = pack2h(__float2half(s0), __float2half(s1));
                }
            }
        }
        if (more) CPWAIT(1); else CPWAIT(0);   // V(kb) ready
        __syncthreads();

        // ---- A += S @ V (V via ldsm.trans) ----
        #pragma unroll
        for (int ks = 0; ks < 8; ks++) {
            uint32_t s4[4][4], v4[4];
            #pragma unroll
            for (int mt = 0; mt < 4; mt++)
                ldsm4(s4[mt], sb + oS + aOffS + (uint32_t)(mt * 16 * SROWB + ks * 32));
            ldsm4t(v4, sb + oV + bOffV + (uint32_t)(ks * 16 * AROWB));
            #pragma unroll
            for (int mt = 0; mt < 4; mt++)
                #pragma unroll
                for (int nt = 0; nt < 2; nt++) {
                    int o = nt * 2;
                    mma16816(oacc[mt][nt], s4[mt], v4[o], v4[o + 1]);
                }
        }
    }

    // ---- headLN(d=64) * u -> fp16 out ----
    __syncthreads();
    #pragma unroll
    for (int mt = 0; mt < 4; mt++)
        #pragma unroll
        for (int half = 0; half < 2; half++) {
            int r = wm * 64 + mt * 16 + groupID + half * 8;
            #pragma unroll
            for (int nt = 0; nt < 2; nt++) {
                int c = wn * 16 + nt * 8 + tid4 * 2;
                float2 v;
                v.x = oacc[mt][nt][half * 2 + 0];
                v.y = oacc[mt][nt][half * 2 + 1];
                *(float2*)(aS + r * 68 + c) = v;
            }
        }
    __syncthreads();
    if (tid < 128) {
        float s = 0.f, s2 = 0.f;
        #pragma unroll
        for (int c = 0; c < 64; c++) {
            float v = aS[tid * 68 + c];
            s += v; s2 += v * v;
        }
        float mu = s * (1.0f / 64.0f);
        float var = s2 * (1.0f / 64.0f) - mu * mu;
        mu_s[tid] = mu;
        rs_s[tid] = rsqrtf(var + 1e-5f);
    }
    __syncthreads();
    {
        int r = tid >> 1;
        int c0 = (tid & 1) * 32;
        int l = qb * 128 + r;
        float mu = mu_s[r], rstd = rs_s[r];
        const __half* uh = (const __half*)(gq + 6144 + (size_t)l * GROWB);
        size_t obase = (size_t)(b * LL + l) * DD + h * HD;
        #pragma unroll
        for (int c = c0; c < c0 + 32; c += 2) {
            float u0 = __half2float(uh[c + 0]);
            float u1 = __half2float(uh[c + 1]);
            float t0 = ((aS[r * 68 + c + 0] - mu) * rstd * nag[c + 0] + nab[c + 0]) * u0;
            float t1 = ((aS[r * 68 + c + 1] - mu) * rstd * nag[c + 1] + nab[c + 1]) * u1;
            *(uint32_t*)(aout + obase + c) = pack2h(__float2half(t0), __float2half(t1));
        }
    }
}

// ---------------- host -------------------------------------------------------
extern "C" void kernel_launch(void* const* d_in, const int* in_sizes, int n_in,
                              void* d_out, int out_size)
{
    const float* x      = (const float*)d_in[0];
    const float* w_qkuv = (const float*)d_in[2];
    const float* w_out  = (const float*)d_in[3];
    const float* w1     = (const float*)d_in[4];
    const float* w2     = (const float*)d_in[5];
    const float* w3     = (const float*)d_in[6];
    const float* ln1_g  = (const float*)d_in[7];
    const float* ln1_b  = (const float*)d_in[8];
    const float* ln2_g  = (const float*)d_in[9];
    const float* ln2_b  = (const float*)d_in[10];
    const float* na_g   = (const float*)d_in[11];
    const float* na_b   = (const float*)d_in[12];
    float* out = (float*)d_out;

    __half *xn, *qk, *a, *xn2, *hbuf;
    __half *wq, *wo, *w1t, *w3t, *w2t;
    float *x1;
    cudaGetSymbolAddress((void**)&xn,   g_xn);
    cudaGetSymbolAddress((void**)&qk,   g_qk);
    cudaGetSymbolAddress((void**)&a,    g_a);
    cudaGetSymbolAddress((void**)&x1,   g_x1);
    cudaGetSymbolAddress((void**)&xn2,  g_xn2);
    cudaGetSymbolAddress((void**)&hbuf, g_h);
    cudaGetSymbolAddress((void**)&wq,   g_wqkuv);
    cudaGetSymbolAddress((void**)&wo,   g_wout);
    cudaGetSymbolAddress((void**)&w1t,  g_w1);
    cudaGetSymbolAddress((void**)&w3t,  g_w3);
    cudaGetSymbolAddress((void**)&w2t,  g_w2);

    cudaFuncSetAttribute(gemm_mma<1>, cudaFuncAttributeMaxDynamicSharedMemorySize, GEMM_SMEM);
    cudaFuncSetAttribute(gemm_mma<3>, cudaFuncAttributeMaxDynamicSharedMemorySize, GEMM_SMEM);
    cudaFuncSetAttribute(gemm_dual,   cudaFuncAttributeMaxDynamicSharedMemorySize, DUAL_SMEM);
    cudaFuncSetAttribute(attn_mma,    cudaFuncAttributeMaxDynamicSharedMemorySize, ATT_SMEM);

    dim3 blk(256);

    // 0. weight transpose -> fp16
    wconv_kernel<<<dim3(4 * DD / 32, DD / 32), blk>>>(w_qkuv, wq,  DD, 4 * DD);
    wconv_kernel<<<dim3(DD / 32, DD / 32),     blk>>>(w_out,  wo,  DD, DD);
    wconv_kernel<<<dim3(FF / 32, DD / 32),     blk>>>(w1,     w1t, DD, FF);
    wconv_kernel<<<dim3(FF / 32, DD / 32),     blk>>>(w3,     w3t, DD, FF);
    wconv_kernel<<<dim3(DD / 32, FF / 32),     blk>>>(w2,     w2t, FF, DD);

    // 1. LN1 -> fp16
    ln_half_kernel<<<MROWS, blk>>>(x, ln1_g, ln1_b, xn);
    // 2. qkuv = silu(xn @ w_qkuv) -> fp16
    gemm_mma<3><<<dim3(4 * DD / 128, MROWS / 128), blk, GEMM_SMEM>>>(
        xn, wq, nullptr, nullptr, qk, MROWS, 4 * DD, DD);
    // 3. attention -> a fp16
    attn_mma<<<dim3(LL / 128, BB * HH), blk, ATT_SMEM>>>(qk, na_g, na_b, a);
    // 4. x1 = x + a @ w_out
    gemm_mma<1><<<dim3(DD / 128, MROWS / 128), blk, GEMM_SMEM>>>(
        a, wo, x1, x, nullptr, MROWS, DD, DD);
    // 5. LN2 -> fp16
    ln_half_kernel<<<MROWS, blk>>>(x1, ln2_g, ln2_b, xn2);
    // 6+7. h = silu(xn2@w1) * (xn2@w3) -> fp16
    gemm_dual<<<dim3(FF / 128, MROWS / 128), blk, DUAL_SMEM>>>(
        xn2, w1t, w3t, hbuf, MROWS, FF, DD);
    // 8. out = x1 + h @ w2
    gemm_mma<1><<<dim3(DD / 128, MROWS / 128), blk, GEMM_SMEM>>>(
        hbuf, w2t, out, x1, nullptr, MROWS, DD, FF);
}

// round 10
// speedup vs baseline: 2.3549x; 1.0965x over previous
#include <cuda_runtime.h>
#include <cuda_fp16.h>
#include <cstdint>
#include <math.h>

#define BB 2
#define LL 2048
#define DD 1024
#define HH 16
#define HD 64
#define FF 4096
#define MROWS (BB*LL)   // 4096

// ---------------- scratch (device globals) ---------------------------------
__device__ __half g_xn  [MROWS * DD];
__device__ __half g_qk  [MROWS * 4 * DD];   // silu(xn@w_qkuv) fp16
__device__ __half g_a   [MROWS * DD];
__device__ float  g_x1  [MROWS * DD];
__device__ __half g_xn2 [MROWS * DD];
__device__ __half g_h   [MROWS * FF];
// transposed weights: [N, K] K-major, fp16
__device__ __half g_wqkuv [4 * DD * DD];
__device__ __half g_wout  [DD * DD];
__device__ __half g_w1    [DD * FF];
__device__ __half g_w3    [DD * FF];
__device__ __half g_w2    [FF * DD];

__device__ __forceinline__ float silu(float x) {
    return __fdividef(x, 1.0f + __expf(-x));
}
__device__ __forceinline__ uint32_t smem_u32(const void* p) {
    uint32_t a;
    asm("{ .reg .u64 t; cvta.to.shared.u64 t, %1; cvt.u32.u64 %0, t; }" : "=r"(a) : "l"(p));
    return a;
}
__device__ __forceinline__ void cp16(uint32_t s, const void* g) {
    asm volatile("cp.async.cg.shared.global [%0], [%1], 16;" :: "r"(s), "l"(g) : "memory");
}
#define CPCOMMIT() asm volatile("cp.async.commit_group;" ::: "memory")
#define CPWAIT(n)  asm volatile("cp.async.wait_group %0;" :: "n"(n) : "memory")
__device__ __forceinline__ uint32_t pack2h(__half a, __half b) {
    return (uint32_t)__half_as_ushort(a) | ((uint32_t)__half_as_ushort(b) << 16);
}
__device__ __forceinline__ void ldsm4(uint32_t* r, uint32_t a) {
    asm volatile("ldmatrix.sync.aligned.m8n8.x4.shared.b16 {%0,%1,%2,%3}, [%4];"
        : "=r"(r[0]), "=r"(r[1]), "=r"(r[2]), "=r"(r[3]) : "r"(a));
}
__device__ __forceinline__ void ldsm4t(uint32_t* r, uint32_t a) {
    asm volatile("ldmatrix.sync.aligned.m8n8.x4.trans.shared.b16 {%0,%1,%2,%3}, [%4];"
        : "=r"(r[0]), "=r"(r[1]), "=r"(r[2]), "=r"(r[3]) : "r"(a));
}
__device__ __forceinline__ void mma16816(float* c, const uint32_t* a, uint32_t b0, uint32_t b1) {
    asm volatile(
        "mma.sync.aligned.m16n8k16.row.col.f32.f16.f16.f32 "
        "{%0,%1,%2,%3}, {%4,%5,%6,%7}, {%8,%9}, {%0,%1,%2,%3};"
        : "+f"(c[0]), "+f"(c[1]), "+f"(c[2]), "+f"(c[3])
        : "r"(a[0]), "r"(a[1]), "r"(a[2]), "r"(a[3]), "r"(b0), "r"(b1));
}

// ---------------- weight transpose -> fp16: w[K,N] -> wt[N,K] ---------------
__global__ __launch_bounds__(256) void wconv_kernel(
    const float* __restrict__ w, __half* __restrict__ wt, int K, int N)
{
    __shared__ float t[32][33];
    int n0 = blockIdx.x * 32, k0 = blockIdx.y * 32;
    int tx = threadIdx.x & 31, ty = threadIdx.x >> 5;
    #pragma unroll
    for (int j = 0; j < 4; j++)
        t[ty + j * 8][tx] = w[(size_t)(k0 + ty + j * 8) * N + n0 + tx];
    __syncthreads();
    // each thread packs 4 fp16 along k -> one 8B store
    int n  = threadIdx.x >> 3;          // 0..31
    int k4 = (threadIdx.x & 7) * 4;     // 0..28
    __half h0 = __float2half(t[k4 + 0][n]);
    __half h1 = __float2half(t[k4 + 1][n]);
    __half h2 = __float2half(t[k4 + 2][n]);
    __half h3 = __float2half(t[k4 + 3][n]);
    *(uint2*)(wt + (size_t)(n0 + n) * K + k0 + k4) =
        make_uint2(pack2h(h0, h1), pack2h(h2, h3));
}

// ---------------- LayerNorm -> fp16 ------------------------------------------
__global__ __launch_bounds__(256) void ln_half_kernel(
    const float* __restrict__ x, const float* __restrict__ g,
    const float* __restrict__ b, __half* __restrict__ o)
{
    int row = blockIdx.x;
    const float* xr = x + (size_t)row * DD;
    float s = 0.f, s2 = 0.f;
    for (int i = threadIdx.x; i < DD; i += 256) {
        float v = xr[i]; s += v; s2 += v * v;
    }
    __shared__ float red[8], red2[8], stats[2];
    for (int off = 16; off > 0; off >>= 1) {
        s  += __shfl_down_sync(0xffffffffu, s,  off);
        s2 += __shfl_down_sync(0xffffffffu, s2, off);
    }
    int wid = threadIdx.x >> 5, lid = threadIdx.x & 31;
    if (lid == 0) { red[wid] = s; red2[wid] = s2; }
    __syncthreads();
    if (threadIdx.x == 0) {
        float ts = 0.f, ts2 = 0.f;
        for (int i = 0; i < 8; i++) { ts += red[i]; ts2 += red2[i]; }
        float mu = ts * (1.0f / DD);
        float var = ts2 * (1.0f / DD) - mu * mu;
        stats[0] = mu; stats[1] = rsqrtf(var + 1e-5f);
    }
    __syncthreads();
    float mu = stats[0], rstd = stats[1];
    for (int i = threadIdx.x; i < DD; i += 256) {
        o[(size_t)row * DD + i] = __float2half((xr[i] - mu) * rstd * g[i] + b[i]);
    }
}

// ---------------- fp16 GEMM: D = A @ W^T -------------------------------------
// MODE 1: Cf = acc + aux (fp32 out).  MODE 3: silu(acc) -> Ch fp16.
// CTA 128x128, BK=64, warp 64x32 (2x4 grid), 3-stage pipeline, 2 CTAs/SM.
#define SROW 144                    // padded row bytes (72 fp16)
#define T128 (128 * SROW)           // 18432
#define STAGE3 (2 * T128)           // 36864 : A, W
#define GEMM_SMEM (3 * STAGE3)      // 110592

template <int MODE>
__global__ __launch_bounds__(256, 2) void gemm_mma(
    const __half* __restrict__ A, const __half* __restrict__ Bw,
    float* __restrict__ Cf, const float* __restrict__ aux,
    __half* __restrict__ Ch,
    int M, int N, int K)
{
    extern __shared__ char smem[];
    const uint32_t sbase = smem_u32(smem);
    const int tid = threadIdx.x, lane = tid & 31, wid = tid >> 5;
    const int wm = wid & 1, wn = wid >> 1;
    const int bx = blockIdx.x, by = blockIdx.y;

    const size_t rowbytes = (size_t)K * 2;
    const char* Ab = (const char*)(A  + (size_t)by * 128 * K);
    const char* Bb = (const char*)(Bw + (size_t)bx * 128 * K);

    const uint32_t aRowOff = (uint32_t)((wm * 64 + (lane & 15)) * SROW + (lane >> 4) * 16);
    const int bg = lane >> 3;
    const uint32_t bRowOff = (uint32_t)((wn * 32 + (bg >> 1) * 8 + (lane & 7)) * SROW + (bg & 1) * 16);

    auto load_slab = [&](int ks, int st) {
        uint32_t stg = sbase + (uint32_t)st * STAGE3;
        size_t koff = (size_t)ks * 128;        // 64 fp16 = 128 B
        #pragma unroll
        for (int i = 0; i < 8; i++) {          // 2 tensors x 1024 chunks
            int c = tid + i * 256;
            int tn = c >> 10;
            int rr = (c >> 3) & 127;
            int ck = (c & 7) * 16;
            cp16(stg + (uint32_t)(tn * T128 + rr * SROW + ck),
                 (tn ? Bb : Ab) + (size_t)rr * rowbytes + koff + ck);
        }
        CPCOMMIT();
    };

    float acc[4][4][4];
    #pragma unroll
    for (int mt = 0; mt < 4; mt++)
        #pragma unroll
        for (int nt = 0; nt < 4; nt++)
            #pragma unroll
            for (int j = 0; j < 4; j++) acc[mt][nt][j] = 0.f;

    const int ns = K >> 6;
    load_slab(0, 0);
    if (ns > 1) load_slab(1, 1);

    for (int i = 0; i < ns; i++) {
        if (i + 1 < ns) CPWAIT(1);
        else            CPWAIT(0);
        __syncthreads();
        if (i + 2 < ns) load_slab(i + 2, (i + 2) % 3);

        uint32_t stg = sbase + (uint32_t)(i % 3) * STAGE3;
        uint32_t aB = stg + aRowOff;
        uint32_t bB = stg + T128 + bRowOff;

        #pragma unroll
        for (int ks = 0; ks < 4; ks++) {
            uint32_t ah[4][4], bh[2][4];
            #pragma unroll
            for (int mt = 0; mt < 4; mt++)
                ldsm4(ah[mt], aB + (uint32_t)(mt * 16 * SROW + ks * 32));
            #pragma unroll
            for (int p = 0; p < 2; p++)
                ldsm4(bh[p], bB + (uint32_t)(p * 16 * SROW + ks * 32));
            #pragma unroll
            for (int mt = 0; mt < 4; mt++)
                #pragma unroll
                for (int nt = 0; nt < 4; nt++) {
                    int p = nt >> 1, o = (nt & 1) * 2;
                    mma16816(acc[mt][nt], ah[mt], bh[p][o], bh[p][o + 1]);
                }
        }
    }

    const int groupID = lane >> 2, tid4 = lane & 3;
    #pragma unroll
    for (int mt = 0; mt < 4; mt++) {
        int r0 = by * 128 + wm * 64 + mt * 16 + groupID;
        #pragma unroll
        for (int nt = 0; nt < 4; nt++) {
            int cg = bx * 128 + wn * 32 + nt * 8 + tid4 * 2;
            float* a = acc[mt][nt];
            #pragma unroll
            for (int half = 0; half < 2; half++) {
                size_t off = (size_t)(r0 + half * 8) * N + cg;
                float v0 = a[half * 2 + 0], v1 = a[half * 2 + 1];
                if (MODE == 1) {
                    float2 ax = *(const float2*)(aux + off);
                    float2 o; o.x = v0 + ax.x; o.y = v1 + ax.y;
                    *(float2*)(Cf + off) = o;
                } else {
                    *(uint32_t*)(Ch + off) = pack2h(__float2half(silu(v0)),
                                                    __float2half(silu(v1)));
                }
            }
        }
    }
}

// ---------------- dual GEMM: h = silu(A@W1) * (A@W3) -> fp16 -----------------
#define DSTAGE (3 * T128)                 // 55296 : A, W1, W3
#define DUAL_SMEM (2 * DSTAGE)            // 110592

__global__ __launch_bounds__(256, 1) void gemm_dual(
    const __half* __restrict__ A,
    const __half* __restrict__ B1, const __half* __restrict__ B3,
    __half* __restrict__ Ch,
    int M, int N, int K)
{
    extern __shared__ char smem[];
    const uint32_t sbase = smem_u32(smem);
    const int tid = threadIdx.x, lane = tid & 31, wid = tid >> 5;
    const int wm = wid & 1, wn = wid >> 1;
    const int bx = blockIdx.x, by = blockIdx.y;

    const size_t rowbytes = (size_t)K * 2;
    const char* base[3] = {
        (const char*)(A  + (size_t)by * 128 * K),
        (const char*)(B1 + (size_t)bx * 128 * K),
        (const char*)(B3 + (size_t)bx * 128 * K)
    };

    const uint32_t aRowOff = (uint32_t)((wm * 64 + (lane & 15)) * SROW + (lane >> 4) * 16);
    const int bg = lane >> 3;
    const uint32_t bRowOff = (uint32_t)((wn * 32 + (bg >> 1) * 8 + (lane & 7)) * SROW + (bg & 1) * 16);

    auto load_slab = [&](int ks, int st) {
        uint32_t stg = sbase + (uint32_t)st * DSTAGE;
        size_t koff = (size_t)ks * 128;
        #pragma unroll
        for (int i = 0; i < 12; i++) {
            int c = tid + i * 256;
            int tn = c >> 10;
            int rr = (c >> 3) & 127;
            int ck = (c & 7) * 16;
            cp16(stg + (uint32_t)(tn * T128 + rr * SROW + ck),
                 base[tn] + (size_t)rr * rowbytes + koff + ck);
        }
        CPCOMMIT();
    };

    float acc1[4][4][4], acc3[4][4][4];
    #pragma unroll
    for (int mt = 0; mt < 4; mt++)
        #pragma unroll
        for (int nt = 0; nt < 4; nt++)
            #pragma unroll
            for (int j = 0; j < 4; j++) { acc1[mt][nt][j] = 0.f; acc3[mt][nt][j] = 0.f; }

    const int ns = K >> 6;
    load_slab(0, 0);

    for (int i = 0; i < ns; i++) {
        CPWAIT(0);
        __syncthreads();
        if (i + 1 < ns) load_slab(i + 1, (i + 1) & 1);

        uint32_t stg = sbase + (uint32_t)(i & 1) * DSTAGE;
        uint32_t aB  = stg + aRowOff;
        uint32_t b1B = stg + T128 + bRowOff;
        uint32_t b3B = stg + 2 * T128 + bRowOff;

        #pragma unroll
        for (int ks = 0; ks < 4; ks++) {
            uint32_t ah[4][4], b1h[2][4], b3h[2][4];
            #pragma unroll
            for (int mt = 0; mt < 4; mt++)
                ldsm4(ah[mt], aB + (uint32_t)(mt * 16 * SROW + ks * 32));
            #pragma unroll
            for (int p = 0; p < 2; p++) {
                uint32_t o = (uint32_t)(p * 16 * SROW + ks * 32);
                ldsm4(b1h[p], b1B + o);
                ldsm4(b3h[p], b3B + o);
            }
            #pragma unroll
            for (int mt = 0; mt < 4; mt++)
                #pragma unroll
                for (int nt = 0; nt < 4; nt++) {
                    int p = nt >> 1, o = (nt & 1) * 2;
                    mma16816(acc1[mt][nt], ah[mt], b1h[p][o], b1h[p][o + 1]);
                    mma16816(acc3[mt][nt], ah[mt], b3h[p][o], b3h[p][o + 1]);
                }
        }
    }

    const int groupID = lane >> 2, tid4 = lane & 3;
    #pragma unroll
    for (int mt = 0; mt < 4; mt++) {
        int r0 = by * 128 + wm * 64 + mt * 16 + groupID;
        #pragma unroll
        for (int nt = 0; nt < 4; nt++) {
            int cg = bx * 128 + wn * 32 + nt * 8 + tid4 * 2;
            #pragma unroll
            for (int half = 0; half < 2; half++) {
                size_t off = (size_t)(r0 + half * 8) * N + cg;
                float t0 = silu(acc1[mt][nt][half * 2 + 0]) * acc3[mt][nt][half * 2 + 0];
                float t1 = silu(acc1[mt][nt][half * 2 + 1]) * acc3[mt][nt][half * 2 + 1];
                *(uint32_t*)(Ch + off) = pack2h(__float2half(t0), __float2half(t1));
            }
        }
    }
}

// ---------------- Fused attention (fp16, pipelined loads) --------------------
// smem: Q 0 (18432) | K stage0 18432, stage1 36864 | V 55296 |
//       S 73728 (128x136 fp16 = 34816). total 108544. aS (fp32 [128][68]) aliases S.
#define AROWB 144
#define SROWB 272
#define ATT_SMEM 108544
#define GROWB 8192     // global row stride of qkuv (4096 fp16)

__global__ __launch_bounds__(256, 1) void attn_mma(
    const __half* __restrict__ qk,
    const float* __restrict__ nag, const float* __restrict__ nab,
    __half* __restrict__ aout)
{
    extern __shared__ char smc[];
    const uint32_t sb = smem_u32(smc);
    const uint32_t oQ = 0;
    const uint32_t oK[2] = {18432, 36864};
    const uint32_t oV = 55296;
    const uint32_t oS = 73728;
    __half* sp = (__half*)(smc + oS);
    float* aS = (float*)(smc + oS);
    __shared__ float mu_s[128], rs_s[128];

    const int qb = (int)gridDim.x - 1 - (int)blockIdx.x;
    const int bh = blockIdx.y;
    const int b = bh >> 4, h = bh & 15;
    const int tid = threadIdx.x, lane = tid & 31, wid = tid >> 5;
    const int wm = wid & 1, wn = wid >> 1;
    const int groupID = lane >> 2, tid4 = lane & 3;

    const char* gq = (const char*)qk + (size_t)(b * LL) * GROWB + h * 128;

    auto ldt = [&](uint32_t so, const char* g) {
        #pragma unroll
        for (int i = 0; i < 4; i++) {
            int idx = tid + i * 256;
            int r = idx >> 3, ck = (idx & 7) * 16;
            cp16(sb + so + (uint32_t)(r * AROWB + ck), g + (size_t)r * GROWB + ck);
        }
    };

    // prologue: Q + K(0)
    ldt(oQ, gq + (size_t)(qb * 128) * GROWB);
    ldt(oK[0], gq + 2048);
    CPCOMMIT();

    const uint32_t aOffQ = (uint32_t)((wm * 64 + (lane & 15)) * AROWB + (lane >> 4) * 16);
    const int bg = lane >> 3;
    const uint32_t bOffK = (uint32_t)((wn * 32 + (bg >> 1) * 8 + (lane & 7)) * AROWB + (bg & 1) * 16);
    const uint32_t aOffS = (uint32_t)((wm * 64 + (lane & 15)) * SROWB + (lane >> 4) * 16);
    const uint32_t bOffV = (uint32_t)(((bg & 1) * 8 + (lane & 7)) * AROWB + (wn * 16 + (bg >> 1) * 8) * 2);

    float oacc[4][2][4];
    #pragma unroll
    for (int mt = 0; mt < 4; mt++)
        #pragma unroll
        for (int nt = 0; nt < 2; nt++)
            #pragma unroll
            for (int j = 0; j < 4; j++) oacc[mt][nt][j] = 0.f;

    for (int kb = 0; kb <= qb; kb++) {
        const int st = kb & 1;
        const bool more = (kb < qb);
        __syncthreads();
        ldt(oV, gq + 4096 + (size_t)(kb * 128) * GROWB);
        CPCOMMIT();
        if (more) {
            ldt(oK[st ^ 1], gq + 2048 + (size_t)((kb + 1) * 128) * GROWB);
            CPCOMMIT();
        }
        if (more) CPWAIT(2); else CPWAIT(1);   // K(kb) ready
        __syncthreads();

        // ---- S = Q @ K^T ----
        float sacc[4][4][4];
        #pragma unroll
        for (int mt = 0; mt < 4; mt++)
            #pragma unroll
            for (int nt = 0; nt < 4; nt++)
                #pragma unroll
                for (int j = 0; j < 4; j++) sacc[mt][nt][j] = 0.f;

        #pragma unroll
        for (int ks = 0; ks < 4; ks++) {
            uint32_t q4[4][4], k4[2][4];
            #pragma unroll
            for (int mt = 0; mt < 4; mt++)
                ldsm4(q4[mt], sb + oQ + aOffQ + (uint32_t)(mt * 16 * AROWB + ks * 32));
            #pragma unroll
            for (int p = 0; p < 2; p++)
                ldsm4(k4[p], sb + oK[st] + bOffK + (uint32_t)(p * 16 * AROWB + ks * 32));
            #pragma unroll
            for (int mt = 0; mt < 4; mt++)
                #pragma unroll
                for (int nt = 0; nt < 4; nt++) {
                    int p = nt >> 1, o = (nt & 1) * 2;
                    mma16816(sacc[mt][nt], q4[mt], k4[p][o], k4[p][o + 1]);
                }
        }

        // ---- silu/scale/mask -> S fp16 to smem ----
        const bool diag = (kb == qb);
        #pragma unroll
        for (int mt = 0; mt < 4; mt++) {
            #pragma unroll
            for (int half = 0; half < 2; half++) {
                int r = wm * 64 + mt * 16 + groupID + half * 8;
                #pragma unroll
                for (int nt = 0; nt < 4; nt++) {
                    int c = wn * 32 + nt * 8 + tid4 * 2;
                    float s0 = silu(sacc[mt][nt][half * 2 + 0] * 0.125f);
                    float s1 = silu(sacc[mt][nt][half * 2 + 1] * 0.125f);
                    if (diag) {
                        if (c > r) s0 = 0.f;
                        if (c + 1 > r) s1 = 0.f;
                    }
                    *(uint32_t*)(sp + r * 136 + c) = pack2h(__float2half(s0), __float2half(s1));
                }
            }
        }
        if (more) CPWAIT(1); else CPWAIT(0);   // V(kb) ready
        __syncthreads();

        // ---- A += S @ V (V via ldsm.trans) ----
        #pragma unroll
        for (int ks = 0; ks < 8; ks++) {
            uint32_t s4[4][4], v4[4];
            #pragma unroll
            for (int mt = 0; mt < 4; mt++)
                ldsm4(s4[mt], sb + oS + aOffS + (uint32_t)(mt * 16 * SROWB + ks * 32));
            ldsm4t(v4, sb + oV + bOffV + (uint32_t)(ks * 16 * AROWB));
            #pragma unroll
            for (int mt = 0; mt < 4; mt++)
                #pragma unroll
                for (int nt = 0; nt < 2; nt++) {
                    int o = nt * 2;
                    mma16816(oacc[mt][nt], s4[mt], v4[o], v4[o + 1]);
                }
        }
    }

    // ---- headLN(d=64) * u -> fp16 out ----
    __syncthreads();
    #pragma unroll
    for (int mt = 0; mt < 4; mt++)
        #pragma unroll
        for (int half = 0; half < 2; half++) {
            int r = wm * 64 + mt * 16 + groupID + half * 8;
            #pragma unroll
            for (int nt = 0; nt < 2; nt++) {
                int c = wn * 16 + nt * 8 + tid4 * 2;
                float2 v;
                v.x = oacc[mt][nt][half * 2 + 0];
                v.y = oacc[mt][nt][half * 2 + 1];
                *(float2*)(aS + r * 68 + c) = v;
            }
        }
    __syncthreads();
    if (tid < 128) {
        float s = 0.f, s2 = 0.f;
        #pragma unroll
        for (int c = 0; c < 64; c++) {
            float v = aS[tid * 68 + c];
            s += v; s2 += v * v;
        }
        float mu = s * (1.0f / 64.0f);
        float var = s2 * (1.0f / 64.0f) - mu * mu;
        mu_s[tid] = mu;
        rs_s[tid] = rsqrtf(var + 1e-5f);
    }
    __syncthreads();
    {
        int r = tid >> 1;
        int c0 = (tid & 1) * 32;
        int l = qb * 128 + r;
        float mu = mu_s[r], rstd = rs_s[r];
        const __half* uh = (const __half*)(gq + 6144 + (size_t)l * GROWB);
        size_t obase = (size_t)(b * LL + l) * DD + h * HD;
        #pragma unroll
        for (int c = c0; c < c0 + 32; c += 2) {
            float u0 = __half2float(uh[c + 0]);
            float u1 = __half2float(uh[c + 1]);
            float t0 = ((aS[r * 68 + c + 0] - mu) * rstd * nag[c + 0] + nab[c + 0]) * u0;
            float t1 = ((aS[r * 68 + c + 1] - mu) * rstd * nag[c + 1] + nab[c + 1]) * u1;
            *(uint32_t*)(aout + obase + c) = pack2h(__float2half(t0), __float2half(t1));
        }
    }
}

// ---------------- host -------------------------------------------------------
extern "C" void kernel_launch(void* const* d_in, const int* in_sizes, int n_in,
                              void* d_out, int out_size)
{
    const float* x      = (const float*)d_in[0];
    const float* w_qkuv = (const float*)d_in[2];
    const float* w_out  = (const float*)d_in[3];
    const float* w1     = (const float*)d_in[4];
    const float* w2     = (const float*)d_in[5];
    const float* w3     = (const float*)d_in[6];
    const float* ln1_g  = (const float*)d_in[7];
    const float* ln1_b  = (const float*)d_in[8];
    const float* ln2_g  = (const float*)d_in[9];
    const float* ln2_b  = (const float*)d_in[10];
    const float* na_g   = (const float*)d_in[11];
    const float* na_b   = (const float*)d_in[12];
    float* out = (float*)d_out;

    __half *xn, *qk, *a, *xn2, *hbuf;
    __half *wq, *wo, *w1t, *w3t, *w2t;
    float *x1;
    cudaGetSymbolAddress((void**)&xn,   g_xn);
    cudaGetSymbolAddress((void**)&qk,   g_qk);
    cudaGetSymbolAddress((void**)&a,    g_a);
    cudaGetSymbolAddress((void**)&x1,   g_x1);
    cudaGetSymbolAddress((void**)&xn2,  g_xn2);
    cudaGetSymbolAddress((void**)&hbuf, g_h);
    cudaGetSymbolAddress((void**)&wq,   g_wqkuv);
    cudaGetSymbolAddress((void**)&wo,   g_wout);
    cudaGetSymbolAddress((void**)&w1t,  g_w1);
    cudaGetSymbolAddress((void**)&w3t,  g_w3);
    cudaGetSymbolAddress((void**)&w2t,  g_w2);

    cudaFuncSetAttribute(gemm_mma<1>, cudaFuncAttributeMaxDynamicSharedMemorySize, GEMM_SMEM);
    cudaFuncSetAttribute(gemm_mma<3>, cudaFuncAttributeMaxDynamicSharedMemorySize, GEMM_SMEM);
    cudaFuncSetAttribute(gemm_dual,   cudaFuncAttributeMaxDynamicSharedMemorySize, DUAL_SMEM);
    cudaFuncSetAttribute(attn_mma,    cudaFuncAttributeMaxDynamicSharedMemorySize, ATT_SMEM);

    dim3 blk(256);

    // 0. weight transpose -> fp16
    wconv_kernel<<<dim3(4 * DD / 32, DD / 32), blk>>>(w_qkuv, wq,  DD, 4 * DD);
    wconv_kernel<<<dim3(DD / 32, DD / 32),     blk>>>(w_out,  wo,  DD, DD);
    wconv_kernel<<<dim3(FF / 32, DD / 32),     blk>>>(w1,     w1t, DD, FF);
    wconv_kernel<<<dim3(FF / 32, DD / 32),     blk>>>(w3,     w3t, DD, FF);
    wconv_kernel<<<dim3(DD / 32, FF / 32),     blk>>>(w2,     w2t, FF, DD);

    // 1. LN1 -> fp16
    ln_half_kernel<<<MROWS, blk>>>(x, ln1_g, ln1_b, xn);
    // 2. qkuv = silu(xn @ w_qkuv) -> fp16
    gemm_mma<3><<<dim3(4 * DD / 128, MROWS / 128), blk, GEMM_SMEM>>>(
        xn, wq, nullptr, nullptr, qk, MROWS, 4 * DD, DD);
    // 3. attention -> a fp16
    attn_mma<<<dim3(LL / 128, BB * HH), blk, ATT_SMEM>>>(qk, na_g, na_b, a);
    // 4. x1 = x + a @ w_out
    gemm_mma<1><<<dim3(DD / 128, MROWS / 128), blk, GEMM_SMEM>>>(
        a, wo, x1, x, nullptr, MROWS, DD, DD);
    // 5. LN2 -> fp16
    ln_half_kernel<<<MROWS, blk>>>(x1, ln2_g, ln2_b, xn2);
    // 6+7. h = silu(xn2@w1) * (xn2@w3) -> fp16
    gemm_dual<<<dim3(FF / 128, MROWS / 128), blk, DUAL_SMEM>>>(
        xn2, w1t, w3t, hbuf, MROWS, FF, DD);
    // 8. out = x1 + h @ w2
    gemm_mma<1><<<dim3(DD / 128, MROWS / 128), blk, GEMM_SMEM>>>(
        hbuf, w2t, out, x1, nullptr, MROWS, DD, FF);
}

// round 11
// speedup vs baseline: 2.3838x; 1.0123x over previous
#include <cuda_runtime.h>
#include <cuda_fp16.h>
#include <cstdint>
#include <math.h>

#define BB 2
#define LL 2048
#define DD 1024
#define HH 16
#define HD 64
#define FF 4096
#define MROWS (BB*LL)   // 4096

// ---------------- scratch (device globals) ---------------------------------
__device__ __half g_xn  [MROWS * DD];
__device__ __half g_qk  [MROWS * 4 * DD];   // silu(xn@w_qkuv) fp16
__device__ __half g_a   [MROWS * DD];
__device__ float  g_x1  [MROWS * DD];
__device__ __half g_xn2 [MROWS * DD];
__device__ __half g_h   [MROWS * FF];
// weights in NATIVE [K, N] layout, fp16 (no transpose)
__device__ __half g_wqkuv [DD * 4 * DD];
__device__ __half g_wout  [DD * DD];
__device__ __half g_w1    [DD * FF];
__device__ __half g_w3    [DD * FF];
__device__ __half g_w2    [FF * DD];

__device__ __forceinline__ float silu(float x) {
    return __fdividef(x, 1.0f + __expf(-x));
}
__device__ __forceinline__ uint32_t smem_u32(const void* p) {
    uint32_t a;
    asm("{ .reg .u64 t; cvta.to.shared.u64 t, %1; cvt.u32.u64 %0, t; }" : "=r"(a) : "l"(p));
    return a;
}
__device__ __forceinline__ void cp16(uint32_t s, const void* g) {
    asm volatile("cp.async.cg.shared.global [%0], [%1], 16;" :: "r"(s), "l"(g) : "memory");
}
#define CPCOMMIT() asm volatile("cp.async.commit_group;" ::: "memory")
#define CPWAIT(n)  asm volatile("cp.async.wait_group %0;" :: "n"(n) : "memory")
__device__ __forceinline__ uint32_t pack2h(__half a, __half b) {
    return (uint32_t)__half_as_ushort(a) | ((uint32_t)__half_as_ushort(b) << 16);
}
__device__ __forceinline__ void ldsm4(uint32_t* r, uint32_t a) {
    asm volatile("ldmatrix.sync.aligned.m8n8.x4.shared.b16 {%0,%1,%2,%3}, [%4];"
        : "=r"(r[0]), "=r"(r[1]), "=r"(r[2]), "=r"(r[3]) : "r"(a));
}
__device__ __forceinline__ void ldsm4t(uint32_t* r, uint32_t a) {
    asm volatile("ldmatrix.sync.aligned.m8n8.x4.trans.shared.b16 {%0,%1,%2,%3}, [%4];"
        : "=r"(r[0]), "=r"(r[1]), "=r"(r[2]), "=r"(r[3]) : "r"(a));
}
__device__ __forceinline__ void mma16816(float* c, const uint32_t* a, uint32_t b0, uint32_t b1) {
    asm volatile(
        "mma.sync.aligned.m16n8k16.row.col.f32.f16.f16.f32 "
        "{%0,%1,%2,%3}, {%4,%5,%6,%7}, {%8,%9}, {%0,%1,%2,%3};"
        : "+f"(c[0]), "+f"(c[1]), "+f"(c[2]), "+f"(c[3])
        : "r"(a[0]), "r"(a[1]), "r"(a[2]), "r"(a[3]), "r"(b0), "r"(b1));
}

// ---------------- weight convert fp32 -> fp16 (same layout, streaming) ------
__global__ __launch_bounds__(256) void wconv_kernel(
    const float* __restrict__ w, __half* __restrict__ wt)
{
    int idx = (blockIdx.x * 256 + threadIdx.x) * 4;
    float4 v = *(const float4*)(w + idx);
    *(uint2*)(wt + idx) = make_uint2(
        pack2h(__float2half(v.x), __float2half(v.y)),
        pack2h(__float2half(v.z), __float2half(v.w)));
}

// ---------------- LayerNorm -> fp16 ------------------------------------------
__global__ __launch_bounds__(256) void ln_half_kernel(
    const float* __restrict__ x, const float* __restrict__ g,
    const float* __restrict__ b, __half* __restrict__ o)
{
    int row = blockIdx.x;
    const float* xr = x + (size_t)row * DD;
    float s = 0.f, s2 = 0.f;
    for (int i = threadIdx.x; i < DD; i += 256) {
        float v = xr[i]; s += v; s2 += v * v;
    }
    __shared__ float red[8], red2[8], stats[2];
    for (int off = 16; off > 0; off >>= 1) {
        s  += __shfl_down_sync(0xffffffffu, s,  off);
        s2 += __shfl_down_sync(0xffffffffu, s2, off);
    }
    int wid = threadIdx.x >> 5, lid = threadIdx.x & 31;
    if (lid == 0) { red[wid] = s; red2[wid] = s2; }
    __syncthreads();
    if (threadIdx.x == 0) {
        float ts = 0.f, ts2 = 0.f;
        for (int i = 0; i < 8; i++) { ts += red[i]; ts2 += red2[i]; }
        float mu = ts * (1.0f / DD);
        float var = ts2 * (1.0f / DD) - mu * mu;
        stats[0] = mu; stats[1] = rsqrtf(var + 1e-5f);
    }
    __syncthreads();
    float mu = stats[0], rstd = stats[1];
    for (int i = threadIdx.x; i < DD; i += 256) {
        o[(size_t)row * DD + i] = __float2half((xr[i] - mu) * rstd * g[i] + b[i]);
    }
}

// ---------------- fp16 GEMM: D[M,N] = A[M,K] @ W[K,N] ------------------------
// W consumed in native [K,N] layout via ldsm.trans.
// MODE 1: Cf = acc + aux (fp32 out).  MODE 3: silu(acc) -> Ch fp16.
// CTA 128x128, BK=64, warp 64x32 (2x4), 3-stage, 2 CTAs/SM.
#define SROW 144                    // A row bytes (72 fp16)
#define WROWB 272                   // W row bytes (128 fp16 + pad)
#define AT (128 * SROW)             // 18432
#define WT (64 * WROWB)             // 17408
#define STAGE3 (AT + WT)            // 35840
#define GEMM_SMEM (3 * STAGE3)      // 107520

template <int MODE>
__global__ __launch_bounds__(256, 2) void gemm_mma(
    const __half* __restrict__ A, const __half* __restrict__ Bw,
    float* __restrict__ Cf, const float* __restrict__ aux,
    __half* __restrict__ Ch,
    int M, int N, int K)
{
    extern __shared__ char smem[];
    const uint32_t sbase = smem_u32(smem);
    const int tid = threadIdx.x, lane = tid & 31, wid = tid >> 5;
    const int wm = wid & 1, wn = wid >> 1;
    const int bx = blockIdx.x, by = blockIdx.y;

    const size_t rowbytesA = (size_t)K * 2;
    const size_t rowbytesB = (size_t)N * 2;
    const char* Ab = (const char*)(A + (size_t)by * 128 * K);
    const char* Bb = (const char*)Bw + (size_t)bx * 256;   // column offset bx*128 fp16

    const uint32_t aRowOff = (uint32_t)((wm * 64 + (lane & 15)) * SROW + (lane >> 4) * 16);
    const int bg = lane >> 3;
    // B fragments via ldsm.trans on [k][n] rows (attention-V pattern)
    const uint32_t bOffW = (uint32_t)(((bg & 1) * 8 + (lane & 7)) * WROWB
                                      + (wn * 32 + (bg >> 1) * 8) * 2);

    auto load_slab = [&](int ks, int st) {
        uint32_t stg = sbase + (uint32_t)st * STAGE3;
        size_t akoff = (size_t)ks * 128;       // 64 fp16 = 128 B
        size_t bk0 = (size_t)ks * 64;
        #pragma unroll
        for (int i = 0; i < 8; i++) {
            int c = tid + i * 256;
            if (c < 1024) {                    // A: 128 rows x 8 chunks
                int rr = c >> 3, ck = (c & 7) * 16;
                cp16(stg + (uint32_t)(rr * SROW + ck),
                     Ab + (size_t)rr * rowbytesA + akoff + ck);
            } else {                           // W: 64 rows x 16 chunks
                int j = c - 1024;
                int rr = j >> 4, ck = (j & 15) * 16;
                cp16(stg + (uint32_t)(AT + rr * WROWB + ck),
                     Bb + (bk0 + rr) * rowbytesB + ck);
            }
        }
        CPCOMMIT();
    };

    float acc[4][4][4];
    #pragma unroll
    for (int mt = 0; mt < 4; mt++)
        #pragma unroll
        for (int nt = 0; nt < 4; nt++)
            #pragma unroll
            for (int j = 0; j < 4; j++) acc[mt][nt][j] = 0.f;

    const int ns = K >> 6;
    load_slab(0, 0);
    if (ns > 1) load_slab(1, 1);

    for (int i = 0; i < ns; i++) {
        if (i + 1 < ns) CPWAIT(1);
        else            CPWAIT(0);
        __syncthreads();
        if (i + 2 < ns) load_slab(i + 2, (i + 2) % 3);

        uint32_t stg = sbase + (uint32_t)(i % 3) * STAGE3;
        uint32_t aB = stg + aRowOff;
        uint32_t bB = stg + AT + bOffW;

        #pragma unroll
        for (int ks = 0; ks < 4; ks++) {
            uint32_t ah[4][4], bh[2][4];
            #pragma unroll
            for (int mt = 0; mt < 4; mt++)
                ldsm4(ah[mt], aB + (uint32_t)(mt * 16 * SROW + ks * 32));
            #pragma unroll
            for (int p = 0; p < 2; p++)
                ldsm4t(bh[p], bB + (uint32_t)(ks * 16 * WROWB + p * 32));
            #pragma unroll
            for (int mt = 0; mt < 4; mt++)
                #pragma unroll
                for (int nt = 0; nt < 4; nt++) {
                    int p = nt >> 1, o = (nt & 1) * 2;
                    mma16816(acc[mt][nt], ah[mt], bh[p][o], bh[p][o + 1]);
                }
        }
    }

    const int groupID = lane >> 2, tid4 = lane & 3;
    #pragma unroll
    for (int mt = 0; mt < 4; mt++) {
        int r0 = by * 128 + wm * 64 + mt * 16 + groupID;
        #pragma unroll
        for (int nt = 0; nt < 4; nt++) {
            int cg = bx * 128 + wn * 32 + nt * 8 + tid4 * 2;
            float* a = acc[mt][nt];
            #pragma unroll
            for (int half = 0; half < 2; half++) {
                size_t off = (size_t)(r0 + half * 8) * N + cg;
                float v0 = a[half * 2 + 0], v1 = a[half * 2 + 1];
                if (MODE == 1) {
                    float2 ax = *(const float2*)(aux + off);
                    float2 o; o.x = v0 + ax.x; o.y = v1 + ax.y;
                    *(float2*)(Cf + off) = o;
                } else {
                    *(uint32_t*)(Ch + off) = pack2h(__float2half(silu(v0)),
                                                    __float2half(silu(v1)));
                }
            }
        }
    }
}

// ---------------- dual GEMM: h = silu(A@W1) * (A@W3) -> fp16 -----------------
// CTA 128x64, warp 64x16 per matrix, 2-stage, 2 CTAs/SM.
#define DWROWB 144                        // 64 fp16 cols + pad
#define DWT (64 * DWROWB)                 // 9216
#define DSTAGE (AT + 2 * DWT)             // 36864
#define DUAL_SMEM (2 * DSTAGE)            // 73728

__global__ __launch_bounds__(256, 2) void gemm_dual(
    const __half* __restrict__ A,
    const __half* __restrict__ B1, const __half* __restrict__ B3,
    __half* __restrict__ Ch,
    int M, int N, int K)
{
    extern __shared__ char smem[];
    const uint32_t sbase = smem_u32(smem);
    const int tid = threadIdx.x, lane = tid & 31, wid = tid >> 5;
    const int wm = wid & 1, wn = wid >> 1;   // 2(M) x 4(N), warp N=16
    const int bx = blockIdx.x, by = blockIdx.y;

    const size_t rowbytesA = (size_t)K * 2;
    const size_t rowbytesB = (size_t)N * 2;
    const char* Ab  = (const char*)(A + (size_t)by * 128 * K);
    const char* B1b = (const char*)B1 + (size_t)bx * 128;   // col offset bx*64 fp16
    const char* B3b = (const char*)B3 + (size_t)bx * 128;

    const uint32_t aRowOff = (uint32_t)((wm * 64 + (lane & 15)) * SROW + (lane >> 4) * 16);
    const int bg = lane >> 3;
    const uint32_t bOffW = (uint32_t)(((bg & 1) * 8 + (lane & 7)) * DWROWB
                                      + (wn * 16 + (bg >> 1) * 8) * 2);

    auto load_slab = [&](int ks, int st) {
        uint32_t stg = sbase + (uint32_t)st * DSTAGE;
        size_t akoff = (size_t)ks * 128;
        size_t bk0 = (size_t)ks * 64;
        #pragma unroll
        for (int i = 0; i < 8; i++) {
            int c = tid + i * 256;
            if (c < 1024) {                    // A
                int rr = c >> 3, ck = (c & 7) * 16;
                cp16(stg + (uint32_t)(rr * SROW + ck),
                     Ab + (size_t)rr * rowbytesA + akoff + ck);
            } else {                           // W1 / W3: 64 rows x 8 chunks each
                int j = c - 1024;
                int tw = j >> 9;               // 0=W1, 1=W3
                int jj = j & 511;
                int rr = jj >> 3, ck = (jj & 7) * 16;
                cp16(stg + (uint32_t)(AT + tw * DWT + rr * DWROWB + ck),
                     (tw ? B3b : B1b) + (bk0 + rr) * rowbytesB + ck);
            }
        }
        CPCOMMIT();
    };

    float acc1[4][2][4], acc3[4][2][4];
    #pragma unroll
    for (int mt = 0; mt < 4; mt++)
        #pragma unroll
        for (int nt = 0; nt < 2; nt++)
            #pragma unroll
            for (int j = 0; j < 4; j++) { acc1[mt][nt][j] = 0.f; acc3[mt][nt][j] = 0.f; }

    const int ns = K >> 6;
    load_slab(0, 0);

    for (int i = 0; i < ns; i++) {
        CPWAIT(0);
        __syncthreads();
        if (i + 1 < ns) load_slab(i + 1, (i + 1) & 1);

        uint32_t stg = sbase + (uint32_t)(i & 1) * DSTAGE;
        uint32_t aB  = stg + aRowOff;
        uint32_t b1B = stg + AT + bOffW;
        uint32_t b3B = stg + AT + DWT + bOffW;

        #pragma unroll
        for (int ks = 0; ks < 4; ks++) {
            uint32_t ah[4][4], b1h[4], b3h[4];
            #pragma unroll
            for (int mt = 0; mt < 4; mt++)
                ldsm4(ah[mt], aB + (uint32_t)(mt * 16 * SROW + ks * 32));
            uint32_t ko = (uint32_t)(ks * 16 * DWROWB);
            ldsm4t(b1h, b1B + ko);
            ldsm4t(b3h, b3B + ko);
            #pragma unroll
            for (int mt = 0; mt < 4; mt++)
                #pragma unroll
                for (int nt = 0; nt < 2; nt++) {
                    int o = nt * 2;
                    mma16816(acc1[mt][nt], ah[mt], b1h[o], b1h[o + 1]);
                    mma16816(acc3[mt][nt], ah[mt], b3h[o], b3h[o + 1]);
                }
        }
    }

    const int groupID = lane >> 2, tid4 = lane & 3;
    #pragma unroll
    for (int mt = 0; mt < 4; mt++) {
        int r0 = by * 128 + wm * 64 + mt * 16 + groupID;
        #pragma unroll
        for (int nt = 0; nt < 2; nt++) {
            int cg = bx * 64 + wn * 16 + nt * 8 + tid4 * 2;
            #pragma unroll
            for (int half = 0; half < 2; half++) {
                size_t off = (size_t)(r0 + half * 8) * N + cg;
                float t0 = silu(acc1[mt][nt][half * 2 + 0]) * acc3[mt][nt][half * 2 + 0];
                float t1 = silu(acc1[mt][nt][half * 2 + 1]) * acc3[mt][nt][half * 2 + 1];
                *(uint32_t*)(Ch + off) = pack2h(__float2half(t0), __float2half(t1));
            }
        }
    }
}

// ---------------- Fused attention (fp16, pipelined loads) --------------------
// smem: Q 0 (18432) | K stage0 18432, stage1 36864 | V 55296 |
//       S 73728 (128x136 fp16 = 34816). total 108544. aS (fp32 [128][68]) aliases S.
#define AROWB 144
#define SROWB 272
#define ATT_SMEM 108544
#define GROWB 8192     // global row stride of qkuv (4096 fp16)

__global__ __launch_bounds__(256, 1) void attn_mma(
    const __half* __restrict__ qk,
    const float* __restrict__ nag, const float* __restrict__ nab,
    __half* __restrict__ aout)
{
    extern __shared__ char smc[];
    const uint32_t sb = smem_u32(smc);
    const uint32_t oQ = 0;
    const uint32_t oK[2] = {18432, 36864};
    const uint32_t oV = 55296;
    const uint32_t oS = 73728;
    __half* sp = (__half*)(smc + oS);
    float* aS = (float*)(smc + oS);
    __shared__ float mu_s[128], rs_s[128];

    const int qb = (int)gridDim.x - 1 - (int)blockIdx.x;
    const int bh = blockIdx.y;
    const int b = bh >> 4, h = bh & 15;
    const int tid = threadIdx.x, lane = tid & 31, wid = tid >> 5;
    const int wm = wid & 1, wn = wid >> 1;
    const int groupID = lane >> 2, tid4 = lane & 3;

    const char* gq = (const char*)qk + (size_t)(b * LL) * GROWB + h * 128;

    auto ldt = [&](uint32_t so, const char* g) {
        #pragma unroll
        for (int i = 0; i < 4; i++) {
            int idx = tid + i * 256;
            int r = idx >> 3, ck = (idx & 7) * 16;
            cp16(sb + so + (uint32_t)(r * AROWB + ck), g + (size_t)r * GROWB + ck);
        }
    };

    // prologue: Q + K(0)
    ldt(oQ, gq + (size_t)(qb * 128) * GROWB);
    ldt(oK[0], gq + 2048);
    CPCOMMIT();

    const uint32_t aOffQ = (uint32_t)((wm * 64 + (lane & 15)) * AROWB + (lane >> 4) * 16);
    const int bg = lane >> 3;
    const uint32_t bOffK = (uint32_t)((wn * 32 + (bg >> 1) * 8 + (lane & 7)) * AROWB + (bg & 1) * 16);
    const uint32_t aOffS = (uint32_t)((wm * 64 + (lane & 15)) * SROWB + (lane >> 4) * 16);
    const uint32_t bOffV = (uint32_t)(((bg & 1) * 8 + (lane & 7)) * AROWB + (wn * 16 + (bg >> 1) * 8) * 2);

    float oacc[4][2][4];
    #pragma unroll
    for (int mt = 0; mt < 4; mt++)
        #pragma unroll
        for (int nt = 0; nt < 2; nt++)
            #pragma unroll
            for (int j = 0; j < 4; j++) oacc[mt][nt][j] = 0.f;

    for (int kb = 0; kb <= qb; kb++) {
        const int st = kb & 1;
        const bool more = (kb < qb);
        __syncthreads();
        ldt(oV, gq + 4096 + (size_t)(kb * 128) * GROWB);
        CPCOMMIT();
        if (more) {
            ldt(oK[st ^ 1], gq + 2048 + (size_t)((kb + 1) * 128) * GROWB);
            CPCOMMIT();
        }
        if (more) CPWAIT(2); else CPWAIT(1);   // K(kb) ready
        __syncthreads();

        // ---- S = Q @ K^T ----
        float sacc[4][4][4];
        #pragma unroll
        for (int mt = 0; mt < 4; mt++)
            #pragma unroll
            for (int nt = 0; nt < 4; nt++)
                #pragma unroll
                for (int j = 0; j < 4; j++) sacc[mt][nt][j] = 0.f;

        #pragma unroll
        for (int ks = 0; ks < 4; ks++) {
            uint32_t q4[4][4], k4[2][4];
            #pragma unroll
            for (int mt = 0; mt < 4; mt++)
                ldsm4(q4[mt], sb + oQ + aOffQ + (uint32_t)(mt * 16 * AROWB + ks * 32));
            #pragma unroll
            for (int p = 0; p < 2; p++)
                ldsm4(k4[p], sb + oK[st] + bOffK + (uint32_t)(p * 16 * AROWB + ks * 32));
            #pragma unroll
            for (int mt = 0; mt < 4; mt++)
                #pragma unroll
                for (int nt = 0; nt < 4; nt++) {
                    int p = nt >> 1, o = (nt & 1) * 2;
                    mma16816(sacc[mt][nt], q4[mt], k4[p][o], k4[p][o + 1]);
                }
        }

        // ---- silu/scale/mask -> S fp16 to smem ----
        const bool diag = (kb == qb);
        #pragma unroll
        for (int mt = 0; mt < 4; mt++) {
            #pragma unroll
            for (int half = 0; half < 2; half++) {
                int r = wm * 64 + mt * 16 + groupID + half * 8;
                #pragma unroll
                for (int nt = 0; nt < 4; nt++) {
                    int c = wn * 32 + nt * 8 + tid4 * 2;
                    float s0 = silu(sacc[mt][nt][half * 2 + 0] * 0.125f);
                    float s1 = silu(sacc[mt][nt][half * 2 + 1] * 0.125f);
                    if (diag) {
                        if (c > r) s0 = 0.f;
                        if (c + 1 > r) s1 = 0.f;
                    }
                    *(uint32_t*)(sp + r * 136 + c) = pack2h(__float2half(s0), __float2half(s1));
                }
            }
        }
        if (more) CPWAIT(1); else CPWAIT(0);   // V(kb) ready
        __syncthreads();

        // ---- A += S @ V (V via ldsm.trans) ----
        #pragma unroll
        for (int ks = 0; ks < 8; ks++) {
            uint32_t s4[4][4], v4[4];
            #pragma unroll
            for (int mt = 0; mt < 4; mt++)
                ldsm4(s4[mt], sb + oS + aOffS + (uint32_t)(mt * 16 * SROWB + ks * 32));
            ldsm4t(v4, sb + oV + bOffV + (uint32_t)(ks * 16 * AROWB));
            #pragma unroll
            for (int mt = 0; mt < 4; mt++)
                #pragma unroll
                for (int nt = 0; nt < 2; nt++) {
                    int o = nt * 2;
                    mma16816(oacc[mt][nt], s4[mt], v4[o], v4[o + 1]);
                }
        }
    }

    // ---- headLN(d=64) * u -> fp16 out ----
    __syncthreads();
    #pragma unroll
    for (int mt = 0; mt < 4; mt++)
        #pragma unroll
        for (int half = 0; half < 2; half++) {
            int r = wm * 64 + mt * 16 + groupID + half * 8;
            #pragma unroll
            for (int nt = 0; nt < 2; nt++) {
                int c = wn * 16 + nt * 8 + tid4 * 2;
                float2 v;
                v.x = oacc[mt][nt][half * 2 + 0];
                v.y = oacc[mt][nt][half * 2 + 1];
                *(float2*)(aS + r * 68 + c) = v;
            }
        }
    __syncthreads();
    if (tid < 128) {
        float s = 0.f, s2 = 0.f;
        #pragma unroll
        for (int c = 0; c < 64; c++) {
            float v = aS[tid * 68 + c];
            s += v; s2 += v * v;
        }
        float mu = s * (1.0f / 64.0f);
        float var = s2 * (1.0f / 64.0f) - mu * mu;
        mu_s[tid] = mu;
        rs_s[tid] = rsqrtf(var + 1e-5f);
    }
    __syncthreads();
    {
        int r = tid >> 1;
        int c0 = (tid & 1) * 32;
        int l = qb * 128 + r;
        float mu = mu_s[r], rstd = rs_s[r];
        const __half* uh = (const __half*)(gq + 6144 + (size_t)l * GROWB);
        size_t obase = (size_t)(b * LL + l) * DD + h * HD;
        #pragma unroll
        for (int c = c0; c < c0 + 32; c += 2) {
            float u0 = __half2float(uh[c + 0]);
            float u1 = __half2float(uh[c + 1]);
            float t0 = ((aS[r * 68 + c + 0] - mu) * rstd * nag[c + 0] + nab[c + 0]) * u0;
            float t1 = ((aS[r * 68 + c + 1] - mu) * rstd * nag[c + 1] + nab[c + 1]) * u1;
            *(uint32_t*)(aout + obase + c) = pack2h(__float2half(t0), __float2half(t1));
        }
    }
}

// ---------------- host -------------------------------------------------------
extern "C" void kernel_launch(void* const* d_in, const int* in_sizes, int n_in,
                              void* d_out, int out_size)
{
    const float* x      = (const float*)d_in[0];
    const float* w_qkuv = (const float*)d_in[2];
    const float* w_out  = (const float*)d_in[3];
    const float* w1     = (const float*)d_in[4];
    const float* w2     = (const float*)d_in[5];
    const float* w3     = (const float*)d_in[6];
    const float* ln1_g  = (const float*)d_in[7];
    const float* ln1_b  = (const float*)d_in[8];
    const float* ln2_g  = (const float*)d_in[9];
    const float* ln2_b  = (const float*)d_in[10];
    const float* na_g   = (const float*)d_in[11];
    const float* na_b   = (const float*)d_in[12];
    float* out = (float*)d_out;

    __half *xn, *qk, *a, *xn2, *hbuf;
    __half *wq, *wo, *w1t, *w3t, *w2t;
    float *x1;
    cudaGetSymbolAddress((void**)&xn,   g_xn);
    cudaGetSymbolAddress((void**)&qk,   g_qk);
    cudaGetSymbolAddress((void**)&a,    g_a);
    cudaGetSymbolAddress((void**)&x1,   g_x1);
    cudaGetSymbolAddress((void**)&xn2,  g_xn2);
    cudaGetSymbolAddress((void**)&hbuf, g_h);
    cudaGetSymbolAddress((void**)&wq,   g_wqkuv);
    cudaGetSymbolAddress((void**)&wo,   g_wout);
    cudaGetSymbolAddress((void**)&w1t,  g_w1);
    cudaGetSymbolAddress((void**)&w3t,  g_w3);
    cudaGetSymbolAddress((void**)&w2t,  g_w2);

    cudaFuncSetAttribute(gemm_mma<1>, cudaFuncAttributeMaxDynamicSharedMemorySize, GEMM_SMEM);
    cudaFuncSetAttribute(gemm_mma<3>, cudaFuncAttributeMaxDynamicSharedMemorySize, GEMM_SMEM);
    cudaFuncSetAttribute(gemm_dual,   cudaFuncAttributeMaxDynamicSharedMemorySize, DUAL_SMEM);
    cudaFuncSetAttribute(attn_mma,    cudaFuncAttributeMaxDynamicSharedMemorySize, ATT_SMEM);

    dim3 blk(256);

    // 0. weight convert fp32 -> fp16 (native [K,N] layout)
    wconv_kernel<<<4 * DD * DD / 1024, blk>>>(w_qkuv, wq);
    wconv_kernel<<<DD * DD / 1024,     blk>>>(w_out,  wo);
    wconv_kernel<<<DD * FF / 1024,     blk>>>(w1,     w1t);
    wconv_kernel<<<DD * FF / 1024,     blk>>>(w3,     w3t);
    wconv_kernel<<<FF * DD / 1024,     blk>>>(w2,     w2t);

    // 1. LN1 -> fp16
    ln_half_kernel<<<MROWS, blk>>>(x, ln1_g, ln1_b, xn);
    // 2. qkuv = silu(xn @ w_qkuv) -> fp16
    gemm_mma<3><<<dim3(4 * DD / 128, MROWS / 128), blk, GEMM_SMEM>>>(
        xn, wq, nullptr, nullptr, qk, MROWS, 4 * DD, DD);
    // 3. attention -> a fp16
    attn_mma<<<dim3(LL / 128, BB * HH), blk, ATT_SMEM>>>(qk, na_g, na_b, a);
    // 4. x1 = x + a @ w_out
    gemm_mma<1><<<dim3(DD / 128, MROWS / 128), blk, GEMM_SMEM>>>(
        a, wo, x1, x, nullptr, MROWS, DD, DD);
    // 5. LN2 -> fp16
    ln_half_kernel<<<MROWS, blk>>>(x1, ln2_g, ln2_b, xn2);
    // 6+7. h = silu(xn2@w1) * (xn2@w3) -> fp16
    gemm_dual<<<dim3(FF / 64, MROWS / 128), blk, DUAL_SMEM>>>(
        xn2, w1t, w3t, hbuf, MROWS, FF, DD);
    // 8. out = x1 + h @ w2
    gemm_mma<1><<<dim3(DD / 128, MROWS / 128), blk, GEMM_SMEM>>>(
        hbuf, w2t, out, x1, nullptr, MROWS, DD, FF);
}

// round 12
// speedup vs baseline: 2.4096x; 1.0108x over previous
#include <cuda_runtime.h>
#include <cuda_fp16.h>
#include <cstdint>
#include <math.h>

#define BB 2
#define LL 2048
#define DD 1024
#define HH 16
#define HD 64
#define FF 4096
#define MROWS (BB*LL)   // 4096

// ---------------- scratch (device globals) ---------------------------------
__device__ __half g_xn  [MROWS * DD];
__device__ __half g_qk  [MROWS * 4 * DD];   // silu(xn@w_qkuv) fp16
__device__ __half g_a   [MROWS * DD];
__device__ float  g_x1  [MROWS * DD];
__device__ __half g_xn2 [MROWS * DD];
__device__ __half g_h   [MROWS * FF];
// weights in NATIVE [K, N] layout, fp16 (no transpose)
__device__ __half g_wqkuv [DD * 4 * DD];
__device__ __half g_wout  [DD * DD];
__device__ __half g_w1    [DD * FF];
__device__ __half g_w3    [DD * FF];
__device__ __half g_w2    [FF * DD];

__device__ __forceinline__ float silu(float x) {
    return __fdividef(x, 1.0f + __expf(-x));
}
__device__ __forceinline__ uint32_t smem_u32(const void* p) {
    uint32_t a;
    asm("{ .reg .u64 t; cvta.to.shared.u64 t, %1; cvt.u32.u64 %0, t; }" : "=r"(a) : "l"(p));
    return a;
}
__device__ __forceinline__ void cp16(uint32_t s, const void* g) {
    asm volatile("cp.async.cg.shared.global [%0], [%1], 16;" :: "r"(s), "l"(g) : "memory");
}
#define CPCOMMIT() asm volatile("cp.async.commit_group;" ::: "memory")
#define CPWAIT(n)  asm volatile("cp.async.wait_group %0;" :: "n"(n) : "memory")
__device__ __forceinline__ uint32_t pack2h(__half a, __half b) {
    return (uint32_t)__half_as_ushort(a) | ((uint32_t)__half_as_ushort(b) << 16);
}
__device__ __forceinline__ void ldsm4(uint32_t* r, uint32_t a) {
    asm volatile("ldmatrix.sync.aligned.m8n8.x4.shared.b16 {%0,%1,%2,%3}, [%4];"
        : "=r"(r[0]), "=r"(r[1]), "=r"(r[2]), "=r"(r[3]) : "r"(a));
}
__device__ __forceinline__ void ldsm4t(uint32_t* r, uint32_t a) {
    asm volatile("ldmatrix.sync.aligned.m8n8.x4.trans.shared.b16 {%0,%1,%2,%3}, [%4];"
        : "=r"(r[0]), "=r"(r[1]), "=r"(r[2]), "=r"(r[3]) : "r"(a));
}
__device__ __forceinline__ void mma16816(float* c, const uint32_t* a, uint32_t b0, uint32_t b1) {
    asm volatile(
        "mma.sync.aligned.m16n8k16.row.col.f32.f16.f16.f32 "
        "{%0,%1,%2,%3}, {%4,%5,%6,%7}, {%8,%9}, {%0,%1,%2,%3};"
        : "+f"(c[0]), "+f"(c[1]), "+f"(c[2]), "+f"(c[3])
        : "r"(a[0]), "r"(a[1]), "r"(a[2]), "r"(a[3]), "r"(b0), "r"(b1));
}

// ---------------- weight convert fp32 -> fp16 (same layout, streaming) ------
__global__ __launch_bounds__(256) void wconv_kernel(
    const float* __restrict__ w, __half* __restrict__ wt)
{
    int idx = (blockIdx.x * 256 + threadIdx.x) * 4;
    float4 v = *(const float4*)(w + idx);
    *(uint2*)(wt + idx) = make_uint2(
        pack2h(__float2half(v.x), __float2half(v.y)),
        pack2h(__float2half(v.z), __float2half(v.w)));
}

// ---------------- LayerNorm -> fp16 (warp per row, 8 rows per block) --------
__global__ __launch_bounds__(256) void ln_half_kernel(
    const float* __restrict__ x, const float* __restrict__ g,
    const float* __restrict__ b, __half* __restrict__ o)
{
    int wid = threadIdx.x >> 5, lid = threadIdx.x & 31;
    int row = blockIdx.x * 8 + wid;
    const float* xr = x + (size_t)row * DD;
    float s = 0.f, s2 = 0.f;
    float v[8];
    #pragma unroll
    for (int j = 0; j < 8; j++) {
        float4 q = *(const float4*)(xr + (j * 32 + lid) * 4 - lid * 3 + lid * 3);
        // (simple strided float4: element index = j*128 + lid*4)
        (void)q;
        v[j] = 0.f;
    }
    // strided float4 loads: 8 x (32 lanes x 4 floats) = 1024
    float4 q4[8];
    #pragma unroll
    for (int j = 0; j < 8; j++) {
        q4[j] = *(const float4*)(xr + j * 128 + lid * 4);
        s  += q4[j].x + q4[j].y + q4[j].z + q4[j].w;
        s2 += q4[j].x * q4[j].x + q4[j].y * q4[j].y
            + q4[j].z * q4[j].z + q4[j].w * q4[j].w;
    }
    #pragma unroll
    for (int off = 16; off > 0; off >>= 1) {
        s  += __shfl_xor_sync(0xffffffffu, s,  off);
        s2 += __shfl_xor_sync(0xffffffffu, s2, off);
    }
    float mu = s * (1.0f / DD);
    float var = s2 * (1.0f / DD) - mu * mu;
    float rstd = rsqrtf(var + 1e-5f);
    #pragma unroll
    for (int j = 0; j < 8; j++) {
        int c = j * 128 + lid * 4;
        float4 gg = *(const float4*)(g + c);
        float4 bb = *(const float4*)(b + c);
        __half h0 = __float2half((q4[j].x - mu) * rstd * gg.x + bb.x);
        __half h1 = __float2half((q4[j].y - mu) * rstd * gg.y + bb.y);
        __half h2 = __float2half((q4[j].z - mu) * rstd * gg.z + bb.z);
        __half h3 = __float2half((q4[j].w - mu) * rstd * gg.w + bb.w);
        *(uint2*)(o + (size_t)row * DD + c) = make_uint2(pack2h(h0, h1), pack2h(h2, h3));
    }
}

// ---------------- fp16 GEMM: D[M,N] = A[M,K] @ W[K,N] ------------------------
// W consumed in native [K,N] layout via ldsm.trans.
// MODE 1: Cf = acc + aux (fp32 out).  MODE 3: silu(acc) -> Ch fp16.
// CTA 128x128, BK=64, warp 64x32 (2x4), 3-stage, 2 CTAs/SM.
#define SROW 144                    // A row bytes (72 fp16)
#define WROWB 272                   // W row bytes (128 fp16 + pad)
#define AT (128 * SROW)             // 18432
#define WT (64 * WROWB)             // 17408
#define STAGE3 (AT + WT)            // 35840
#define GEMM_SMEM (3 * STAGE3)      // 107520

template <int MODE>
__global__ __launch_bounds__(256, 2) void gemm_mma(
    const __half* __restrict__ A, const __half* __restrict__ Bw,
    float* __restrict__ Cf, const float* __restrict__ aux,
    __half* __restrict__ Ch,
    int M, int N, int K)
{
    extern __shared__ char smem[];
    const uint32_t sbase = smem_u32(smem);
    const int tid = threadIdx.x, lane = tid & 31, wid = tid >> 5;
    const int wm = wid & 1, wn = wid >> 1;
    const int bx = blockIdx.x, by = blockIdx.y;

    const size_t rowbytesA = (size_t)K * 2;
    const size_t rowbytesB = (size_t)N * 2;
    const char* Ab = (const char*)(A + (size_t)by * 128 * K);
    const char* Bb = (const char*)Bw + (size_t)bx * 256;   // column offset bx*128 fp16

    const uint32_t aRowOff = (uint32_t)((wm * 64 + (lane & 15)) * SROW + (lane >> 4) * 16);
    const int bg = lane >> 3;
    const uint32_t bOffW = (uint32_t)(((bg & 1) * 8 + (lane & 7)) * WROWB
                                      + (wn * 32 + (bg >> 1) * 8) * 2);

    auto load_slab = [&](int ks, int st) {
        uint32_t stg = sbase + (uint32_t)st * STAGE3;
        size_t akoff = (size_t)ks * 128;
        size_t bk0 = (size_t)ks * 64;
        #pragma unroll
        for (int i = 0; i < 8; i++) {
            int c = tid + i * 256;
            if (c < 1024) {
                int rr = c >> 3, ck = (c & 7) * 16;
                cp16(stg + (uint32_t)(rr * SROW + ck),
                     Ab + (size_t)rr * rowbytesA + akoff + ck);
            } else {
                int j = c - 1024;
                int rr = j >> 4, ck = (j & 15) * 16;
                cp16(stg + (uint32_t)(AT + rr * WROWB + ck),
                     Bb + (bk0 + rr) * rowbytesB + ck);
            }
        }
        CPCOMMIT();
    };

    float acc[4][4][4];
    #pragma unroll
    for (int mt = 0; mt < 4; mt++)
        #pragma unroll
        for (int nt = 0; nt < 4; nt++)
            #pragma unroll
            for (int j = 0; j < 4; j++) acc[mt][nt][j] = 0.f;

    const int ns = K >> 6;
    load_slab(0, 0);
    if (ns > 1) load_slab(1, 1);

    for (int i = 0; i < ns; i++) {
        if (i + 1 < ns) CPWAIT(1);
        else            CPWAIT(0);
        __syncthreads();
        if (i + 2 < ns) load_slab(i + 2, (i + 2) % 3);

        uint32_t stg = sbase + (uint32_t)(i % 3) * STAGE3;
        uint32_t aB = stg + aRowOff;
        uint32_t bB = stg + AT + bOffW;

        #pragma unroll
        for (int ks = 0; ks < 4; ks++) {
            uint32_t ah[4][4], bh[2][4];
            #pragma unroll
            for (int mt = 0; mt < 4; mt++)
                ldsm4(ah[mt], aB + (uint32_t)(mt * 16 * SROW + ks * 32));
            #pragma unroll
            for (int p = 0; p < 2; p++)
                ldsm4t(bh[p], bB + (uint32_t)(ks * 16 * WROWB + p * 32));
            #pragma unroll
            for (int mt = 0; mt < 4; mt++)
                #pragma unroll
                for (int nt = 0; nt < 4; nt++) {
                    int p = nt >> 1, o = (nt & 1) * 2;
                    mma16816(acc[mt][nt], ah[mt], bh[p][o], bh[p][o + 1]);
                }
        }
    }

    const int groupID = lane >> 2, tid4 = lane & 3;
    #pragma unroll
    for (int mt = 0; mt < 4; mt++) {
        int r0 = by * 128 + wm * 64 + mt * 16 + groupID;
        #pragma unroll
        for (int nt = 0; nt < 4; nt++) {
            int cg = bx * 128 + wn * 32 + nt * 8 + tid4 * 2;
            float* a = acc[mt][nt];
            #pragma unroll
            for (int half = 0; half < 2; half++) {
                size_t off = (size_t)(r0 + half * 8) * N + cg;
                float v0 = a[half * 2 + 0], v1 = a[half * 2 + 1];
                if (MODE == 1) {
                    float2 ax = *(const float2*)(aux + off);
                    float2 o; o.x = v0 + ax.x; o.y = v1 + ax.y;
                    *(float2*)(Cf + off) = o;
                } else {
                    *(uint32_t*)(Ch + off) = pack2h(__float2half(silu(v0)),
                                                    __float2half(silu(v1)));
                }
            }
        }
    }
}

// ---------------- dual GEMM: h = silu(A@W1) * (A@W3) -> fp16 -----------------
#define DWROWB 144
#define DWT (64 * DWROWB)                 // 9216
#define DSTAGE (AT + 2 * DWT)             // 36864
#define DUAL_SMEM (2 * DSTAGE)            // 73728

__global__ __launch_bounds__(256, 2) void gemm_dual(
    const __half* __restrict__ A,
    const __half* __restrict__ B1, const __half* __restrict__ B3,
    __half* __restrict__ Ch,
    int M, int N, int K)
{
    extern __shared__ char smem[];
    const uint32_t sbase = smem_u32(smem);
    const int tid = threadIdx.x, lane = tid & 31, wid = tid >> 5;
    const int wm = wid & 1, wn = wid >> 1;
    const int bx = blockIdx.x, by = blockIdx.y;

    const size_t rowbytesA = (size_t)K * 2;
    const size_t rowbytesB = (size_t)N * 2;
    const char* Ab  = (const char*)(A + (size_t)by * 128 * K);
    const char* B1b = (const char*)B1 + (size_t)bx * 128;
    const char* B3b = (const char*)B3 + (size_t)bx * 128;

    const uint32_t aRowOff = (uint32_t)((wm * 64 + (lane & 15)) * SROW + (lane >> 4) * 16);
    const int bg = lane >> 3;
    const uint32_t bOffW = (uint32_t)(((bg & 1) * 8 + (lane & 7)) * DWROWB
                                      + (wn * 16 + (bg >> 1) * 8) * 2);

    auto load_slab = [&](int ks, int st) {
        uint32_t stg = sbase + (uint32_t)st * DSTAGE;
        size_t akoff = (size_t)ks * 128;
        size_t bk0 = (size_t)ks * 64;
        #pragma unroll
        for (int i = 0; i < 8; i++) {
            int c = tid + i * 256;
            if (c < 1024) {
                int rr = c >> 3, ck = (c & 7) * 16;
                cp16(stg + (uint32_t)(rr * SROW + ck),
                     Ab + (size_t)rr * rowbytesA + akoff + ck);
            } else {
                int j = c - 1024;
                int tw = j >> 9;
                int jj = j & 511;
                int rr = jj >> 3, ck = (jj & 7) * 16;
                cp16(stg + (uint32_t)(AT + tw * DWT + rr * DWROWB + ck),
                     (tw ? B3b : B1b) + (bk0 + rr) * rowbytesB + ck);
            }
        }
        CPCOMMIT();
    };

    float acc1[4][2][4], acc3[4][2][4];
    #pragma unroll
    for (int mt = 0; mt < 4; mt++)
        #pragma unroll
        for (int nt = 0; nt < 2; nt++)
            #pragma unroll
            for (int j = 0; j < 4; j++) { acc1[mt][nt][j] = 0.f; acc3[mt][nt][j] = 0.f; }

    const int ns = K >> 6;
    load_slab(0, 0);

    for (int i = 0; i < ns; i++) {
        CPWAIT(0);
        __syncthreads();
        if (i + 1 < ns) load_slab(i + 1, (i + 1) & 1);

        uint32_t stg = sbase + (uint32_t)(i & 1) * DSTAGE;
        uint32_t aB  = stg + aRowOff;
        uint32_t b1B = stg + AT + bOffW;
        uint32_t b3B = stg + AT + DWT + bOffW;

        #pragma unroll
        for (int ks = 0; ks < 4; ks++) {
            uint32_t ah[4][4], b1h[4], b3h[4];
            #pragma unroll
            for (int mt = 0; mt < 4; mt++)
                ldsm4(ah[mt], aB + (uint32_t)(mt * 16 * SROW + ks * 32));
            uint32_t ko = (uint32_t)(ks * 16 * DWROWB);
            ldsm4t(b1h, b1B + ko);
            ldsm4t(b3h, b3B + ko);
            #pragma unroll
            for (int mt = 0; mt < 4; mt++)
                #pragma unroll
                for (int nt = 0; nt < 2; nt++) {
                    int o = nt * 2;
                    mma16816(acc1[mt][nt], ah[mt], b1h[o], b1h[o + 1]);
                    mma16816(acc3[mt][nt], ah[mt], b3h[o], b3h[o + 1]);
                }
        }
    }

    const int groupID = lane >> 2, tid4 = lane & 3;
    #pragma unroll
    for (int mt = 0; mt < 4; mt++) {
        int r0 = by * 128 + wm * 64 + mt * 16 + groupID;
        #pragma unroll
        for (int nt = 0; nt < 2; nt++) {
            int cg = bx * 64 + wn * 16 + nt * 8 + tid4 * 2;
            #pragma unroll
            for (int half = 0; half < 2; half++) {
                size_t off = (size_t)(r0 + half * 8) * N + cg;
                float t0 = silu(acc1[mt][nt][half * 2 + 0]) * acc3[mt][nt][half * 2 + 0];
                float t1 = silu(acc1[mt][nt][half * 2 + 1]) * acc3[mt][nt][half * 2 + 1];
                *(uint32_t*)(Ch + off) = pack2h(__float2half(t0), __float2half(t1));
            }
        }
    }
}

// ---------------- Fused attention (fp16, pipelined loads, 2 CTAs/SM) ---------
#define AROWB 144
#define SROWB 272
#define ATT_SMEM 108544
#define GROWB 8192

__global__ __launch_bounds__(256, 2) void attn_mma(
    const __half* __restrict__ qk,
    const float* __restrict__ nag, const float* __restrict__ nab,
    __half* __restrict__ aout)
{
    extern __shared__ char smc[];
    const uint32_t sb = smem_u32(smc);
    const uint32_t oQ = 0;
    const uint32_t oK[2] = {18432, 36864};
    const uint32_t oV = 55296;
    const uint32_t oS = 73728;
    __half* sp = (__half*)(smc + oS);
    float* aS = (float*)(smc + oS);
    __shared__ float mu_s[128], rs_s[128];

    const int qb = (int)gridDim.x - 1 - (int)blockIdx.x;
    const int bh = blockIdx.y;
    const int b = bh >> 4, h = bh & 15;
    const int tid = threadIdx.x, lane = tid & 31, wid = tid >> 5;
    const int wm = wid & 1, wn = wid >> 1;
    const int groupID = lane >> 2, tid4 = lane & 3;

    const char* gq = (const char*)qk + (size_t)(b * LL) * GROWB + h * 128;

    auto ldt = [&](uint32_t so, const char* g) {
        #pragma unroll
        for (int i = 0; i < 4; i++) {
            int idx = tid + i * 256;
            int r = idx >> 3, ck = (idx & 7) * 16;
            cp16(sb + so + (uint32_t)(r * AROWB + ck), g + (size_t)r * GROWB + ck);
        }
    };

    ldt(oQ, gq + (size_t)(qb * 128) * GROWB);
    ldt(oK[0], gq + 2048);
    CPCOMMIT();

    const uint32_t aOffQ = (uint32_t)((wm * 64 + (lane & 15)) * AROWB + (lane >> 4) * 16);
    const int bg = lane >> 3;
    const uint32_t bOffK = (uint32_t)((wn * 32 + (bg >> 1) * 8 + (lane & 7)) * AROWB + (bg & 1) * 16);
    const uint32_t aOffS = (uint32_t)((wm * 64 + (lane & 15)) * SROWB + (lane >> 4) * 16);
    const uint32_t bOffV = (uint32_t)(((bg & 1) * 8 + (lane & 7)) * AROWB + (wn * 16 + (bg >> 1) * 8) * 2);

    float oacc[4][2][4];
    #pragma unroll
    for (int mt = 0; mt < 4; mt++)
        #pragma unroll
        for (int nt = 0; nt < 2; nt++)
            #pragma unroll
            for (int j = 0; j < 4; j++) oacc[mt][nt][j] = 0.f;

    for (int kb = 0; kb <= qb; kb++) {
        const int st = kb & 1;
        const bool more = (kb < qb);
        __syncthreads();
        ldt(oV, gq + 4096 + (size_t)(kb * 128) * GROWB);
        CPCOMMIT();
        if (more) {
            ldt(oK[st ^ 1], gq + 2048 + (size_t)((kb + 1) * 128) * GROWB);
            CPCOMMIT();
        }
        if (more) CPWAIT(2); else CPWAIT(1);
        __syncthreads();

        float sacc[4][4][4];
        #pragma unroll
        for (int mt = 0; mt < 4; mt++)
            #pragma unroll
            for (int nt = 0; nt < 4; nt++)
                #pragma unroll
                for (int j = 0; j < 4; j++) sacc[mt][nt][j] = 0.f;

        #pragma unroll
        for (int ks = 0; ks < 4; ks++) {
            uint32_t q4[4][4], k4[2][4];
            #pragma unroll
            for (int mt = 0; mt < 4; mt++)
                ldsm4(q4[mt], sb + oQ + aOffQ + (uint32_t)(mt * 16 * AROWB + ks * 32));
            #pragma unroll
            for (int p = 0; p < 2; p++)
                ldsm4(k4[p], sb + oK[st] + bOffK + (uint32_t)(p * 16 * AROWB + ks * 32));
            #pragma unroll
            for (int mt = 0; mt < 4; mt++)
                #pragma unroll
                for (int nt = 0; nt < 4; nt++) {
                    int p = nt >> 1, o = (nt & 1) * 2;
                    mma16816(sacc[mt][nt], q4[mt], k4[p][o], k4[p][o + 1]);
                }
        }

        const bool diag = (kb == qb);
        #pragma unroll
        for (int mt = 0; mt < 4; mt++) {
            #pragma unroll
            for (int half = 0; half < 2; half++) {
                int r = wm * 64 + mt * 16 + groupID + half * 8;
                #pragma unroll
                for (int nt = 0; nt < 4; nt++) {
                    int c = wn * 32 + nt * 8 + tid4 * 2;
                    float s0 = silu(sacc[mt][nt][half * 2 + 0] * 0.125f);
                    float s1 = silu(sacc[mt][nt][half * 2 + 1] * 0.125f);
                    if (diag) {
                        if (c > r) s0 = 0.f;
                        if (c + 1 > r) s1 = 0.f;
                    }
                    *(uint32_t*)(sp + r * 136 + c) = pack2h(__float2half(s0), __float2half(s1));
                }
            }
        }
        if (more) CPWAIT(1); else CPWAIT(0);
        __syncthreads();

        #pragma unroll
        for (int ks = 0; ks < 8; ks++) {
            uint32_t s4[4][4], v4[4];
            #pragma unroll
            for (int mt = 0; mt < 4; mt++)
                ldsm4(s4[mt], sb + oS + aOffS + (uint32_t)(mt * 16 * SROWB + ks * 32));
            ldsm4t(v4, sb + oV + bOffV + (uint32_t)(ks * 16 * AROWB));
            #pragma unroll
            for (int mt = 0; mt < 4; mt++)
                #pragma unroll
                for (int nt = 0; nt < 2; nt++) {
                    int o = nt * 2;
                    mma16816(oacc[mt][nt], s4[mt], v4[o], v4[o + 1]);
                }
        }
    }

    __syncthreads();
    #pragma unroll
    for (int mt = 0; mt < 4; mt++)
        #pragma unroll
        for (int half = 0; half < 2; half++) {
            int r = wm * 64 + mt * 16 + groupID + half * 8;
            #pragma unroll
            for (int nt = 0; nt < 2; nt++) {
                int c = wn * 16 + nt * 8 + tid4 * 2;
                float2 v;
                v.x = oacc[mt][nt][half * 2 + 0];
                v.y = oacc[mt][nt][half * 2 + 1];
                *(float2*)(aS + r * 68 + c) = v;
            }
        }
    __syncthreads();
    if (tid < 128) {
        float s = 0.f, s2 = 0.f;
        #pragma unroll
        for (int c = 0; c < 64; c++) {
            float v = aS[tid * 68 + c];
            s += v; s2 += v * v;
        }
        float mu = s * (1.0f / 64.0f);
        float var = s2 * (1.0f / 64.0f) - mu * mu;
        mu_s[tid] = mu;
        rs_s[tid] = rsqrtf(var + 1e-5f);
    }
    __syncthreads();
    {
        int r = tid >> 1;
        int c0 = (tid & 1) * 32;
        int l = qb * 128 + r;
        float mu = mu_s[r], rstd = rs_s[r];
        const __half* uh = (const __half*)(gq + 6144 + (size_t)l * GROWB);
        size_t obase = (size_t)(b * LL + l) * DD + h * HD;
        #pragma unroll
        for (int c = c0; c < c0 + 32; c += 2) {
            float u0 = __half2float(uh[c + 0]);
            float u1 = __half2float(uh[c + 1]);
            float t0 = ((aS[r * 68 + c + 0] - mu) * rstd * nag[c + 0] + nab[c + 0]) * u0;
            float t1 = ((aS[r * 68 + c + 1] - mu) * rstd * nag[c + 1] + nab[c + 1]) * u1;
            *(uint32_t*)(aout + obase + c) = pack2h(__float2half(t0), __float2half(t1));
        }
    }
}

// ---------------- host -------------------------------------------------------
extern "C" void kernel_launch(void* const* d_in, const int* in_sizes, int n_in,
                              void* d_out, int out_size)
{
    const float* x      = (const float*)d_in[0];
    const float* w_qkuv = (const float*)d_in[2];
    const float* w_out  = (const float*)d_in[3];
    const float* w1     = (const float*)d_in[4];
    const float* w2     = (const float*)d_in[5];
    const float* w3     = (const float*)d_in[6];
    const float* ln1_g  = (const float*)d_in[7];
    const float* ln1_b  = (const float*)d_in[8];
    const float* ln2_g  = (const float*)d_in[9];
    const float* ln2_b  = (const float*)d_in[10];
    const float* na_g   = (const float*)d_in[11];
    const float* na_b   = (const float*)d_in[12];
    float* out = (float*)d_out;

    __half *xn, *qk, *a, *xn2, *hbuf;
    __half *wq, *wo, *w1t, *w3t, *w2t;
    float *x1;
    cudaGetSymbolAddress((void**)&xn,   g_xn);
    cudaGetSymbolAddress((void**)&qk,   g_qk);
    cudaGetSymbolAddress((void**)&a,    g_a);
    cudaGetSymbolAddress((void**)&x1,   g_x1);
    cudaGetSymbolAddress((void**)&xn2,  g_xn2);
    cudaGetSymbolAddress((void**)&hbuf, g_h);
    cudaGetSymbolAddress((void**)&wq,   g_wqkuv);
    cudaGetSymbolAddress((void**)&wo,   g_wout);
    cudaGetSymbolAddress((void**)&w1t,  g_w1);
    cudaGetSymbolAddress((void**)&w3t,  g_w3);
    cudaGetSymbolAddress((void**)&w2t,  g_w2);

    cudaFuncSetAttribute(gemm_mma<1>, cudaFuncAttributeMaxDynamicSharedMemorySize, GEMM_SMEM);
    cudaFuncSetAttribute(gemm_mma<3>, cudaFuncAttributeMaxDynamicSharedMemorySize, GEMM_SMEM);
    cudaFuncSetAttribute(gemm_dual,   cudaFuncAttributeMaxDynamicSharedMemorySize, DUAL_SMEM);
    cudaFuncSetAttribute(attn_mma,    cudaFuncAttributeMaxDynamicSharedMemorySize, ATT_SMEM);

    dim3 blk(256);

    // 0. weight convert fp32 -> fp16 (native [K,N] layout)
    wconv_kernel<<<4 * DD * DD / 1024, blk>>>(w_qkuv, wq);
    wconv_kernel<<<DD * DD / 1024,     blk>>>(w_out,  wo);
    wconv_kernel<<<DD * FF / 1024,     blk>>>(w1,     w1t);
    wconv_kernel<<<DD * FF / 1024,     blk>>>(w3,     w3t);
    wconv_kernel<<<FF * DD / 1024,     blk>>>(w2,     w2t);

    // 1. LN1 -> fp16
    ln_half_kernel<<<MROWS / 8, blk>>>(x, ln1_g, ln1_b, xn);
    // 2. qkuv = silu(xn @ w_qkuv) -> fp16
    gemm_mma<3><<<dim3(4 * DD / 128, MROWS / 128), blk, GEMM_SMEM>>>(
        xn, wq, nullptr, nullptr, qk, MROWS, 4 * DD, DD);
    // 3. attention -> a fp16
    attn_mma<<<dim3(LL / 128, BB * HH), blk, ATT_SMEM>>>(qk, na_g, na_b, a);
    // 4. x1 = x + a @ w_out
    gemm_mma<1><<<dim3(DD / 128, MROWS / 128), blk, GEMM_SMEM>>>(
        a, wo, x1, x, nullptr, MROWS, DD, DD);
    // 5. LN2 -> fp16
    ln_half_kernel<<<MROWS / 8, blk>>>(x1, ln2_g, ln2_b, xn2);
    // 6+7. h = silu(xn2@w1) * (xn2@w3) -> fp16
    gemm_dual<<<dim3(FF / 64, MROWS / 128), blk, DUAL_SMEM>>>(
        xn2, w1t, w3t, hbuf, MROWS, FF, DD);
    // 8. out = x1 + h @ w2
    gemm_mma<1><<<dim3(DD / 128, MROWS / 128), blk, GEMM_SMEM>>>(
        hbuf, w2t, out, x1, nullptr, MROWS, DD, FF);
}

// round 13
// speedup vs baseline: 2.7196x; 1.1286x over previous
#include <cuda_runtime.h>
#include <cuda_fp16.h>
#include <cstdint>
#include <math.h>

#define BB 2
#define LL 2048
#define DD 1024
#define HH 16
#define HD 64
#define FF 4096
#define MROWS (BB*LL)   // 4096

// ---------------- scratch (device globals) ---------------------------------
__device__ __half g_xn  [MROWS * DD];
__device__ __half g_qk  [MROWS * 4 * DD];   // silu(xn@w_qkuv) fp16
__device__ __half g_a   [MROWS * DD];
__device__ float  g_x1  [MROWS * DD];
__device__ __half g_xn2 [MROWS * DD];
__device__ __half g_h   [MROWS * FF];
// weights in NATIVE [K, N] layout, fp16 (no transpose)
__device__ __half g_wqkuv [DD * 4 * DD];
__device__ __half g_wout  [DD * DD];
__device__ __half g_w1    [DD * FF];
__device__ __half g_w3    [DD * FF];
__device__ __half g_w2    [FF * DD];

__device__ __forceinline__ float silu(float x) {
    return __fdividef(x, 1.0f + __expf(-x));
}
__device__ __forceinline__ uint32_t smem_u32(const void* p) {
    uint32_t a;
    asm("{ .reg .u64 t; cvta.to.shared.u64 t, %1; cvt.u32.u64 %0, t; }" : "=r"(a) : "l"(p));
    return a;
}
__device__ __forceinline__ void cp16(uint32_t s, const void* g) {
    asm volatile("cp.async.cg.shared.global [%0], [%1], 16;" :: "r"(s), "l"(g) : "memory");
}
#define CPCOMMIT() asm volatile("cp.async.commit_group;" ::: "memory")
#define CPWAIT(n)  asm volatile("cp.async.wait_group %0;" :: "n"(n) : "memory")
__device__ __forceinline__ uint32_t pack2h(__half a, __half b) {
    return (uint32_t)__half_as_ushort(a) | ((uint32_t)__half_as_ushort(b) << 16);
}
__device__ __forceinline__ void ldsm4(uint32_t* r, uint32_t a) {
    asm volatile("ldmatrix.sync.aligned.m8n8.x4.shared.b16 {%0,%1,%2,%3}, [%4];"
        : "=r"(r[0]), "=r"(r[1]), "=r"(r[2]), "=r"(r[3]) : "r"(a));
}
__device__ __forceinline__ void ldsm4t(uint32_t* r, uint32_t a) {
    asm volatile("ldmatrix.sync.aligned.m8n8.x4.trans.shared.b16 {%0,%1,%2,%3}, [%4];"
        : "=r"(r[0]), "=r"(r[1]), "=r"(r[2]), "=r"(r[3]) : "r"(a));
}
__device__ __forceinline__ void mma16816(float* c, const uint32_t* a, uint32_t b0, uint32_t b1) {
    asm volatile(
        "mma.sync.aligned.m16n8k16.row.col.f32.f16.f16.f32 "
        "{%0,%1,%2,%3}, {%4,%5,%6,%7}, {%8,%9}, {%0,%1,%2,%3};"
        : "+f"(c[0]), "+f"(c[1]), "+f"(c[2]), "+f"(c[3])
        : "r"(a[0]), "r"(a[1]), "r"(a[2]), "r"(a[3]), "r"(b0), "r"(b1));
}

// ---------------- fp32 -> fp16 chunk convert (32768 elems per CTA) ----------
__device__ __forceinline__ void conv_chunk(const float* __restrict__ src,
                                           __half* __restrict__ dst,
                                           int cta, int tid)
{
    size_t base = (size_t)cta * 32768;
    #pragma unroll
    for (int it = 0; it < 32; it++) {
        size_t idx = base + (size_t)(it * 256 + tid) * 4;
        float4 v = *(const float4*)(src + idx);
        *(uint2*)(dst + idx) = make_uint2(
            pack2h(__float2half(v.x), __float2half(v.y)),
            pack2h(__float2half(v.z), __float2half(v.w)));
    }
}

// ---------------- LayerNorm row (warp-per-row body) --------------------------
__device__ __forceinline__ void ln_row(const float* __restrict__ xr,
                                       const float* __restrict__ g,
                                       const float* __restrict__ b,
                                       __half* __restrict__ orow, int lid)
{
    float s = 0.f, s2 = 0.f;
    float4 q4[8];
    #pragma unroll
    for (int j = 0; j < 8; j++) {
        q4[j] = *(const float4*)(xr + j * 128 + lid * 4);
        s  += q4[j].x + q4[j].y + q4[j].z + q4[j].w;
        s2 += q4[j].x * q4[j].x + q4[j].y * q4[j].y
            + q4[j].z * q4[j].z + q4[j].w * q4[j].w;
    }
    #pragma unroll
    for (int off = 16; off > 0; off >>= 1) {
        s  += __shfl_xor_sync(0xffffffffu, s,  off);
        s2 += __shfl_xor_sync(0xffffffffu, s2, off);
    }
    float mu = s * (1.0f / DD);
    float var = s2 * (1.0f / DD) - mu * mu;
    float rstd = rsqrtf(var + 1e-5f);
    #pragma unroll
    for (int j = 0; j < 8; j++) {
        int c = j * 128 + lid * 4;
        float4 gg = *(const float4*)(g + c);
        float4 bb = *(const float4*)(b + c);
        __half h0 = __float2half((q4[j].x - mu) * rstd * gg.x + bb.x);
        __half h1 = __float2half((q4[j].y - mu) * rstd * gg.y + bb.y);
        __half h2 = __float2half((q4[j].z - mu) * rstd * gg.z + bb.z);
        __half h3 = __float2half((q4[j].w - mu) * rstd * gg.w + bb.w);
        *(uint2*)(orow + c) = make_uint2(pack2h(h0, h1), pack2h(h2, h3));
    }
}

// ---------------- LN1 + wqkuv convert, fused launch --------------------------
// CTAs [0, 512): LN of 8 rows each. CTAs [512, 512+128): convert w_qkuv.
__global__ __launch_bounds__(256) void ln_conv_kernel(
    const float* __restrict__ x, const float* __restrict__ g,
    const float* __restrict__ b, __half* __restrict__ o,
    const float* __restrict__ wsrc, __half* __restrict__ wdst)
{
    int bid = blockIdx.x;
    int wid = threadIdx.x >> 5, lid = threadIdx.x & 31;
    if (bid < MROWS / 8) {
        int row = bid * 8 + wid;
        ln_row(x + (size_t)row * DD, g, b, o + (size_t)row * DD, lid);
    } else {
        conv_chunk(wsrc, wdst, bid - MROWS / 8, threadIdx.x);
    }
}

// ---------------- LayerNorm standalone (LN2) ---------------------------------
__global__ __launch_bounds__(256) void ln_half_kernel(
    const float* __restrict__ x, const float* __restrict__ g,
    const float* __restrict__ b, __half* __restrict__ o)
{
    int wid = threadIdx.x >> 5, lid = threadIdx.x & 31;
    int row = blockIdx.x * 8 + wid;
    ln_row(x + (size_t)row * DD, g, b, o + (size_t)row * DD, lid);
}

// ---------------- fp16 GEMM: D[M,N] = A[M,K] @ W[K,N] ------------------------
#define SROW 144
#define WROWB 272
#define AT (128 * SROW)             // 18432
#define WT (64 * WROWB)             // 17408
#define STAGE3 (AT + WT)            // 35840
#define GEMM_SMEM (3 * STAGE3)      // 107520

template <int MODE>
__global__ __launch_bounds__(256, 2) void gemm_mma(
    const __half* __restrict__ A, const __half* __restrict__ Bw,
    float* __restrict__ Cf, const float* __restrict__ aux,
    __half* __restrict__ Ch,
    int M, int N, int K)
{
    extern __shared__ char smem[];
    const uint32_t sbase = smem_u32(smem);
    const int tid = threadIdx.x, lane = tid & 31, wid = tid >> 5;
    const int wm = wid & 1, wn = wid >> 1;
    const int bx = blockIdx.x, by = blockIdx.y;

    const size_t rowbytesA = (size_t)K * 2;
    const size_t rowbytesB = (size_t)N * 2;
    const char* Ab = (const char*)(A + (size_t)by * 128 * K);
    const char* Bb = (const char*)Bw + (size_t)bx * 256;

    const uint32_t aRowOff = (uint32_t)((wm * 64 + (lane & 15)) * SROW + (lane >> 4) * 16);
    const int bg = lane >> 3;
    const uint32_t bOffW = (uint32_t)(((bg & 1) * 8 + (lane & 7)) * WROWB
                                      + (wn * 32 + (bg >> 1) * 8) * 2);

    auto load_slab = [&](int ks, int st) {
        uint32_t stg = sbase + (uint32_t)st * STAGE3;
        size_t akoff = (size_t)ks * 128;
        size_t bk0 = (size_t)ks * 64;
        #pragma unroll
        for (int i = 0; i < 8; i++) {
            int c = tid + i * 256;
            if (c < 1024) {
                int rr = c >> 3, ck = (c & 7) * 16;
                cp16(stg + (uint32_t)(rr * SROW + ck),
                     Ab + (size_t)rr * rowbytesA + akoff + ck);
            } else {
                int j = c - 1024;
                int rr = j >> 4, ck = (j & 15) * 16;
                cp16(stg + (uint32_t)(AT + rr * WROWB + ck),
                     Bb + (bk0 + rr) * rowbytesB + ck);
            }
        }
        CPCOMMIT();
    };

    float acc[4][4][4];
    #pragma unroll
    for (int mt = 0; mt < 4; mt++)
        #pragma unroll
        for (int nt = 0; nt < 4; nt++)
            #pragma unroll
            for (int j = 0; j < 4; j++) acc[mt][nt][j] = 0.f;

    const int ns = K >> 6;
    load_slab(0, 0);
    if (ns > 1) load_slab(1, 1);

    for (int i = 0; i < ns; i++) {
        if (i + 1 < ns) CPWAIT(1);
        else            CPWAIT(0);
        __syncthreads();
        if (i + 2 < ns) load_slab(i + 2, (i + 2) % 3);

        uint32_t stg = sbase + (uint32_t)(i % 3) * STAGE3;
        uint32_t aB = stg + aRowOff;
        uint32_t bB = stg + AT + bOffW;

        #pragma unroll
        for (int ks = 0; ks < 4; ks++) {
            uint32_t ah[4][4], bh[2][4];
            #pragma unroll
            for (int mt = 0; mt < 4; mt++)
                ldsm4(ah[mt], aB + (uint32_t)(mt * 16 * SROW + ks * 32));
            #pragma unroll
            for (int p = 0; p < 2; p++)
                ldsm4t(bh[p], bB + (uint32_t)(ks * 16 * WROWB + p * 32));
            #pragma unroll
            for (int mt = 0; mt < 4; mt++)
                #pragma unroll
                for (int nt = 0; nt < 4; nt++) {
                    int p = nt >> 1, o = (nt & 1) * 2;
                    mma16816(acc[mt][nt], ah[mt], bh[p][o], bh[p][o + 1]);
                }
        }
    }

    const int groupID = lane >> 2, tid4 = lane & 3;
    #pragma unroll
    for (int mt = 0; mt < 4; mt++) {
        int r0 = by * 128 + wm * 64 + mt * 16 + groupID;
        #pragma unroll
        for (int nt = 0; nt < 4; nt++) {
            int cg = bx * 128 + wn * 32 + nt * 8 + tid4 * 2;
            float* a = acc[mt][nt];
            #pragma unroll
            for (int half = 0; half < 2; half++) {
                size_t off = (size_t)(r0 + half * 8) * N + cg;
                float v0 = a[half * 2 + 0], v1 = a[half * 2 + 1];
                if (MODE == 1) {
                    float2 ax = *(const float2*)(aux + off);
                    float2 o; o.x = v0 + ax.x; o.y = v1 + ax.y;
                    *(float2*)(Cf + off) = o;
                } else {
                    *(uint32_t*)(Ch + off) = pack2h(__float2half(silu(v0)),
                                                    __float2half(silu(v1)));
                }
            }
        }
    }
}

// ---------------- dual GEMM: h = silu(A@W1) * (A@W3) -> fp16 -----------------
#define DWROWB 144
#define DWT (64 * DWROWB)                 // 9216
#define DSTAGE (AT + 2 * DWT)             // 36864
#define DUAL_SMEM (2 * DSTAGE)            // 73728

__global__ __launch_bounds__(256, 2) void gemm_dual(
    const __half* __restrict__ A,
    const __half* __restrict__ B1, const __half* __restrict__ B3,
    __half* __restrict__ Ch,
    int M, int N, int K)
{
    extern __shared__ char smem[];
    const uint32_t sbase = smem_u32(smem);
    const int tid = threadIdx.x, lane = tid & 31, wid = tid >> 5;
    const int wm = wid & 1, wn = wid >> 1;
    const int bx = blockIdx.x, by = blockIdx.y;

    const size_t rowbytesA = (size_t)K * 2;
    const size_t rowbytesB = (size_t)N * 2;
    const char* Ab  = (const char*)(A + (size_t)by * 128 * K);
    const char* B1b = (const char*)B1 + (size_t)bx * 128;
    const char* B3b = (const char*)B3 + (size_t)bx * 128;

    const uint32_t aRowOff = (uint32_t)((wm * 64 + (lane & 15)) * SROW + (lane >> 4) * 16);
    const int bg = lane >> 3;
    const uint32_t bOffW = (uint32_t)(((bg & 1) * 8 + (lane & 7)) * DWROWB
                                      + (wn * 16 + (bg >> 1) * 8) * 2);

    auto load_slab = [&](int ks, int st) {
        uint32_t stg = sbase + (uint32_t)st * DSTAGE;
        size_t akoff = (size_t)ks * 128;
        size_t bk0 = (size_t)ks * 64;
        #pragma unroll
        for (int i = 0; i < 8; i++) {
            int c = tid + i * 256;
            if (c < 1024) {
                int rr = c >> 3, ck = (c & 7) * 16;
                cp16(stg + (uint32_t)(rr * SROW + ck),
                     Ab + (size_t)rr * rowbytesA + akoff + ck);
            } else {
                int j = c - 1024;
                int tw = j >> 9;
                int jj = j & 511;
                int rr = jj >> 3, ck = (jj & 7) * 16;
                cp16(stg + (uint32_t)(AT + tw * DWT + rr * DWROWB + ck),
                     (tw ? B3b : B1b) + (bk0 + rr) * rowbytesB + ck);
            }
        }
        CPCOMMIT();
    };

    float acc1[4][2][4], acc3[4][2][4];
    #pragma unroll
    for (int mt = 0; mt < 4; mt++)
        #pragma unroll
        for (int nt = 0; nt < 2; nt++)
            #pragma unroll
            for (int j = 0; j < 4; j++) { acc1[mt][nt][j] = 0.f; acc3[mt][nt][j] = 0.f; }

    const int ns = K >> 6;
    load_slab(0, 0);

    for (int i = 0; i < ns; i++) {
        CPWAIT(0);
        __syncthreads();
        if (i + 1 < ns) load_slab(i + 1, (i + 1) & 1);

        uint32_t stg = sbase + (uint32_t)(i & 1) * DSTAGE;
        uint32_t aB  = stg + aRowOff;
        uint32_t b1B = stg + AT + bOffW;
        uint32_t b3B = stg + AT + DWT + bOffW;

        #pragma unroll
        for (int ks = 0; ks < 4; ks++) {
            uint32_t ah[4][4], b1h[4], b3h[4];
            #pragma unroll
            for (int mt = 0; mt < 4; mt++)
                ldsm4(ah[mt], aB + (uint32_t)(mt * 16 * SROW + ks * 32));
            uint32_t ko = (uint32_t)(ks * 16 * DWROWB);
            ldsm4t(b1h, b1B + ko);
            ldsm4t(b3h, b3B + ko);
            #pragma unroll
            for (int mt = 0; mt < 4; mt++)
                #pragma unroll
                for (int nt = 0; nt < 2; nt++) {
                    int o = nt * 2;
                    mma16816(acc1[mt][nt], ah[mt], b1h[o], b1h[o + 1]);
                    mma16816(acc3[mt][nt], ah[mt], b3h[o], b3h[o + 1]);
                }
        }
    }

    const int groupID = lane >> 2, tid4 = lane & 3;
    #pragma unroll
    for (int mt = 0; mt < 4; mt++) {
        int r0 = by * 128 + wm * 64 + mt * 16 + groupID;
        #pragma unroll
        for (int nt = 0; nt < 2; nt++) {
            int cg = bx * 64 + wn * 16 + nt * 8 + tid4 * 2;
            #pragma unroll
            for (int half = 0; half < 2; half++) {
                size_t off = (size_t)(r0 + half * 8) * N + cg;
                float t0 = silu(acc1[mt][nt][half * 2 + 0]) * acc3[mt][nt][half * 2 + 0];
                float t1 = silu(acc1[mt][nt][half * 2 + 1]) * acc3[mt][nt][half * 2 + 1];
                *(uint32_t*)(Ch + off) = pack2h(__float2half(t0), __float2half(t1));
            }
        }
    }
}

// ---------------- Fused attention + late weight conversions ------------------
// CTAs [0, 512): attention (heavy-first). CTAs [512, 512+416): convert
// w_out (32 chunks), w1 (128), w3 (128), w2 (128).
#define AROWB 144
#define SROWB 272
#define ATT_SMEM 108544
#define GROWB 8192
#define ATT_CTAS 512
#define CONV_CTAS 416

__global__ __launch_bounds__(256, 2) void attn_mma(
    const __half* __restrict__ qk,
    const float* __restrict__ nag, const float* __restrict__ nab,
    __half* __restrict__ aout,
    const float* __restrict__ woF, __half* __restrict__ woH,
    const float* __restrict__ w1F, __half* __restrict__ w1H,
    const float* __restrict__ w3F, __half* __restrict__ w3H,
    const float* __restrict__ w2F, __half* __restrict__ w2H)
{
    const int bid = blockIdx.x;
    const int tid = threadIdx.x;
    if (bid >= ATT_CTAS) {
        int j = bid - ATT_CTAS;
        if (j < 32)        conv_chunk(woF, woH, j, tid);
        else if (j < 160)  conv_chunk(w1F, w1H, j - 32, tid);
        else if (j < 288)  conv_chunk(w3F, w3H, j - 160, tid);
        else               conv_chunk(w2F, w2H, j - 288, tid);
        return;
    }

    extern __shared__ char smc[];
    const uint32_t sb = smem_u32(smc);
    const uint32_t oQ = 0;
    const uint32_t oK[2] = {18432, 36864};
    const uint32_t oV = 55296;
    const uint32_t oS = 73728;
    __half* sp = (__half*)(smc + oS);
    float* aS = (float*)(smc + oS);
    __shared__ float mu_s[128], rs_s[128];

    const int qb = 15 - (bid >> 5);     // heavy blocks first
    const int bh = bid & 31;
    const int b = bh >> 4, h = bh & 15;
    const int lane = tid & 31, wid = tid >> 5;
    const int wm = wid & 1, wn = wid >> 1;
    const int groupID = lane >> 2, tid4 = lane & 3;

    const char* gq = (const char*)qk + (size_t)(b * LL) * GROWB + h * 128;

    auto ldt = [&](uint32_t so, const char* g) {
        #pragma unroll
        for (int i = 0; i < 4; i++) {
            int idx = tid + i * 256;
            int r = idx >> 3, ck = (idx & 7) * 16;
            cp16(sb + so + (uint32_t)(r * AROWB + ck), g + (size_t)r * GROWB + ck);
        }
    };

    ldt(oQ, gq + (size_t)(qb * 128) * GROWB);
    ldt(oK[0], gq + 2048);
    CPCOMMIT();

    const uint32_t aOffQ = (uint32_t)((wm * 64 + (lane & 15)) * AROWB + (lane >> 4) * 16);
    const int bg = lane >> 3;
    const uint32_t bOffK = (uint32_t)((wn * 32 + (bg >> 1) * 8 + (lane & 7)) * AROWB + (bg & 1) * 16);
    const uint32_t aOffS = (uint32_t)((wm * 64 + (lane & 15)) * SROWB + (lane >> 4) * 16);
    const uint32_t bOffV = (uint32_t)(((bg & 1) * 8 + (lane & 7)) * AROWB + (wn * 16 + (bg >> 1) * 8) * 2);

    float oacc[4][2][4];
    #pragma unroll
    for (int mt = 0; mt < 4; mt++)
        #pragma unroll
        for (int nt = 0; nt < 2; nt++)
            #pragma unroll
            for (int j = 0; j < 4; j++) oacc[mt][nt][j] = 0.f;

    for (int kb = 0; kb <= qb; kb++) {
        const int st = kb & 1;
        const bool more = (kb < qb);
        __syncthreads();
        ldt(oV, gq + 4096 + (size_t)(kb * 128) * GROWB);
        CPCOMMIT();
        if (more) {
            ldt(oK[st ^ 1], gq + 2048 + (size_t)((kb + 1) * 128) * GROWB);
            CPCOMMIT();
        }
        if (more) CPWAIT(2); else CPWAIT(1);
        __syncthreads();

        float sacc[4][4][4];
        #pragma unroll
        for (int mt = 0; mt < 4; mt++)
            #pragma unroll
            for (int nt = 0; nt < 4; nt++)
                #pragma unroll
                for (int j = 0; j < 4; j++) sacc[mt][nt][j] = 0.f;

        #pragma unroll
        for (int ks = 0; ks < 4; ks++) {
            uint32_t q4[4][4], k4[2][4];
            #pragma unroll
            for (int mt = 0; mt < 4; mt++)
                ldsm4(q4[mt], sb + oQ + aOffQ + (uint32_t)(mt * 16 * AROWB + ks * 32));
            #pragma unroll
            for (int p = 0; p < 2; p++)
                ldsm4(k4[p], sb + oK[st] + bOffK + (uint32_t)(p * 16 * AROWB + ks * 32));
            #pragma unroll
            for (int mt = 0; mt < 4; mt++)
                #pragma unroll
                for (int nt = 0; nt < 4; nt++) {
                    int p = nt >> 1, o = (nt & 1) * 2;
                    mma16816(sacc[mt][nt], q4[mt], k4[p][o], k4[p][o + 1]);
                }
        }

        const bool diag = (kb == qb);
        #pragma unroll
        for (int mt = 0; mt < 4; mt++) {
            #pragma unroll
            for (int half = 0; half < 2; half++) {
                int r = wm * 64 + mt * 16 + groupID + half * 8;
                #pragma unroll
                for (int nt = 0; nt < 4; nt++) {
                    int c = wn * 32 + nt * 8 + tid4 * 2;
                    float s0 = silu(sacc[mt][nt][half * 2 + 0] * 0.125f);
                    float s1 = silu(sacc[mt][nt][half * 2 + 1] * 0.125f);
                    if (diag) {
                        if (c > r) s0 = 0.f;
                        if (c + 1 > r) s1 = 0.f;
                    }
                    *(uint32_t*)(sp + r * 136 + c) = pack2h(__float2half(s0), __float2half(s1));
                }
            }
        }
        if (more) CPWAIT(1); else CPWAIT(0);
        __syncthreads();

        #pragma unroll
        for (int ks = 0; ks < 8; ks++) {
            uint32_t s4[4][4], v4[4];
            #pragma unroll
            for (int mt = 0; mt < 4; mt++)
                ldsm4(s4[mt], sb + oS + aOffS + (uint32_t)(mt * 16 * SROWB + ks * 32));
            ldsm4t(v4, sb + oV + bOffV + (uint32_t)(ks * 16 * AROWB));
            #pragma unroll
            for (int mt = 0; mt < 4; mt++)
                #pragma unroll
                for (int nt = 0; nt < 2; nt++) {
                    int o = nt * 2;
                    mma16816(oacc[mt][nt], s4[mt], v4[o], v4[o + 1]);
                }
        }
    }

    __syncthreads();
    #pragma unroll
    for (int mt = 0; mt < 4; mt++)
        #pragma unroll
        for (int half = 0; half < 2; half++) {
            int r = wm * 64 + mt * 16 + groupID + half * 8;
            #pragma unroll
            for (int nt = 0; nt < 2; nt++) {
                int c = wn * 16 + nt * 8 + tid4 * 2;
                float2 v;
                v.x = oacc[mt][nt][half * 2 + 0];
                v.y = oacc[mt][nt][half * 2 + 1];
                *(float2*)(aS + r * 68 + c) = v;
            }
        }
    __syncthreads();
    if (tid < 128) {
        float s = 0.f, s2 = 0.f;
        #pragma unroll
        for (int c = 0; c < 64; c++) {
            float v = aS[tid * 68 + c];
            s += v; s2 += v * v;
        }
        float mu = s * (1.0f / 64.0f);
        float var = s2 * (1.0f / 64.0f) - mu * mu;
        mu_s[tid] = mu;
        rs_s[tid] = rsqrtf(var + 1e-5f);
    }
    __syncthreads();
    {
        int r = tid >> 1;
        int c0 = (tid & 1) * 32;
        int l = qb * 128 + r;
        float mu = mu_s[r], rstd = rs_s[r];
        const __half* uh = (const __half*)(gq + 6144 + (size_t)l * GROWB);
        size_t obase = (size_t)(b * LL + l) * DD + h * HD;
        #pragma unroll
        for (int c = c0; c < c0 + 32; c += 2) {
            float u0 = __half2float(uh[c + 0]);
            float u1 = __half2float(uh[c + 1]);
            float t0 = ((aS[r * 68 + c + 0] - mu) * rstd * nag[c + 0] + nab[c + 0]) * u0;
            float t1 = ((aS[r * 68 + c + 1] - mu) * rstd * nag[c + 1] + nab[c + 1]) * u1;
            *(uint32_t*)(aout + obase + c) = pack2h(__float2half(t0), __float2half(t1));
        }
    }
}

// ---------------- host -------------------------------------------------------
extern "C" void kernel_launch(void* const* d_in, const int* in_sizes, int n_in,
                              void* d_out, int out_size)
{
    const float* x      = (const float*)d_in[0];
    const float* w_qkuv = (const float*)d_in[2];
    const float* w_out  = (const float*)d_in[3];
    const float* w1     = (const float*)d_in[4];
    const float* w2     = (const float*)d_in[5];
    const float* w3     = (const float*)d_in[6];
    const float* ln1_g  = (const float*)d_in[7];
    const float* ln1_b  = (const float*)d_in[8];
    const float* ln2_g  = (const float*)d_in[9];
    const float* ln2_b  = (const float*)d_in[10];
    const float* na_g   = (const float*)d_in[11];
    const float* na_b   = (const float*)d_in[12];
    float* out = (float*)d_out;

    __half *xn, *qk, *a, *xn2, *hbuf;
    __half *wq, *wo, *w1t, *w3t, *w2t;
    float *x1;
    cudaGetSymbolAddress((void**)&xn,   g_xn);
    cudaGetSymbolAddress((void**)&qk,   g_qk);
    cudaGetSymbolAddress((void**)&a,    g_a);
    cudaGetSymbolAddress((void**)&x1,   g_x1);
    cudaGetSymbolAddress((void**)&xn2,  g_xn2);
    cudaGetSymbolAddress((void**)&hbuf, g_h);
    cudaGetSymbolAddress((void**)&wq,   g_wqkuv);
    cudaGetSymbolAddress((void**)&wo,   g_wout);
    cudaGetSymbolAddress((void**)&w1t,  g_w1);
    cudaGetSymbolAddress((void**)&w3t,  g_w3);
    cudaGetSymbolAddress((void**)&w2t,  g_w2);

    cudaFuncSetAttribute(gemm_mma<1>, cudaFuncAttributeMaxDynamicSharedMemorySize, GEMM_SMEM);
    cudaFuncSetAttribute(gemm_mma<3>, cudaFuncAttributeMaxDynamicSharedMemorySize, GEMM_SMEM);
    cudaFuncSetAttribute(gemm_dual,   cudaFuncAttributeMaxDynamicSharedMemorySize, DUAL_SMEM);
    cudaFuncSetAttribute(attn_mma,    cudaFuncAttributeMaxDynamicSharedMemorySize, ATT_SMEM);

    dim3 blk(256);

    // 1. LN1 -> fp16  +  wqkuv convert (fused launch)
    ln_conv_kernel<<<MROWS / 8 + 128, blk>>>(x, ln1_g, ln1_b, xn, w_qkuv, wq);
    // 2. qkuv = silu(xn @ w_qkuv) -> fp16
    gemm_mma<3><<<dim3(4 * DD / 128, MROWS / 128), blk, GEMM_SMEM>>>(
        xn, wq, nullptr, nullptr, qk, MROWS, 4 * DD, DD);
    // 3. attention -> a fp16  +  late weight conversions (fused launch)
    attn_mma<<<ATT_CTAS + CONV_CTAS, blk, ATT_SMEM>>>(
        qk, na_g, na_b, a,
        w_out, wo, w1, w1t, w3, w3t, w2, w2t);
    // 4. x1 = x + a @ w_out
    gemm_mma<1><<<dim3(DD / 128, MROWS / 128), blk, GEMM_SMEM>>>(
        a, wo, x1, x, nullptr, MROWS, DD, DD);
    // 5. LN2 -> fp16
    ln_half_kernel<<<MROWS / 8, blk>>>(x1, ln2_g, ln2_b, xn2);
    // 6+7. h = silu(xn2@w1) * (xn2@w3) -> fp16
    gemm_dual<<<dim3(FF / 64, MROWS / 128), blk, DUAL_SMEM>>>(
        xn2, w1t, w3t, hbuf, MROWS, FF, DD);
    // 8. out = x1 + h @ w2
    gemm_mma<1><<<dim3(DD / 128, MROWS / 128), blk, GEMM_SMEM>>>(
        hbuf, w2t, out, x1, nullptr, MROWS, DD, FF);
}